// round 10
// baseline (speedup 1.0000x reference)
#include <cuda_runtime.h>
#include <cuda_bf16.h>
#include <math.h>
#include <stdint.h>

#define BATCH 4
#define C64   64
#define HW    65536
#define HEADS 4
#define HID   128
#define EPSF  1e-5f

#define TOT (BATCH*C64*HW)

// ---------------- scratch (device globals; no allocs) ----------------
__device__ unsigned short g_hi[(size_t)4*TOT];
__device__ unsigned short g_lo[(size_t)4*TOT];
__device__ float g_gram256[BATCH*256*256];
// pre-split M (pitch 136): per batch: [0]=(Mc|Mc), [1]=(Mid|Med)
__device__ unsigned short g_Mh[BATCH*2*8704];
__device__ unsigned short g_Ml[BATCH*2*8704];
// pre-split weights: W1 pitch 72 (128 rows), W2 pitch 136 (64 rows); [0]=common,[1]=diff
__device__ unsigned short g_W1h[2*9216];
__device__ unsigned short g_W1l[2*9216];
__device__ unsigned short g_W2h[2*8704];
__device__ unsigned short g_W2l[2*8704];

// ======================= helpers ========================
__device__ __forceinline__ uint32_t smem_u32(const void* p){
    uint32_t a;
    asm("{ .reg .u64 t; cvta.to.shared.u64 t, %1; cvt.u32.u64 %0, t; }" : "=r"(a) : "l"(p));
    return a;
}
__device__ __forceinline__ void ldm_x4(uint32_t* r, uint32_t addr){
    asm volatile("ldmatrix.sync.aligned.m8n8.x4.shared.b16 {%0,%1,%2,%3}, [%4];"
        : "=r"(r[0]), "=r"(r[1]), "=r"(r[2]), "=r"(r[3]) : "r"(addr));
}
__device__ __forceinline__ void ldm_t4(uint32_t* r, uint32_t addr){
    asm volatile("ldmatrix.sync.aligned.m8n8.x4.trans.shared.b16 {%0,%1,%2,%3}, [%4];"
        : "=r"(r[0]), "=r"(r[1]), "=r"(r[2]), "=r"(r[3]) : "r"(addr));
}
__device__ __forceinline__ void mma_bf16(float& d0, float& d1, float& d2, float& d3,
        uint32_t a0, uint32_t a1, uint32_t a2, uint32_t a3,
        uint32_t b0, uint32_t b1){
    asm volatile("mma.sync.aligned.m16n8k16.row.col.f32.bf16.bf16.f32 "
        "{%0,%1,%2,%3}, {%4,%5,%6,%7}, {%8,%9}, {%0,%1,%2,%3};"
        : "+f"(d0), "+f"(d1), "+f"(d2), "+f"(d3)
        : "r"(a0), "r"(a1), "r"(a2), "r"(a3), "r"(b0), "r"(b1));
}
#define MMA3(ACC, AH, AL, BH0, BH1, BL0, BL1) do { \
    mma_bf16((ACC)[0],(ACC)[1],(ACC)[2],(ACC)[3], (AH)[0],(AH)[1],(AH)[2],(AH)[3], (BH0),(BH1)); \
    mma_bf16((ACC)[0],(ACC)[1],(ACC)[2],(ACC)[3], (AH)[0],(AH)[1],(AH)[2],(AH)[3], (BL0),(BL1)); \
    mma_bf16((ACC)[0],(ACC)[1],(ACC)[2],(ACC)[3], (AL)[0],(AL)[1],(AL)[2],(AL)[3], (BH0),(BH1)); \
} while(0)

__device__ __forceinline__ void split1(float a, unsigned short& h, unsigned short& l){
    __nv_bfloat16 hb = __float2bfloat16(a);
    float r = a - __bfloat162float(hb);
    h = __bfloat16_as_ushort(hb);
    l = __bfloat16_as_ushort(__float2bfloat16(r));
}
__device__ __forceinline__ void split2(float a, float b, uint32_t& h, uint32_t& l){
    __nv_bfloat16 ha=__float2bfloat16(a), hb=__float2bfloat16(b);
    float ra = a-__bfloat162float(ha), rb = b-__bfloat162float(hb);
    h = (uint32_t)__bfloat16_as_ushort(ha) | ((uint32_t)__bfloat16_as_ushort(hb)<<16);
    l = (uint32_t)__bfloat16_as_ushort(__float2bfloat16(ra))
      | ((uint32_t)__bfloat16_as_ushort(__float2bfloat16(rb))<<16);
}
__device__ __forceinline__ float gelu_f(float h){
    return 0.5f*h*(1.f + erff(h*0.70710678118654752f));
}

// =====================================================================
// K1: channel LayerNorm -> pre-split hi/lo planes (+ zero gram accum)
// =====================================================================
__global__ void __launch_bounds__(256) ln_kernel(
    const float* __restrict__ img, const float* __restrict__ evt,
    const float* __restrict__ wi, const float* __restrict__ bi,
    const float* __restrict__ we, const float* __restrict__ be,
    const float* __restrict__ wc, const float* __restrict__ bc,
    const float* __restrict__ wd, const float* __restrict__ bd)
{
    if (blockIdx.x < 256) {
        int base = blockIdx.x * 1024 + threadIdx.x * 4;
        g_gram256[base+0] = 0.f; g_gram256[base+1] = 0.f;
        g_gram256[base+2] = 0.f; g_gram256[base+3] = 0.f;
    }
    int b  = blockIdx.x >> 7;
    int p  = ((blockIdx.x & 127) << 9) + threadIdx.x*2;
    const float* ip = img + (size_t)b*C64*HW + p;
    const float* ep = evt + (size_t)b*C64*HW + p;

    float si0=0,si1=0,se0=0,se1=0,sii0=0,sii1=0,see0=0,see1=0,sie0=0,sie1=0;
    #pragma unroll 8
    for (int c=0;c<C64;c++){
        float2 iv = *(const float2*)&ip[(size_t)c*HW];
        float2 ev = *(const float2*)&ep[(size_t)c*HW];
        si0+=iv.x; si1+=iv.y; se0+=ev.x; se1+=ev.y;
        sii0+=iv.x*iv.x; sii1+=iv.y*iv.y;
        see0+=ev.x*ev.x; see1+=ev.y*ev.y;
        sie0+=iv.x*ev.x; sie1+=iv.y*ev.y;
    }
    const float inv64 = 1.f/64.f;
    float mi0=si0*inv64, mi1=si1*inv64, me0=se0*inv64, me1=se1*inv64;
    float mc0=(si0+se0)*inv64, mc1=(si1+se1)*inv64;
    float md0=(si0-se0)*inv64, md1=(si1-se1)*inv64;
    float ri0=rsqrtf(sii0*inv64-mi0*mi0+EPSF), ri1=rsqrtf(sii1*inv64-mi1*mi1+EPSF);
    float re0=rsqrtf(see0*inv64-me0*me0+EPSF), re1=rsqrtf(see1*inv64-me1*me1+EPSF);
    float rc0=rsqrtf((sii0+2.f*sie0+see0)*inv64-mc0*mc0+EPSF);
    float rc1=rsqrtf((sii1+2.f*sie1+see1)*inv64-mc1*mc1+EPSF);
    float rd0=rsqrtf((sii0-2.f*sie0+see0)*inv64-md0*md0+EPSF);
    float rd1=rsqrtf((sii1-2.f*sie1+see1)*inv64-md1*md1+EPSF);

    size_t ob = (size_t)b*C64*HW + p;
    #pragma unroll 4
    for (int c=0;c<C64;c++){
        float2 iv = *(const float2*)&ip[(size_t)c*HW];
        float2 ev = *(const float2*)&ep[(size_t)c*HW];
        size_t o = ob + (size_t)c*HW;
        uint32_t hh, ll;
        split2((iv.x-mi0)*ri0*wi[c]+bi[c], (iv.y-mi1)*ri1*wi[c]+bi[c], hh, ll);
        *(uint32_t*)&g_hi[o] = hh; *(uint32_t*)&g_lo[o] = ll;
        split2((ev.x-me0)*re0*we[c]+be[c], (ev.y-me1)*re1*we[c]+be[c], hh, ll);
        *(uint32_t*)&g_hi[(size_t)TOT + o] = hh; *(uint32_t*)&g_lo[(size_t)TOT + o] = ll;
        split2((iv.x+ev.x-mc0)*rc0*wc[c]+bc[c], (iv.y+ev.y-mc1)*rc1*wc[c]+bc[c], hh, ll);
        *(uint32_t*)&g_hi[(size_t)2*TOT + o] = hh; *(uint32_t*)&g_lo[(size_t)2*TOT + o] = ll;
        split2((iv.x-ev.x-md0)*rd0*wd[c]+bd[c], (iv.y-ev.y-md1)*rd1*wd[c]+bd[c], hh, ll);
        *(uint32_t*)&g_hi[(size_t)3*TOT + o] = hh; *(uint32_t*)&g_lo[(size_t)3*TOT + o] = ll;
    }
}

// =====================================================================
// K2: stacked Gram via mma.sync bf16 hi/lo (3 passes), fp32 accum.
// 3 output tiles only (quadrant rows{ni,ne} x cols{nc,nd} is never read):
//   tile 0: (m0,n0)=(0,0)   ; tile 1: (128,0) ; tile 2: (128,128)
// KC=64 (dynamic smem 72KB), 3 CTA/SM -> 384 CTAs = single wave.
// =====================================================================
#define GK_KSPLIT 32
#define GK_KRANGE (HW/GK_KSPLIT)    // 2048
#define GK_KC     64
#define GK_NCH    (GK_KRANGE/GK_KC) // 32
#define SP2       72
#define GR_SMEM_BYTES (4*128*SP2*2) // 73728

__global__ void __launch_bounds__(256,3) gram_mma_kernel()
{
    extern __shared__ unsigned short gsm[];
    unsigned short* sAhi = gsm;
    unsigned short* sAlo = gsm + 128*SP2;
    unsigned short* sBhi = gsm + 2*128*SP2;
    unsigned short* sBlo = gsm + 3*128*SP2;

    int tid = threadIdx.x;
    int wid = tid >> 5, lane = tid & 31;
    int ks = blockIdx.x, tileid = blockIdx.y, b = blockIdx.z;
    int m0 = (tileid==0) ? 0 : 128;
    int n0 = (tileid==2) ? 128 : 0;
    int warp_m = (wid >> 1) * 32;
    int warp_n = (wid & 1) * 64;

    int lr = tid >> 1;
    int lc = (tid & 1) * 32;
    size_t offA_g = (size_t)((m0+lr)>>6)*TOT + ((size_t)(b*C64)+((m0+lr)&63))*HW + (size_t)ks*GK_KRANGE + lc;
    size_t offB_g = (size_t)((n0+lr)>>6)*TOT + ((size_t)(b*C64)+((n0+lr)&63))*HW + (size_t)ks*GK_KRANGE + lc;
    const unsigned short* sAg_h = g_hi + offA_g;
    const unsigned short* sAg_l = g_lo + offA_g;
    const unsigned short* sBg_h = g_hi + offB_g;
    const unsigned short* sBg_l = g_lo + offB_g;

    uint32_t aHi = smem_u32(sAhi), aLo = smem_u32(sAlo);
    uint32_t bHi = smem_u32(sBhi), bLo = smem_u32(sBlo);

    int rowA = warp_m + (lane & 15);
    int colA = (lane >> 4) * 8;
    uint32_t offA = (uint32_t)(rowA*SP2 + colA) * 2;
    int rowB = warp_n + (lane & 7) + ((lane >> 4) & 1) * 8;
    int colB = ((lane >> 3) & 1) * 8;
    uint32_t offB = (uint32_t)(rowB*SP2 + colB) * 2;

    float acc[2][8][4];
    #pragma unroll
    for (int i=0;i<2;i++)
        #pragma unroll
        for (int j=0;j<8;j++)
            #pragma unroll
            for (int k=0;k<4;k++) acc[i][j][k] = 0.f;

    unsigned short* dAh = sAhi + lr*SP2 + lc;
    unsigned short* dAl = sAlo + lr*SP2 + lc;
    unsigned short* dBh = sBhi + lr*SP2 + lc;
    unsigned short* dBl = sBlo + lr*SP2 + lc;

    for (int t = 0; t < GK_NCH; t++) {
        __syncthreads();
        int kc = t * GK_KC;
        #pragma unroll
        for (int j=0;j<4;j++){
            *(uint4*)&dAh[j*8] = *(const uint4*)&sAg_h[kc + j*8];
            *(uint4*)&dAl[j*8] = *(const uint4*)&sAg_l[kc + j*8];
            *(uint4*)&dBh[j*8] = *(const uint4*)&sBg_h[kc + j*8];
            *(uint4*)&dBl[j*8] = *(const uint4*)&sBg_l[kc + j*8];
        }
        __syncthreads();
        #pragma unroll
        for (int k16 = 0; k16 < GK_KC; k16 += 16) {
            uint32_t kb = (uint32_t)(k16 * 2);
            uint32_t Ah0[4], Ah1[4], Al0[4], Al1[4];
            ldm_x4(Ah0, aHi + offA + kb);
            ldm_x4(Ah1, aHi + offA + kb + 16*SP2*2);
            ldm_x4(Al0, aLo + offA + kb);
            ldm_x4(Al1, aLo + offA + kb + 16*SP2*2);
            #pragma unroll
            for (int np = 0; np < 4; np++) {
                uint32_t Bh[4], Bl[4];
                uint32_t ob = offB + kb + (uint32_t)(np*16*SP2*2);
                ldm_x4(Bh, bHi + ob);
                ldm_x4(Bl, bLo + ob);
                int n2 = np*2;
                MMA3(acc[0][n2],   Ah0, Al0, Bh[0],Bh[1], Bl[0],Bl[1]);
                MMA3(acc[0][n2+1], Ah0, Al0, Bh[2],Bh[3], Bl[2],Bl[3]);
                MMA3(acc[1][n2],   Ah1, Al1, Bh[0],Bh[1], Bl[0],Bl[1]);
                MMA3(acc[1][n2+1], Ah1, Al1, Bh[2],Bh[3], Bl[2],Bl[3]);
            }
        }
    }

    float* G = g_gram256 + (size_t)b*65536;
    int rbase = m0 + warp_m + (lane >> 2);
    int cbase = n0 + warp_n + (lane & 3)*2;
    #pragma unroll
    for (int i=0;i<2;i++){
        #pragma unroll
        for (int ns=0;ns<8;ns++){
            int rr = rbase + i*16;
            int cc = cbase + ns*8;
            atomicAdd(&G[rr*256 + cc],       acc[i][ns][0]);
            atomicAdd(&G[rr*256 + cc + 1],   acc[i][ns][1]);
            atomicAdd(&G[(rr+8)*256 + cc],   acc[i][ns][2]);
            atomicAdd(&G[(rr+8)*256 + cc+1], acc[i][ns][3]);
        }
    }
}

// =====================================================================
// K3: per-batch, per-branch math -> pre-split M + weights.
// grid (BATCH, 2): y=0 common, y=1 differential.
// =====================================================================
__device__ __forceinline__ void ld_mat(float* s, const float* __restrict__ g, int tid){
    for (int i=tid; i<4096; i+=256) s[i] = g[i];
}
__device__ __forceinline__ void ld_matg(float* s, const float* __restrict__ g, int tid){
    for (int i=tid; i<4096; i+=256) s[i] = g[(i>>6)*256 + (i&63)];
}
__device__ __forceinline__ void mm64_nn(float* Cm, const float* A, const float* Bm, int tid){
    int ty = tid>>4, tx = tid&15;
    float acc[4][4] = {};
    for (int k=0;k<64;k++){
        float4 bv = *(const float4*)&Bm[k*64 + tx*4];
        float b4[4] = {bv.x,bv.y,bv.z,bv.w};
        #pragma unroll
        for (int ii=0;ii<4;ii++){
            float a = A[(ty*4+ii)*64 + k];
            #pragma unroll
            for (int jj=0;jj<4;jj++) acc[ii][jj] += a*b4[jj];
        }
    }
    #pragma unroll
    for (int ii=0;ii<4;ii++)
        #pragma unroll
        for (int jj=0;jj<4;jj++)
            Cm[(ty*4+ii)*64 + tx*4+jj] = acc[ii][jj];
    __syncthreads();
}
__device__ __forceinline__ void mm64_nt(float* Cm, const float* A, const float* Bm, int tid){
    int ty = tid>>4, tx = tid&15;
    float acc[4][4] = {};
    for (int k=0;k<64;k++){
        float a4[4], b4[4];
        #pragma unroll
        for (int ii=0;ii<4;ii++) a4[ii] = A[(ty*4+ii)*64 + k];
        #pragma unroll
        for (int jj=0;jj<4;jj++) b4[jj] = Bm[(tx*4+jj)*64 + k];
        #pragma unroll
        for (int ii=0;ii<4;ii++)
            #pragma unroll
            for (int jj=0;jj<4;jj++) acc[ii][jj] += a4[ii]*b4[jj];
    }
    #pragma unroll
    for (int ii=0;ii<4;ii++)
        #pragma unroll
        for (int jj=0;jj<4;jj++)
            Cm[(ty*4+ii)*64 + tx*4+jj] = acc[ii][jj];
    __syncthreads();
}
__device__ __forceinline__ void rownorm_inv(float* inv, const float* T, const float* Wm, int tid){
    if (tid < 64){
        float s = 0.f;
        for (int k=0;k<64;k++) s += T[tid*64+k]*Wm[tid*64+k];
        inv[tid] = 1.f / fmaxf(sqrtf(fmaxf(s, 0.f)), 1e-12f);
    }
    __syncthreads();
}
__device__ __forceinline__ void attn_softmax(float* out, const float* raw,
        const float* invq, const float* invk, const float* __restrict__ temp, int tid){
    if (tid < 64){
        int head = tid >> 4, base = head*16;
        float t = temp[head];
        float l[16]; float mx = -1e30f;
        #pragma unroll
        for (int s=0;s<16;s++){
            l[s] = raw[tid*64 + base + s] * invq[tid] * invk[base+s] * t;
            mx = fmaxf(mx, l[s]);
        }
        float sum = 0.f;
        #pragma unroll
        for (int s=0;s<16;s++){ l[s] = expf(l[s]-mx); sum += l[s]; }
        float r = 1.f/sum;
        #pragma unroll
        for (int s=0;s<16;s++) out[tid*16+s] = l[s]*r;
    }
    __syncthreads();
}
__device__ __forceinline__ void bdv(float* Cm, const float* at, const float* Wv, int tid){
    int ty = tid>>4, tx = tid&15;
    float acc[4][4] = {};
    for (int s=0;s<16;s++){
        #pragma unroll
        for (int ii=0;ii<4;ii++){
            int row = ty*4+ii; int head = row >> 4;
            float a = at[row*16 + s];
            float4 wv = *(const float4*)&Wv[(head*16+s)*64 + tx*4];
            acc[ii][0] += a*wv.x; acc[ii][1] += a*wv.y;
            acc[ii][2] += a*wv.z; acc[ii][3] += a*wv.w;
        }
    }
    #pragma unroll
    for (int ii=0;ii<4;ii++)
        #pragma unroll
        for (int jj=0;jj<4;jj++)
            Cm[(ty*4+ii)*64 + tx*4+jj] = acc[ii][jj];
    __syncthreads();
}
__device__ __forceinline__ void store_M_half(const float* sR, int b, int buf, int half, int tid){
    size_t base = ((size_t)b*2+buf)*8704;
    for (int i=tid;i<4096;i+=256){
        int r=i>>6, k=i&63;
        unsigned short h,l; split1(sR[i],h,l);
        g_Mh[base + r*136 + half*64 + k] = h;
        g_Ml[base + r*136 + half*64 + k] = l;
    }
    __syncthreads();
}

__global__ void __launch_bounds__(256) smallmath_kernel(
    const float* __restrict__ Wq_c, const float* __restrict__ Wk_c, const float* __restrict__ Wv_c,
    const float* __restrict__ temp_c,
    const float* __restrict__ Wq_d, const float* __restrict__ Wk_d, const float* __restrict__ Wv_d,
    const float* __restrict__ temp_d,
    const float* __restrict__ proj1, const float* __restrict__ proj2,
    const float* __restrict__ fc1c_w, const float* __restrict__ fc2c_w,
    const float* __restrict__ fc1d_w, const float* __restrict__ fc2d_w)
{
    extern __shared__ float sm[];
    float* sA   = sm;
    float* sB   = sA + 4096;
    float* sG   = sB + 4096;
    float* sT   = sG + 4096;
    float* sR   = sT + 4096;
    float* aA   = sR + 4096;
    float* aB   = aA + 1024;
    float* invq  = aB + 1024;
    float* invk1 = invq + 64;
    float* invk2 = invk1 + 64;

    int b = blockIdx.x;
    int br = blockIdx.y;      // 0 = common, 1 = differential
    int tid = threadIdx.x;

    // block (0, br) pre-splits that branch's FFN weights
    if (b == 0){
        const float* W1s = br ? fc1d_w : fc1c_w;
        const float* W2s = br ? fc2d_w : fc2c_w;
        int o1 = br*9216, o2 = br*8704;
        for (int i=tid;i<8192;i+=256){
            int r=i>>6, k=i&63;
            unsigned short h,l;
            split1(W1s[i],h,l); g_W1h[o1+r*72+k]=h; g_W1l[o1+r*72+k]=l;
        }
        for (int i=tid;i<8192;i+=256){
            int r=i>>7, k=i&127;
            unsigned short h,l;
            split1(W2s[i],h,l); g_W2h[o2+r*136+k]=h; g_W2l[o2+r*136+k]=l;
        }
    }

    const float* Wq   = br ? Wq_d   : Wq_c;
    const float* Wk   = br ? Wk_d   : Wk_c;
    const float* Wv   = br ? Wv_d   : Wv_c;
    const float* temp = br ? temp_d : temp_c;
    const float* proj = br ? proj2  : proj1;
    int qr = br ? 3 : 2;

    #define GB(bi,bj) (g_gram256 + (size_t)b*65536 + (bi)*64*256 + (bj)*64)

    ld_mat(sA, Wq, tid); ld_matg(sG, GB(qr,qr), tid); __syncthreads();
    mm64_nn(sT, sA, sG, tid);
    rownorm_inv(invq, sT, sA, tid);
    ld_mat(sB, Wk, tid); ld_matg(sG, GB(0,0), tid); __syncthreads();
    mm64_nn(sT, sB, sG, tid);
    rownorm_inv(invk1, sT, sB, tid);
    ld_matg(sG, GB(1,1), tid); __syncthreads();
    mm64_nn(sT, sB, sG, tid);
    rownorm_inv(invk2, sT, sB, tid);
    ld_matg(sG, GB(qr,0), tid); __syncthreads();
    mm64_nn(sT, sA, sG, tid);
    mm64_nt(sR, sT, sB, tid);
    attn_softmax(aA, sR, invq, invk1, temp, tid);
    ld_matg(sG, GB(qr,1), tid); __syncthreads();
    mm64_nn(sT, sA, sG, tid);
    mm64_nt(sR, sT, sB, tid);
    attn_softmax(aB, sR, invq, invk2, temp, tid);

    if (br == 0){
        if (tid < 64){
            #pragma unroll
            for (int s=0;s<16;s++) aA[tid*16+s] *= aB[tid*16+s];
        }
        __syncthreads();
        ld_mat(sB, Wv, tid); __syncthreads();
        bdv(sT, aA, sB, tid);
        ld_mat(sA, proj, tid); __syncthreads();
        mm64_nn(sR, sA, sT, tid);
        store_M_half(sR, b, 0, 0, tid);
        store_M_half(sR, b, 0, 1, tid);
    } else {
        ld_mat(sB, Wv, tid); ld_mat(sA, proj, tid); __syncthreads();
        bdv(sT, aA, sB, tid);
        mm64_nn(sR, sA, sT, tid);
        store_M_half(sR, b, 1, 0, tid);
        bdv(sT, aB, sB, tid);
        mm64_nn(sR, sA, sT, tid);
        store_M_half(sR, b, 1, 1, tid);
    }
    #undef GB
}

// =====================================================================
// K4: unified apply kernel (unchanged from R9 — passing at 212us)
// =====================================================================
#define AP_SMEM_BYTES 111616

__global__ void __launch_bounds__(256) apply_kernel(
    int msel, int widx,
    const float* __restrict__ lnw, const float* __restrict__ lnb,
    const float* __restrict__ b1g, const float* __restrict__ b2g,
    float* __restrict__ outp)
{
    extern __shared__ char smraw[];
    unsigned short* sAh = (unsigned short*)(smraw);
    unsigned short* sAl = (unsigned short*)(smraw + 18432);
    unsigned short* sXh = (unsigned short*)(smraw + 36864);
    unsigned short* sXl = (unsigned short*)(smraw + 46080);
    unsigned short* sHh = (unsigned short*)(smraw + 55296);
    unsigned short* sHl = (unsigned short*)(smraw + 73728);
    float* sY  = (float*)(smraw + 92160);
    float* sb1 = (float*)(smraw + 109568);
    float* sb2 = sb1 + 128;
    float* slw = sb2 + 64;
    float* slb = slw + 64;
    float* smu = slb + 64;
    float* srs = smu + 64;

    uint32_t aH = smem_u32(sAh), aL = smem_u32(sAl);
    uint32_t xH = smem_u32(sXh), xL = smem_u32(sXl);
    uint32_t hH = smem_u32(sHh), hL = smem_u32(sHl);

    int b = blockIdx.y, p0 = blockIdx.x*64;
    int tid = threadIdx.x, w = tid>>5, lane = tid&31;
    int wc = (w>>1)*16, wpx = (w&1)*32;

    if (tid < 128) sb1[tid] = b1g[tid];
    if (tid < 64){ sb2[tid]=b2g[tid]; slw[tid]=lnw[tid]; slb[tid]=lnb[tid]; }

    {
        const uint4* mh = (const uint4*)&g_Mh[((size_t)b*2+msel)*8704];
        const uint4* ml = (const uint4*)&g_Ml[((size_t)b*2+msel)*8704];
        uint4* dh = (uint4*)sAh; uint4* dl = (uint4*)sAl;
        for (int i=tid;i<1088;i+=256){ dh[i]=mh[i]; dl[i]=ml[i]; }
    }
    for (int i=tid;i<512;i+=256){
        int c=i>>3, q=i&7;
        size_t off = ((size_t)(b*C64+c))*HW + p0 + q*8;
        *(uint4*)&sXh[c*72 + q*8] = *(const uint4*)&g_hi[off];
        *(uint4*)&sXl[c*72 + q*8] = *(const uint4*)&g_lo[off];
    }
    __syncthreads();

    float acc[4][4];
    #pragma unroll
    for (int g=0;g<4;g++)
        #pragma unroll
        for (int k=0;k<4;k++) acc[g][k]=0.f;
    uint32_t offA = (uint32_t)(((wc+(lane&15))*136 + ((lane>>4)&1)*8)*2);
    uint32_t offB = (uint32_t)((((lane&7)+((lane>>3)&1)*8)*72 + ((lane>>4)&1)*8)*2);

    #pragma unroll
    for (int k16=0;k16<4;k16++){
        uint32_t Ah[4],Al[4];
        ldm_x4(Ah, aH + offA + k16*32);
        ldm_x4(Al, aL + offA + k16*32);
        #pragma unroll
        for (int hf=0;hf<2;hf++){
            uint32_t Bh[4],Bl[4];
            uint32_t ob = offB + (uint32_t)(k16*16*144 + (wpx+hf*16)*2);
            ldm_t4(Bh, xH + ob); ldm_t4(Bl, xL + ob);
            MMA3(acc[hf*2],   Ah, Al, Bh[0],Bh[1], Bl[0],Bl[1]);
            MMA3(acc[hf*2+1], Ah, Al, Bh[2],Bh[3], Bl[2],Bl[3]);
        }
    }
    __syncthreads();
    for (int i=tid;i<512;i+=256){
        int c=i>>3, q=i&7;
        size_t off = (size_t)TOT + ((size_t)(b*C64+c))*HW + p0 + q*8;
        *(uint4*)&sXh[c*72 + q*8] = *(const uint4*)&g_hi[off];
        *(uint4*)&sXl[c*72 + q*8] = *(const uint4*)&g_lo[off];
    }
    __syncthreads();
    #pragma unroll
    for (int k16=0;k16<4;k16++){
        uint32_t Ah[4],Al[4];
        ldm_x4(Ah, aH + offA + 128 + k16*32);
        ldm_x4(Al, aL + offA + 128 + k16*32);
        #pragma unroll
        for (int hf=0;hf<2;hf++){
            uint32_t Bh[4],Bl[4];
            uint32_t ob = offB + (uint32_t)(k16*16*144 + (wpx+hf*16)*2);
            ldm_t4(Bh, xH + ob); ldm_t4(Bl, xL + ob);
            MMA3(acc[hf*2],   Ah, Al, Bh[0],Bh[1], Bl[0],Bl[1]);
            MMA3(acc[hf*2+1], Ah, Al, Bh[2],Bh[3], Bl[2],Bl[3]);
        }
    }
    {
        int c0 = wc + (lane>>2);
        int pxb = wpx + (lane&3)*2;
        #pragma unroll
        for (int g=0; g<4; g++){
            int px = pxb + g*8;
            *(float2*)&sY[c0*68+px]     = make_float2(acc[g][0], acc[g][1]);
            *(float2*)&sY[(c0+8)*68+px] = make_float2(acc[g][2], acc[g][3]);
        }
    }
    __syncthreads();

    if (tid < 64){
        float s=0.f, ss=0.f;
        for (int c=0;c<64;c++){ float v = sY[c*68+tid]; s += v; ss += v*v; }
        float mu = s*(1.f/64.f);
        float var = ss*(1.f/64.f) - mu*mu;
        smu[tid] = mu; srs[tid] = rsqrtf(var + EPSF);
    }
    __syncthreads();
    for (int i=tid;i<2048;i+=256){
        int c = i>>5, px = (i&31)*2;
        float z0 = (sY[c*68+px  ]-smu[px  ])*srs[px  ]*slw[c] + slb[c];
        float z1 = (sY[c*68+px+1]-smu[px+1])*srs[px+1]*slw[c] + slb[c];
        uint32_t hh, ll; split2(z0, z1, hh, ll);
        *(uint32_t*)&sXh[c*72+px] = hh;
        *(uint32_t*)&sXl[c*72+px] = ll;
    }
    {
        const uint4* wh = (const uint4*)&g_W1h[widx*9216];
        const uint4* wl = (const uint4*)&g_W1l[widx*9216];
        uint4* dh = (uint4*)sAh; uint4* dl = (uint4*)sAl;
        for (int i=tid;i<1152;i+=256){ dh[i]=wh[i]; dl[i]=wl[i]; }
    }
    __syncthreads();

    {
        int wh_ = (w>>1)*32;
        float a2[2][4][4];
        #pragma unroll
        for (int m=0;m<2;m++)
            #pragma unroll
            for (int g=0;g<4;g++)
                #pragma unroll
                for (int k=0;k<4;k++) a2[m][g][k]=0.f;
        uint32_t offA2 = (uint32_t)(((wh_+(lane&15))*72 + ((lane>>4)&1)*8)*2);
        #pragma unroll
        for (int k16=0;k16<4;k16++){
            uint32_t Ah0[4],Al0[4],Ah1[4],Al1[4];
            ldm_x4(Ah0, aH + offA2 + k16*32);
            ldm_x4(Al0, aL + offA2 + k16*32);
            ldm_x4(Ah1, aH + offA2 + k16*32 + 16*144);
            ldm_x4(Al1, aL + offA2 + k16*32 + 16*144);
            #pragma unroll
            for (int hf=0;hf<2;hf++){
                uint32_t Bh[4],Bl[4];
                uint32_t ob = offB + (uint32_t)(k16*16*144 + (wpx+hf*16)*2);
                ldm_t4(Bh, xH + ob); ldm_t4(Bl, xL + ob);
                int g0=hf*2, g1=hf*2+1;
                MMA3(a2[0][g0], Ah0, Al0, Bh[0],Bh[1], Bl[0],Bl[1]);
                MMA3(a2[0][g1], Ah0, Al0, Bh[2],Bh[3], Bl[2],Bl[3]);
                MMA3(a2[1][g0], Ah1, Al1, Bh[0],Bh[1], Bl[0],Bl[1]);
                MMA3(a2[1][g1], Ah1, Al1, Bh[2],Bh[3], Bl[2],Bl[3]);
            }
        }
        int hb = wh_ + (lane>>2);
        int pxb = wpx + (lane&3)*2;
        #pragma unroll
        for (int m=0;m<2;m++){
            int r0 = hb + m*16, r1 = r0 + 8;
            float bb0 = sb1[r0], bb1 = sb1[r1];
            #pragma unroll
            for (int g=0; g<4; g++){
                int px = pxb + g*8;
                float v0 = gelu_f(a2[m][g][0] + bb0);
                float v1 = gelu_f(a2[m][g][1] + bb0);
                float v2 = gelu_f(a2[m][g][2] + bb1);
                float v3 = gelu_f(a2[m][g][3] + bb1);
                uint32_t hh, ll;
                split2(v0, v1, hh, ll);
                *(uint32_t*)&sHh[r0*72+px] = hh; *(uint32_t*)&sHl[r0*72+px] = ll;
                split2(v2, v3, hh, ll);
                *(uint32_t*)&sHh[r1*72+px] = hh; *(uint32_t*)&sHl[r1*72+px] = ll;
            }
        }
    }
    __syncthreads();
    {
        const uint4* wh = (const uint4*)&g_W2h[widx*8704];
        const uint4* wl = (const uint4*)&g_W2l[widx*8704];
        uint4* dh = (uint4*)sAh; uint4* dl = (uint4*)sAl;
        for (int i=tid;i<1088;i+=256){ dh[i]=wh[i]; dl[i]=wl[i]; }
    }
    __syncthreads();

    {
        float a3[4][4];
        #pragma unroll
        for (int g=0;g<4;g++)
            #pragma unroll
            for (int k=0;k<4;k++) a3[g][k]=0.f;
        uint32_t offA3 = (uint32_t)(((wc+(lane&15))*136 + ((lane>>4)&1)*8)*2);
        #pragma unroll
        for (int k16=0;k16<8;k16++){
            uint32_t Ah[4],Al[4];
            ldm_x4(Ah, aH + offA3 + k16*32);
            ldm_x4(Al, aL + offA3 + k16*32);
            #pragma unroll
            for (int hf=0;hf<2;hf++){
                uint32_t Bh[4],Bl[4];
                uint32_t ob = offB + (uint32_t)(k16*16*144 + (wpx+hf*16)*2);
                ldm_t4(Bh, hH + ob); ldm_t4(Bl, hL + ob);
                MMA3(a3[hf*2],   Ah, Al, Bh[0],Bh[1], Bl[0],Bl[1]);
                MMA3(a3[hf*2+1], Ah, Al, Bh[2],Bh[3], Bl[2],Bl[3]);
            }
        }
        int c0 = wc + (lane>>2);
        int pxb = wpx + (lane&3)*2;
        float bc0 = sb2[c0], bc1 = sb2[c0+8];
        #pragma unroll
        for (int g=0; g<4; g++){
            int px = pxb + g*8;
            float2 o;
            o.x = a3[g][0] + bc0 + sY[c0*68+px];
            o.y = a3[g][1] + bc0 + sY[c0*68+px+1];
            *(float2*)&outp[((size_t)(b*C64+c0))*HW + p0 + px] = o;
            o.x = a3[g][2] + bc1 + sY[(c0+8)*68+px];
            o.y = a3[g][3] + bc1 + sY[(c0+8)*68+px+1];
            *(float2*)&outp[((size_t)(b*C64+c0+8))*HW + p0 + px] = o;
        }
    }
}

// =====================================================================
extern "C" void kernel_launch(void* const* d_in, const int* in_sizes, int n_in,
                              void* d_out, int out_size)
{
    (void)in_sizes; (void)n_in; (void)out_size;
    const float* image  = (const float*)d_in[0];
    const float* event_ = (const float*)d_in[1];
    const float* Wq_c = (const float*)d_in[2];
    const float* Wk_c = (const float*)d_in[3];
    const float* Wv_c = (const float*)d_in[4];
    const float* temp_c = (const float*)d_in[5];
    const float* Wq_d = (const float*)d_in[6];
    const float* Wk_d = (const float*)d_in[7];
    const float* Wv_d = (const float*)d_in[8];
    const float* temp_d = (const float*)d_in[9];
    const float* ln_img_w = (const float*)d_in[10];
    const float* ln_img_b = (const float*)d_in[11];
    const float* ln_evt_w = (const float*)d_in[12];
    const float* ln_evt_b = (const float*)d_in[13];
    const float* ln_com_w = (const float*)d_in[14];
    const float* ln_com_b = (const float*)d_in[15];
    const float* ln_dif_w = (const float*)d_in[16];
    const float* ln_dif_b = (const float*)d_in[17];
    const float* ln1_w = (const float*)d_in[18];
    const float* ln1_b = (const float*)d_in[19];
    const float* ln2_w = (const float*)d_in[20];
    const float* ln2_b = (const float*)d_in[21];
    const float* fc1c_w = (const float*)d_in[22];
    const float* fc1c_b = (const float*)d_in[23];
    const float* fc2c_w = (const float*)d_in[24];
    const float* fc2c_b = (const float*)d_in[25];
    const float* fc1d_w = (const float*)d_in[26];
    const float* fc1d_b = (const float*)d_in[27];
    const float* fc2d_w = (const float*)d_in[28];
    const float* fc2d_b = (const float*)d_in[29];
    const float* proj1_w = (const float*)d_in[30];
    const float* proj2_w = (const float*)d_in[31];

    float* outc = (float*)d_out;
    float* outd = outc + (size_t)BATCH*C64*HW;

    const int SM3 = (4096*5 + 1024*2 + 64*3) * sizeof(float);

    cudaFuncSetAttribute(gram_mma_kernel,  cudaFuncAttributeMaxDynamicSharedMemorySize, GR_SMEM_BYTES);
    cudaFuncSetAttribute(smallmath_kernel, cudaFuncAttributeMaxDynamicSharedMemorySize, SM3);
    cudaFuncSetAttribute(apply_kernel,     cudaFuncAttributeMaxDynamicSharedMemorySize, AP_SMEM_BYTES);

    ln_kernel<<<BATCH*(HW/512), 256>>>(image, event_,
        ln_img_w, ln_img_b, ln_evt_w, ln_evt_b,
        ln_com_w, ln_com_b, ln_dif_w, ln_dif_b);

    dim3 g2(GK_KSPLIT, 3, BATCH);
    gram_mma_kernel<<<g2, 256, GR_SMEM_BYTES>>>();

    dim3 g3(BATCH, 2);
    smallmath_kernel<<<g3, 256, SM3>>>(Wq_c, Wk_c, Wv_c, temp_c,
                                       Wq_d, Wk_d, Wv_d, temp_d,
                                       proj1_w, proj2_w,
                                       fc1c_w, fc2c_w, fc1d_w, fc2d_w);

    dim3 g4(HW/64, BATCH);
    apply_kernel<<<g4, 256, AP_SMEM_BYTES>>>(0, 0, ln1_w, ln1_b, fc1c_b, fc2c_b, outc);
    apply_kernel<<<g4, 256, AP_SMEM_BYTES>>>(1, 1, ln2_w, ln2_b, fc1d_b, fc2d_b, outd);
}

// round 11
// speedup vs baseline: 1.1495x; 1.1495x over previous
#include <cuda_runtime.h>
#include <cuda_bf16.h>
#include <math.h>
#include <stdint.h>

#define BATCH 4
#define C64   64
#define HW    65536
#define HEADS 4
#define HID   128
#define EPSF  1e-5f

#define TOT (BATCH*C64*HW)

// ---------------- scratch (device globals; no allocs) ----------------
__device__ unsigned short g_hi[(size_t)4*TOT];
__device__ unsigned short g_lo[(size_t)4*TOT];
__device__ float g_gram256[BATCH*256*256];
// pre-split M (pitch 136): per batch: [0]=(Mc|Mc), [1]=(Mid|Med)
__device__ unsigned short g_Mh[BATCH*2*8704];
__device__ unsigned short g_Ml[BATCH*2*8704];
// pre-split weights: W1 pitch 72 (128 rows), W2 pitch 136 (64 rows); [0]=common,[1]=diff
__device__ unsigned short g_W1h[2*9216];
__device__ unsigned short g_W1l[2*9216];
__device__ unsigned short g_W2h[2*8704];
__device__ unsigned short g_W2l[2*8704];

// ======================= helpers ========================
__device__ __forceinline__ uint32_t smem_u32(const void* p){
    uint32_t a;
    asm("{ .reg .u64 t; cvta.to.shared.u64 t, %1; cvt.u32.u64 %0, t; }" : "=r"(a) : "l"(p));
    return a;
}
__device__ __forceinline__ void ldm_x4(uint32_t* r, uint32_t addr){
    asm volatile("ldmatrix.sync.aligned.m8n8.x4.shared.b16 {%0,%1,%2,%3}, [%4];"
        : "=r"(r[0]), "=r"(r[1]), "=r"(r[2]), "=r"(r[3]) : "r"(addr));
}
__device__ __forceinline__ void ldm_t4(uint32_t* r, uint32_t addr){
    asm volatile("ldmatrix.sync.aligned.m8n8.x4.trans.shared.b16 {%0,%1,%2,%3}, [%4];"
        : "=r"(r[0]), "=r"(r[1]), "=r"(r[2]), "=r"(r[3]) : "r"(addr));
}
__device__ __forceinline__ void mma_bf16(float& d0, float& d1, float& d2, float& d3,
        uint32_t a0, uint32_t a1, uint32_t a2, uint32_t a3,
        uint32_t b0, uint32_t b1){
    asm volatile("mma.sync.aligned.m16n8k16.row.col.f32.bf16.bf16.f32 "
        "{%0,%1,%2,%3}, {%4,%5,%6,%7}, {%8,%9}, {%0,%1,%2,%3};"
        : "+f"(d0), "+f"(d1), "+f"(d2), "+f"(d3)
        : "r"(a0), "r"(a1), "r"(a2), "r"(a3), "r"(b0), "r"(b1));
}
#define MMA3(ACC, AH, AL, BH0, BH1, BL0, BL1) do { \
    mma_bf16((ACC)[0],(ACC)[1],(ACC)[2],(ACC)[3], (AH)[0],(AH)[1],(AH)[2],(AH)[3], (BH0),(BH1)); \
    mma_bf16((ACC)[0],(ACC)[1],(ACC)[2],(ACC)[3], (AH)[0],(AH)[1],(AH)[2],(AH)[3], (BL0),(BL1)); \
    mma_bf16((ACC)[0],(ACC)[1],(ACC)[2],(ACC)[3], (AL)[0],(AL)[1],(AL)[2],(AL)[3], (BH0),(BH1)); \
} while(0)

__device__ __forceinline__ void split1(float a, unsigned short& h, unsigned short& l){
    __nv_bfloat16 hb = __float2bfloat16(a);
    float r = a - __bfloat162float(hb);
    h = __bfloat16_as_ushort(hb);
    l = __bfloat16_as_ushort(__float2bfloat16(r));
}
__device__ __forceinline__ void split2(float a, float b, uint32_t& h, uint32_t& l){
    __nv_bfloat16 ha=__float2bfloat16(a), hb=__float2bfloat16(b);
    float ra = a-__bfloat162float(ha), rb = b-__bfloat162float(hb);
    h = (uint32_t)__bfloat16_as_ushort(ha) | ((uint32_t)__bfloat16_as_ushort(hb)<<16);
    l = (uint32_t)__bfloat16_as_ushort(__float2bfloat16(ra))
      | ((uint32_t)__bfloat16_as_ushort(__float2bfloat16(rb))<<16);
}
__device__ __forceinline__ float gelu_f(float h){
    return 0.5f*h*(1.f + erff(h*0.70710678118654752f));
}

// =====================================================================
// K1: channel LayerNorm -> pre-split hi/lo planes (+ zero gram accum)
// =====================================================================
__global__ void __launch_bounds__(256) ln_kernel(
    const float* __restrict__ img, const float* __restrict__ evt,
    const float* __restrict__ wi, const float* __restrict__ bi,
    const float* __restrict__ we, const float* __restrict__ be,
    const float* __restrict__ wc, const float* __restrict__ bc,
    const float* __restrict__ wd, const float* __restrict__ bd)
{
    if (blockIdx.x < 256) {
        int base = blockIdx.x * 1024 + threadIdx.x * 4;
        g_gram256[base+0] = 0.f; g_gram256[base+1] = 0.f;
        g_gram256[base+2] = 0.f; g_gram256[base+3] = 0.f;
    }
    int b  = blockIdx.x >> 7;
    int p  = ((blockIdx.x & 127) << 9) + threadIdx.x*2;
    const float* ip = img + (size_t)b*C64*HW + p;
    const float* ep = evt + (size_t)b*C64*HW + p;

    float si0=0,si1=0,se0=0,se1=0,sii0=0,sii1=0,see0=0,see1=0,sie0=0,sie1=0;
    #pragma unroll 8
    for (int c=0;c<C64;c++){
        float2 iv = *(const float2*)&ip[(size_t)c*HW];
        float2 ev = *(const float2*)&ep[(size_t)c*HW];
        si0+=iv.x; si1+=iv.y; se0+=ev.x; se1+=ev.y;
        sii0+=iv.x*iv.x; sii1+=iv.y*iv.y;
        see0+=ev.x*ev.x; see1+=ev.y*ev.y;
        sie0+=iv.x*ev.x; sie1+=iv.y*ev.y;
    }
    const float inv64 = 1.f/64.f;
    float mi0=si0*inv64, mi1=si1*inv64, me0=se0*inv64, me1=se1*inv64;
    float mc0=(si0+se0)*inv64, mc1=(si1+se1)*inv64;
    float md0=(si0-se0)*inv64, md1=(si1-se1)*inv64;
    float ri0=rsqrtf(sii0*inv64-mi0*mi0+EPSF), ri1=rsqrtf(sii1*inv64-mi1*mi1+EPSF);
    float re0=rsqrtf(see0*inv64-me0*me0+EPSF), re1=rsqrtf(see1*inv64-me1*me1+EPSF);
    float rc0=rsqrtf((sii0+2.f*sie0+see0)*inv64-mc0*mc0+EPSF);
    float rc1=rsqrtf((sii1+2.f*sie1+see1)*inv64-mc1*mc1+EPSF);
    float rd0=rsqrtf((sii0-2.f*sie0+see0)*inv64-md0*md0+EPSF);
    float rd1=rsqrtf((sii1-2.f*sie1+see1)*inv64-md1*md1+EPSF);

    size_t ob = (size_t)b*C64*HW + p;
    #pragma unroll 4
    for (int c=0;c<C64;c++){
        float2 iv = *(const float2*)&ip[(size_t)c*HW];
        float2 ev = *(const float2*)&ep[(size_t)c*HW];
        size_t o = ob + (size_t)c*HW;
        uint32_t hh, ll;
        split2((iv.x-mi0)*ri0*wi[c]+bi[c], (iv.y-mi1)*ri1*wi[c]+bi[c], hh, ll);
        *(uint32_t*)&g_hi[o] = hh; *(uint32_t*)&g_lo[o] = ll;
        split2((ev.x-me0)*re0*we[c]+be[c], (ev.y-me1)*re1*we[c]+be[c], hh, ll);
        *(uint32_t*)&g_hi[(size_t)TOT + o] = hh; *(uint32_t*)&g_lo[(size_t)TOT + o] = ll;
        split2((iv.x+ev.x-mc0)*rc0*wc[c]+bc[c], (iv.y+ev.y-mc1)*rc1*wc[c]+bc[c], hh, ll);
        *(uint32_t*)&g_hi[(size_t)2*TOT + o] = hh; *(uint32_t*)&g_lo[(size_t)2*TOT + o] = ll;
        split2((iv.x-ev.x-md0)*rd0*wd[c]+bd[c], (iv.y-ev.y-md1)*rd1*wd[c]+bd[c], hh, ll);
        *(uint32_t*)&g_hi[(size_t)3*TOT + o] = hh; *(uint32_t*)&g_lo[(size_t)3*TOT + o] = ll;
    }
}

// =====================================================================
// K2: stacked Gram via mma.sync bf16 hi/lo — EXACT R9 per-CTA code,
// only the tile grid changed: 3 tiles (drop unused rows{0,1}xcols{2,3}):
//   tile 0: (m0,n0)=(0,0) ; tile 1: (128,0) ; tile 2: (128,128)
// 3*32*4 = 384 CTAs -> single wave at 3 CTA/SM.
// =====================================================================
#define GK_KSPLIT 32
#define GK_KRANGE (HW/GK_KSPLIT)
#define GK_KC     32
#define GK_NCH    (GK_KRANGE/GK_KC)
#define SPITCH    40

__global__ void __launch_bounds__(256) gram_mma_kernel()
{
    __shared__ __align__(16) unsigned short sAhi[128*SPITCH];
    __shared__ __align__(16) unsigned short sAlo[128*SPITCH];
    __shared__ __align__(16) unsigned short sBhi[128*SPITCH];
    __shared__ __align__(16) unsigned short sBlo[128*SPITCH];

    int tid = threadIdx.x;
    int wid = tid >> 5, lane = tid & 31;
    int ks = blockIdx.x, tileid = blockIdx.y, b = blockIdx.z;
    int m0 = (tileid==0) ? 0 : 128;
    int n0 = (tileid==2) ? 128 : 0;
    int warp_m = (wid >> 1) * 32;
    int warp_n = (wid & 1) * 64;

    int lr = tid >> 1;
    int lc = (tid & 1) * 16;
    size_t offA_g = (size_t)((m0+lr)>>6)*TOT + ((size_t)(b*C64)+((m0+lr)&63))*HW + (size_t)ks*GK_KRANGE + lc;
    size_t offB_g = (size_t)((n0+lr)>>6)*TOT + ((size_t)(b*C64)+((n0+lr)&63))*HW + (size_t)ks*GK_KRANGE + lc;
    const unsigned short* sAg_h = g_hi + offA_g;
    const unsigned short* sAg_l = g_lo + offA_g;
    const unsigned short* sBg_h = g_hi + offB_g;
    const unsigned short* sBg_l = g_lo + offB_g;

    uint32_t aHi = smem_u32(sAhi), aLo = smem_u32(sAlo);
    uint32_t bHi = smem_u32(sBhi), bLo = smem_u32(sBlo);

    int rowA = warp_m + (lane & 15);
    int colA = (lane >> 4) * 8;
    uint32_t offA = (uint32_t)(rowA*SPITCH + colA) * 2;
    int rowB = warp_n + (lane & 7) + ((lane >> 4) & 1) * 8;
    int colB = ((lane >> 3) & 1) * 8;
    uint32_t offB = (uint32_t)(rowB*SPITCH + colB) * 2;

    float acc[2][8][4];
    #pragma unroll
    for (int i=0;i<2;i++)
        #pragma unroll
        for (int j=0;j<8;j++)
            #pragma unroll
            for (int k=0;k<4;k++) acc[i][j][k] = 0.f;

    unsigned short* dAh = sAhi + lr*SPITCH + lc;
    unsigned short* dAl = sAlo + lr*SPITCH + lc;
    unsigned short* dBh = sBhi + lr*SPITCH + lc;
    unsigned short* dBl = sBlo + lr*SPITCH + lc;

    for (int t = 0; t < GK_NCH; t++) {
        __syncthreads();
        int kc = t * GK_KC;
        *(uint4*)&dAh[0] = *(const uint4*)&sAg_h[kc];
        *(uint4*)&dAh[8] = *(const uint4*)&sAg_h[kc+8];
        *(uint4*)&dAl[0] = *(const uint4*)&sAg_l[kc];
        *(uint4*)&dAl[8] = *(const uint4*)&sAg_l[kc+8];
        *(uint4*)&dBh[0] = *(const uint4*)&sBg_h[kc];
        *(uint4*)&dBh[8] = *(const uint4*)&sBg_h[kc+8];
        *(uint4*)&dBl[0] = *(const uint4*)&sBg_l[kc];
        *(uint4*)&dBl[8] = *(const uint4*)&sBg_l[kc+8];
        __syncthreads();
        #pragma unroll
        for (int k16 = 0; k16 < GK_KC; k16 += 16) {
            uint32_t kb = (uint32_t)(k16 * 2);
            uint32_t Ah0[4], Ah1[4], Al0[4], Al1[4];
            ldm_x4(Ah0, aHi + offA + kb);
            ldm_x4(Ah1, aHi + offA + kb + 16*SPITCH*2);
            ldm_x4(Al0, aLo + offA + kb);
            ldm_x4(Al1, aLo + offA + kb + 16*SPITCH*2);
            #pragma unroll
            for (int np = 0; np < 4; np++) {
                uint32_t Bh[4], Bl[4];
                uint32_t ob = offB + kb + (uint32_t)(np*16*SPITCH*2);
                ldm_x4(Bh, bHi + ob);
                ldm_x4(Bl, bLo + ob);
                int n2 = np*2;
                MMA3(acc[0][n2],   Ah0, Al0, Bh[0],Bh[1], Bl[0],Bl[1]);
                MMA3(acc[0][n2+1], Ah0, Al0, Bh[2],Bh[3], Bl[2],Bl[3]);
                MMA3(acc[1][n2],   Ah1, Al1, Bh[0],Bh[1], Bl[0],Bl[1]);
                MMA3(acc[1][n2+1], Ah1, Al1, Bh[2],Bh[3], Bl[2],Bl[3]);
            }
        }
    }

    float* G = g_gram256 + (size_t)b*65536;
    int rbase = m0 + warp_m + (lane >> 2);
    int cbase = n0 + warp_n + (lane & 3)*2;
    #pragma unroll
    for (int i=0;i<2;i++){
        #pragma unroll
        for (int ns=0;ns<8;ns++){
            int rr = rbase + i*16;
            int cc = cbase + ns*8;
            atomicAdd(&G[rr*256 + cc],       acc[i][ns][0]);
            atomicAdd(&G[rr*256 + cc + 1],   acc[i][ns][1]);
            atomicAdd(&G[(rr+8)*256 + cc],   acc[i][ns][2]);
            atomicAdd(&G[(rr+8)*256 + cc+1], acc[i][ns][3]);
        }
    }
}

// =====================================================================
// K3: per-batch, per-branch math -> pre-split M + weights.
// grid (BATCH, 2): y=0 common, y=1 differential.
// =====================================================================
__device__ __forceinline__ void ld_mat(float* s, const float* __restrict__ g, int tid){
    for (int i=tid; i<4096; i+=256) s[i] = g[i];
}
__device__ __forceinline__ void ld_matg(float* s, const float* __restrict__ g, int tid){
    for (int i=tid; i<4096; i+=256) s[i] = g[(i>>6)*256 + (i&63)];
}
__device__ __forceinline__ void mm64_nn(float* Cm, const float* A, const float* Bm, int tid){
    int ty = tid>>4, tx = tid&15;
    float acc[4][4] = {};
    for (int k=0;k<64;k++){
        float4 bv = *(const float4*)&Bm[k*64 + tx*4];
        float b4[4] = {bv.x,bv.y,bv.z,bv.w};
        #pragma unroll
        for (int ii=0;ii<4;ii++){
            float a = A[(ty*4+ii)*64 + k];
            #pragma unroll
            for (int jj=0;jj<4;jj++) acc[ii][jj] += a*b4[jj];
        }
    }
    #pragma unroll
    for (int ii=0;ii<4;ii++)
        #pragma unroll
        for (int jj=0;jj<4;jj++)
            Cm[(ty*4+ii)*64 + tx*4+jj] = acc[ii][jj];
    __syncthreads();
}
__device__ __forceinline__ void mm64_nt(float* Cm, const float* A, const float* Bm, int tid){
    int ty = tid>>4, tx = tid&15;
    float acc[4][4] = {};
    for (int k=0;k<64;k++){
        float a4[4], b4[4];
        #pragma unroll
        for (int ii=0;ii<4;ii++) a4[ii] = A[(ty*4+ii)*64 + k];
        #pragma unroll
        for (int jj=0;jj<4;jj++) b4[jj] = Bm[(tx*4+jj)*64 + k];
        #pragma unroll
        for (int ii=0;ii<4;ii++)
            #pragma unroll
            for (int jj=0;jj<4;jj++) acc[ii][jj] += a4[ii]*b4[jj];
    }
    #pragma unroll
    for (int ii=0;ii<4;ii++)
        #pragma unroll
        for (int jj=0;jj<4;jj++)
            Cm[(ty*4+ii)*64 + tx*4+jj] = acc[ii][jj];
    __syncthreads();
}
__device__ __forceinline__ void rownorm_inv(float* inv, const float* T, const float* Wm, int tid){
    if (tid < 64){
        float s = 0.f;
        for (int k=0;k<64;k++) s += T[tid*64+k]*Wm[tid*64+k];
        inv[tid] = 1.f / fmaxf(sqrtf(fmaxf(s, 0.f)), 1e-12f);
    }
    __syncthreads();
}
__device__ __forceinline__ void attn_softmax(float* out, const float* raw,
        const float* invq, const float* invk, const float* __restrict__ temp, int tid){
    if (tid < 64){
        int head = tid >> 4, base = head*16;
        float t = temp[head];
        float l[16]; float mx = -1e30f;
        #pragma unroll
        for (int s=0;s<16;s++){
            l[s] = raw[tid*64 + base + s] * invq[tid] * invk[base+s] * t;
            mx = fmaxf(mx, l[s]);
        }
        float sum = 0.f;
        #pragma unroll
        for (int s=0;s<16;s++){ l[s] = expf(l[s]-mx); sum += l[s]; }
        float r = 1.f/sum;
        #pragma unroll
        for (int s=0;s<16;s++) out[tid*16+s] = l[s]*r;
    }
    __syncthreads();
}
__device__ __forceinline__ void bdv(float* Cm, const float* at, const float* Wv, int tid){
    int ty = tid>>4, tx = tid&15;
    float acc[4][4] = {};
    for (int s=0;s<16;s++){
        #pragma unroll
        for (int ii=0;ii<4;ii++){
            int row = ty*4+ii; int head = row >> 4;
            float a = at[row*16 + s];
            float4 wv = *(const float4*)&Wv[(head*16+s)*64 + tx*4];
            acc[ii][0] += a*wv.x; acc[ii][1] += a*wv.y;
            acc[ii][2] += a*wv.z; acc[ii][3] += a*wv.w;
        }
    }
    #pragma unroll
    for (int ii=0;ii<4;ii++)
        #pragma unroll
        for (int jj=0;jj<4;jj++)
            Cm[(ty*4+ii)*64 + tx*4+jj] = acc[ii][jj];
    __syncthreads();
}
__device__ __forceinline__ void store_M_half(const float* sR, int b, int buf, int half, int tid){
    size_t base = ((size_t)b*2+buf)*8704;
    for (int i=tid;i<4096;i+=256){
        int r=i>>6, k=i&63;
        unsigned short h,l; split1(sR[i],h,l);
        g_Mh[base + r*136 + half*64 + k] = h;
        g_Ml[base + r*136 + half*64 + k] = l;
    }
    __syncthreads();
}

__global__ void __launch_bounds__(256) smallmath_kernel(
    const float* __restrict__ Wq_c, const float* __restrict__ Wk_c, const float* __restrict__ Wv_c,
    const float* __restrict__ temp_c,
    const float* __restrict__ Wq_d, const float* __restrict__ Wk_d, const float* __restrict__ Wv_d,
    const float* __restrict__ temp_d,
    const float* __restrict__ proj1, const float* __restrict__ proj2,
    const float* __restrict__ fc1c_w, const float* __restrict__ fc2c_w,
    const float* __restrict__ fc1d_w, const float* __restrict__ fc2d_w)
{
    extern __shared__ float sm[];
    float* sA   = sm;
    float* sB   = sA + 4096;
    float* sG   = sB + 4096;
    float* sT   = sG + 4096;
    float* sR   = sT + 4096;
    float* aA   = sR + 4096;
    float* aB   = aA + 1024;
    float* invq  = aB + 1024;
    float* invk1 = invq + 64;
    float* invk2 = invk1 + 64;

    int b = blockIdx.x;
    int br = blockIdx.y;
    int tid = threadIdx.x;

    if (b == 0){
        const float* W1s = br ? fc1d_w : fc1c_w;
        const float* W2s = br ? fc2d_w : fc2c_w;
        int o1 = br*9216, o2 = br*8704;
        for (int i=tid;i<8192;i+=256){
            int r=i>>6, k=i&63;
            unsigned short h,l;
            split1(W1s[i],h,l); g_W1h[o1+r*72+k]=h; g_W1l[o1+r*72+k]=l;
        }
        for (int i=tid;i<8192;i+=256){
            int r=i>>7, k=i&127;
            unsigned short h,l;
            split1(W2s[i],h,l); g_W2h[o2+r*136+k]=h; g_W2l[o2+r*136+k]=l;
        }
    }

    const float* Wq   = br ? Wq_d   : Wq_c;
    const float* Wk   = br ? Wk_d   : Wk_c;
    const float* Wv   = br ? Wv_d   : Wv_c;
    const float* temp = br ? temp_d : temp_c;
    const float* proj = br ? proj2  : proj1;
    int qr = br ? 3 : 2;

    #define GB(bi,bj) (g_gram256 + (size_t)b*65536 + (bi)*64*256 + (bj)*64)

    ld_mat(sA, Wq, tid); ld_matg(sG, GB(qr,qr), tid); __syncthreads();
    mm64_nn(sT, sA, sG, tid);
    rownorm_inv(invq, sT, sA, tid);
    ld_mat(sB, Wk, tid); ld_matg(sG, GB(0,0), tid); __syncthreads();
    mm64_nn(sT, sB, sG, tid);
    rownorm_inv(invk1, sT, sB, tid);
    ld_matg(sG, GB(1,1), tid); __syncthreads();
    mm64_nn(sT, sB, sG, tid);
    rownorm_inv(invk2, sT, sB, tid);
    ld_matg(sG, GB(qr,0), tid); __syncthreads();
    mm64_nn(sT, sA, sG, tid);
    mm64_nt(sR, sT, sB, tid);
    attn_softmax(aA, sR, invq, invk1, temp, tid);
    ld_matg(sG, GB(qr,1), tid); __syncthreads();
    mm64_nn(sT, sA, sG, tid);
    mm64_nt(sR, sT, sB, tid);
    attn_softmax(aB, sR, invq, invk2, temp, tid);

    if (br == 0){
        if (tid < 64){
            #pragma unroll
            for (int s=0;s<16;s++) aA[tid*16+s] *= aB[tid*16+s];
        }
        __syncthreads();
        ld_mat(sB, Wv, tid); __syncthreads();
        bdv(sT, aA, sB, tid);
        ld_mat(sA, proj, tid); __syncthreads();
        mm64_nn(sR, sA, sT, tid);
        store_M_half(sR, b, 0, 0, tid);
        store_M_half(sR, b, 0, 1, tid);
    } else {
        ld_mat(sB, Wv, tid); ld_mat(sA, proj, tid); __syncthreads();
        bdv(sT, aA, sB, tid);
        mm64_nn(sR, sA, sT, tid);
        store_M_half(sR, b, 1, 0, tid);
        bdv(sT, aB, sB, tid);
        mm64_nn(sR, sA, sT, tid);
        store_M_half(sR, b, 1, 1, tid);
    }
    #undef GB
}

// =====================================================================
// K4: unified apply kernel (unchanged — passing at 212us)
// =====================================================================
#define AP_SMEM_BYTES 111616

__global__ void __launch_bounds__(256) apply_kernel(
    int msel, int widx,
    const float* __restrict__ lnw, const float* __restrict__ lnb,
    const float* __restrict__ b1g, const float* __restrict__ b2g,
    float* __restrict__ outp)
{
    extern __shared__ char smraw[];
    unsigned short* sAh = (unsigned short*)(smraw);
    unsigned short* sAl = (unsigned short*)(smraw + 18432);
    unsigned short* sXh = (unsigned short*)(smraw + 36864);
    unsigned short* sXl = (unsigned short*)(smraw + 46080);
    unsigned short* sHh = (unsigned short*)(smraw + 55296);
    unsigned short* sHl = (unsigned short*)(smraw + 73728);
    float* sY  = (float*)(smraw + 92160);
    float* sb1 = (float*)(smraw + 109568);
    float* sb2 = sb1 + 128;
    float* slw = sb2 + 64;
    float* slb = slw + 64;
    float* smu = slb + 64;
    float* srs = smu + 64;

    uint32_t aH = smem_u32(sAh), aL = smem_u32(sAl);
    uint32_t xH = smem_u32(sXh), xL = smem_u32(sXl);
    uint32_t hH = smem_u32(sHh), hL = smem_u32(sHl);

    int b = blockIdx.y, p0 = blockIdx.x*64;
    int tid = threadIdx.x, w = tid>>5, lane = tid&31;
    int wc = (w>>1)*16, wpx = (w&1)*32;

    if (tid < 128) sb1[tid] = b1g[tid];
    if (tid < 64){ sb2[tid]=b2g[tid]; slw[tid]=lnw[tid]; slb[tid]=lnb[tid]; }

    {
        const uint4* mh = (const uint4*)&g_Mh[((size_t)b*2+msel)*8704];
        const uint4* ml = (const uint4*)&g_Ml[((size_t)b*2+msel)*8704];
        uint4* dh = (uint4*)sAh; uint4* dl = (uint4*)sAl;
        for (int i=tid;i<1088;i+=256){ dh[i]=mh[i]; dl[i]=ml[i]; }
    }
    for (int i=tid;i<512;i+=256){
        int c=i>>3, q=i&7;
        size_t off = ((size_t)(b*C64+c))*HW + p0 + q*8;
        *(uint4*)&sXh[c*72 + q*8] = *(const uint4*)&g_hi[off];
        *(uint4*)&sXl[c*72 + q*8] = *(const uint4*)&g_lo[off];
    }
    __syncthreads();

    float acc[4][4];
    #pragma unroll
    for (int g=0;g<4;g++)
        #pragma unroll
        for (int k=0;k<4;k++) acc[g][k]=0.f;
    uint32_t offA = (uint32_t)(((wc+(lane&15))*136 + ((lane>>4)&1)*8)*2);
    uint32_t offB = (uint32_t)((((lane&7)+((lane>>3)&1)*8)*72 + ((lane>>4)&1)*8)*2);

    #pragma unroll
    for (int k16=0;k16<4;k16++){
        uint32_t Ah[4],Al[4];
        ldm_x4(Ah, aH + offA + k16*32);
        ldm_x4(Al, aL + offA + k16*32);
        #pragma unroll
        for (int hf=0;hf<2;hf++){
            uint32_t Bh[4],Bl[4];
            uint32_t ob = offB + (uint32_t)(k16*16*144 + (wpx+hf*16)*2);
            ldm_t4(Bh, xH + ob); ldm_t4(Bl, xL + ob);
            MMA3(acc[hf*2],   Ah, Al, Bh[0],Bh[1], Bl[0],Bl[1]);
            MMA3(acc[hf*2+1], Ah, Al, Bh[2],Bh[3], Bl[2],Bl[3]);
        }
    }
    __syncthreads();
    for (int i=tid;i<512;i+=256){
        int c=i>>3, q=i&7;
        size_t off = (size_t)TOT + ((size_t)(b*C64+c))*HW + p0 + q*8;
        *(uint4*)&sXh[c*72 + q*8] = *(const uint4*)&g_hi[off];
        *(uint4*)&sXl[c*72 + q*8] = *(const uint4*)&g_lo[off];
    }
    __syncthreads();
    #pragma unroll
    for (int k16=0;k16<4;k16++){
        uint32_t Ah[4],Al[4];
        ldm_x4(Ah, aH + offA + 128 + k16*32);
        ldm_x4(Al, aL + offA + 128 + k16*32);
        #pragma unroll
        for (int hf=0;hf<2;hf++){
            uint32_t Bh[4],Bl[4];
            uint32_t ob = offB + (uint32_t)(k16*16*144 + (wpx+hf*16)*2);
            ldm_t4(Bh, xH + ob); ldm_t4(Bl, xL + ob);
            MMA3(acc[hf*2],   Ah, Al, Bh[0],Bh[1], Bl[0],Bl[1]);
            MMA3(acc[hf*2+1], Ah, Al, Bh[2],Bh[3], Bl[2],Bl[3]);
        }
    }
    {
        int c0 = wc + (lane>>2);
        int pxb = wpx + (lane&3)*2;
        #pragma unroll
        for (int g=0; g<4; g++){
            int px = pxb + g*8;
            *(float2*)&sY[c0*68+px]     = make_float2(acc[g][0], acc[g][1]);
            *(float2*)&sY[(c0+8)*68+px] = make_float2(acc[g][2], acc[g][3]);
        }
    }
    __syncthreads();

    if (tid < 64){
        float s=0.f, ss=0.f;
        for (int c=0;c<64;c++){ float v = sY[c*68+tid]; s += v; ss += v*v; }
        float mu = s*(1.f/64.f);
        float var = ss*(1.f/64.f) - mu*mu;
        smu[tid] = mu; srs[tid] = rsqrtf(var + EPSF);
    }
    __syncthreads();
    for (int i=tid;i<2048;i+=256){
        int c = i>>5, px = (i&31)*2;
        float z0 = (sY[c*68+px  ]-smu[px  ])*srs[px  ]*slw[c] + slb[c];
        float z1 = (sY[c*68+px+1]-smu[px+1])*srs[px+1]*slw[c] + slb[c];
        uint32_t hh, ll; split2(z0, z1, hh, ll);
        *(uint32_t*)&sXh[c*72+px] = hh;
        *(uint32_t*)&sXl[c*72+px] = ll;
    }
    {
        const uint4* wh = (const uint4*)&g_W1h[widx*9216];
        const uint4* wl = (const uint4*)&g_W1l[widx*9216];
        uint4* dh = (uint4*)sAh; uint4* dl = (uint4*)sAl;
        for (int i=tid;i<1152;i+=256){ dh[i]=wh[i]; dl[i]=wl[i]; }
    }
    __syncthreads();

    {
        int wh_ = (w>>1)*32;
        float a2[2][4][4];
        #pragma unroll
        for (int m=0;m<2;m++)
            #pragma unroll
            for (int g=0;g<4;g++)
                #pragma unroll
                for (int k=0;k<4;k++) a2[m][g][k]=0.f;
        uint32_t offA2 = (uint32_t)(((wh_+(lane&15))*72 + ((lane>>4)&1)*8)*2);
        #pragma unroll
        for (int k16=0;k16<4;k16++){
            uint32_t Ah0[4],Al0[4],Ah1[4],Al1[4];
            ldm_x4(Ah0, aH + offA2 + k16*32);
            ldm_x4(Al0, aL + offA2 + k16*32);
            ldm_x4(Ah1, aH + offA2 + k16*32 + 16*144);
            ldm_x4(Al1, aL + offA2 + k16*32 + 16*144);
            #pragma unroll
            for (int hf=0;hf<2;hf++){
                uint32_t Bh[4],Bl[4];
                uint32_t ob = offB + (uint32_t)(k16*16*144 + (wpx+hf*16)*2);
                ldm_t4(Bh, xH + ob); ldm_t4(Bl, xL + ob);
                int g0=hf*2, g1=hf*2+1;
                MMA3(a2[0][g0], Ah0, Al0, Bh[0],Bh[1], Bl[0],Bl[1]);
                MMA3(a2[0][g1], Ah0, Al0, Bh[2],Bh[3], Bl[2],Bl[3]);
                MMA3(a2[1][g0], Ah1, Al1, Bh[0],Bh[1], Bl[0],Bl[1]);
                MMA3(a2[1][g1], Ah1, Al1, Bh[2],Bh[3], Bl[2],Bl[3]);
            }
        }
        int hb = wh_ + (lane>>2);
        int pxb = wpx + (lane&3)*2;
        #pragma unroll
        for (int m=0;m<2;m++){
            int r0 = hb + m*16, r1 = r0 + 8;
            float bb0 = sb1[r0], bb1 = sb1[r1];
            #pragma unroll
            for (int g=0; g<4; g++){
                int px = pxb + g*8;
                float v0 = gelu_f(a2[m][g][0] + bb0);
                float v1 = gelu_f(a2[m][g][1] + bb0);
                float v2 = gelu_f(a2[m][g][2] + bb1);
                float v3 = gelu_f(a2[m][g][3] + bb1);
                uint32_t hh, ll;
                split2(v0, v1, hh, ll);
                *(uint32_t*)&sHh[r0*72+px] = hh; *(uint32_t*)&sHl[r0*72+px] = ll;
                split2(v2, v3, hh, ll);
                *(uint32_t*)&sHh[r1*72+px] = hh; *(uint32_t*)&sHl[r1*72+px] = ll;
            }
        }
    }
    __syncthreads();
    {
        const uint4* wh = (const uint4*)&g_W2h[widx*8704];
        const uint4* wl = (const uint4*)&g_W2l[widx*8704];
        uint4* dh = (uint4*)sAh; uint4* dl = (uint4*)sAl;
        for (int i=tid;i<1088;i+=256){ dh[i]=wh[i]; dl[i]=wl[i]; }
    }
    __syncthreads();

    {
        float a3[4][4];
        #pragma unroll
        for (int g=0;g<4;g++)
            #pragma unroll
            for (int k=0;k<4;k++) a3[g][k]=0.f;
        uint32_t offA3 = (uint32_t)(((wc+(lane&15))*136 + ((lane>>4)&1)*8)*2);
        #pragma unroll
        for (int k16=0;k16<8;k16++){
            uint32_t Ah[4],Al[4];
            ldm_x4(Ah, aH + offA3 + k16*32);
            ldm_x4(Al, aL + offA3 + k16*32);
            #pragma unroll
            for (int hf=0;hf<2;hf++){
                uint32_t Bh[4],Bl[4];
                uint32_t ob = offB + (uint32_t)(k16*16*144 + (wpx+hf*16)*2);
                ldm_t4(Bh, hH + ob); ldm_t4(Bl, hL + ob);
                MMA3(a3[hf*2],   Ah, Al, Bh[0],Bh[1], Bl[0],Bl[1]);
                MMA3(a3[hf*2+1], Ah, Al, Bh[2],Bh[3], Bl[2],Bl[3]);
            }
        }
        int c0 = wc + (lane>>2);
        int pxb = wpx + (lane&3)*2;
        float bc0 = sb2[c0], bc1 = sb2[c0+8];
        #pragma unroll
        for (int g=0; g<4; g++){
            int px = pxb + g*8;
            float2 o;
            o.x = a3[g][0] + bc0 + sY[c0*68+px];
            o.y = a3[g][1] + bc0 + sY[c0*68+px+1];
            *(float2*)&outp[((size_t)(b*C64+c0))*HW + p0 + px] = o;
            o.x = a3[g][2] + bc1 + sY[(c0+8)*68+px];
            o.y = a3[g][3] + bc1 + sY[(c0+8)*68+px+1];
            *(float2*)&outp[((size_t)(b*C64+c0+8))*HW + p0 + px] = o;
        }
    }
}

// =====================================================================
extern "C" void kernel_launch(void* const* d_in, const int* in_sizes, int n_in,
                              void* d_out, int out_size)
{
    (void)in_sizes; (void)n_in; (void)out_size;
    const float* image  = (const float*)d_in[0];
    const float* event_ = (const float*)d_in[1];
    const float* Wq_c = (const float*)d_in[2];
    const float* Wk_c = (const float*)d_in[3];
    const float* Wv_c = (const float*)d_in[4];
    const float* temp_c = (const float*)d_in[5];
    const float* Wq_d = (const float*)d_in[6];
    const float* Wk_d = (const float*)d_in[7];
    const float* Wv_d = (const float*)d_in[8];
    const float* temp_d = (const float*)d_in[9];
    const float* ln_img_w = (const float*)d_in[10];
    const float* ln_img_b = (const float*)d_in[11];
    const float* ln_evt_w = (const float*)d_in[12];
    const float* ln_evt_b = (const float*)d_in[13];
    const float* ln_com_w = (const float*)d_in[14];
    const float* ln_com_b = (const float*)d_in[15];
    const float* ln_dif_w = (const float*)d_in[16];
    const float* ln_dif_b = (const float*)d_in[17];
    const float* ln1_w = (const float*)d_in[18];
    const float* ln1_b = (const float*)d_in[19];
    const float* ln2_w = (const float*)d_in[20];
    const float* ln2_b = (const float*)d_in[21];
    const float* fc1c_w = (const float*)d_in[22];
    const float* fc1c_b = (const float*)d_in[23];
    const float* fc2c_w = (const float*)d_in[24];
    const float* fc2c_b = (const float*)d_in[25];
    const float* fc1d_w = (const float*)d_in[26];
    const float* fc1d_b = (const float*)d_in[27];
    const float* fc2d_w = (const float*)d_in[28];
    const float* fc2d_b = (const float*)d_in[29];
    const float* proj1_w = (const float*)d_in[30];
    const float* proj2_w = (const float*)d_in[31];

    float* outc = (float*)d_out;
    float* outd = outc + (size_t)BATCH*C64*HW;

    const int SM3 = (4096*5 + 1024*2 + 64*3) * sizeof(float);

    cudaFuncSetAttribute(smallmath_kernel, cudaFuncAttributeMaxDynamicSharedMemorySize, SM3);
    cudaFuncSetAttribute(apply_kernel,     cudaFuncAttributeMaxDynamicSharedMemorySize, AP_SMEM_BYTES);

    ln_kernel<<<BATCH*(HW/512), 256>>>(image, event_,
        ln_img_w, ln_img_b, ln_evt_w, ln_evt_b,
        ln_com_w, ln_com_b, ln_dif_w, ln_dif_b);

    dim3 g2(GK_KSPLIT, 3, BATCH);
    gram_mma_kernel<<<g2, 256>>>();

    dim3 g3(BATCH, 2);
    smallmath_kernel<<<g3, 256, SM3>>>(Wq_c, Wk_c, Wv_c, temp_c,
                                       Wq_d, Wk_d, Wv_d, temp_d,
                                       proj1_w, proj2_w,
                                       fc1c_w, fc2c_w, fc1d_w, fc2d_w);

    dim3 g4(HW/64, BATCH);
    apply_kernel<<<g4, 256, AP_SMEM_BYTES>>>(0, 0, ln1_w, ln1_b, fc1c_b, fc2c_b, outc);
    apply_kernel<<<g4, 256, AP_SMEM_BYTES>>>(1, 1, ln2_w, ln2_b, fc1d_b, fc2d_b, outd);
}

// round 12
// speedup vs baseline: 1.3051x; 1.1354x over previous
#include <cuda_runtime.h>
#include <cuda_bf16.h>
#include <math.h>
#include <stdint.h>

#define BATCH 4
#define C64   64
#define HW    65536
#define HEADS 4
#define HID   128
#define EPSF  1e-5f

#define TOT (BATCH*C64*HW)

// ---------------- scratch (device globals; no allocs) ----------------
__device__ unsigned short g_hi[(size_t)4*TOT];
__device__ unsigned short g_lo[(size_t)4*TOT];
__device__ float g_gram256[BATCH*256*256];
// pre-split M (pitch 136): per batch: [0]=(Mc|Mc), [1]=(Mid|Med)
__device__ unsigned short g_Mh[BATCH*2*8704];
__device__ unsigned short g_Ml[BATCH*2*8704];
// pre-split weights: W1 pitch 72 (128 rows), W2 pitch 136 (64 rows); [0]=common,[1]=diff
__device__ unsigned short g_W1h[2*9216];
__device__ unsigned short g_W1l[2*9216];
__device__ unsigned short g_W2h[2*8704];
__device__ unsigned short g_W2l[2*8704];

// ======================= helpers ========================
__device__ __forceinline__ uint32_t smem_u32(const void* p){
    uint32_t a;
    asm("{ .reg .u64 t; cvta.to.shared.u64 t, %1; cvt.u32.u64 %0, t; }" : "=r"(a) : "l"(p));
    return a;
}
__device__ __forceinline__ void ldm_x4(uint32_t* r, uint32_t addr){
    asm volatile("ldmatrix.sync.aligned.m8n8.x4.shared.b16 {%0,%1,%2,%3}, [%4];"
        : "=r"(r[0]), "=r"(r[1]), "=r"(r[2]), "=r"(r[3]) : "r"(addr));
}
__device__ __forceinline__ void ldm_t4(uint32_t* r, uint32_t addr){
    asm volatile("ldmatrix.sync.aligned.m8n8.x4.trans.shared.b16 {%0,%1,%2,%3}, [%4];"
        : "=r"(r[0]), "=r"(r[1]), "=r"(r[2]), "=r"(r[3]) : "r"(addr));
}
__device__ __forceinline__ void mma_bf16(float& d0, float& d1, float& d2, float& d3,
        uint32_t a0, uint32_t a1, uint32_t a2, uint32_t a3,
        uint32_t b0, uint32_t b1){
    asm volatile("mma.sync.aligned.m16n8k16.row.col.f32.bf16.bf16.f32 "
        "{%0,%1,%2,%3}, {%4,%5,%6,%7}, {%8,%9}, {%0,%1,%2,%3};"
        : "+f"(d0), "+f"(d1), "+f"(d2), "+f"(d3)
        : "r"(a0), "r"(a1), "r"(a2), "r"(a3), "r"(b0), "r"(b1));
}
#define MMA3(ACC, AH, AL, BH0, BH1, BL0, BL1) do { \
    mma_bf16((ACC)[0],(ACC)[1],(ACC)[2],(ACC)[3], (AH)[0],(AH)[1],(AH)[2],(AH)[3], (BH0),(BH1)); \
    mma_bf16((ACC)[0],(ACC)[1],(ACC)[2],(ACC)[3], (AH)[0],(AH)[1],(AH)[2],(AH)[3], (BL0),(BL1)); \
    mma_bf16((ACC)[0],(ACC)[1],(ACC)[2],(ACC)[3], (AL)[0],(AL)[1],(AL)[2],(AL)[3], (BH0),(BH1)); \
} while(0)

__device__ __forceinline__ void split1(float a, unsigned short& h, unsigned short& l){
    __nv_bfloat16 hb = __float2bfloat16(a);
    float r = a - __bfloat162float(hb);
    h = __bfloat16_as_ushort(hb);
    l = __bfloat16_as_ushort(__float2bfloat16(r));
}
__device__ __forceinline__ void split2(float a, float b, uint32_t& h, uint32_t& l){
    __nv_bfloat16 ha=__float2bfloat16(a), hb=__float2bfloat16(b);
    float ra = a-__bfloat162float(ha), rb = b-__bfloat162float(hb);
    h = (uint32_t)__bfloat16_as_ushort(ha) | ((uint32_t)__bfloat16_as_ushort(hb)<<16);
    l = (uint32_t)__bfloat16_as_ushort(__float2bfloat16(ra))
      | ((uint32_t)__bfloat16_as_ushort(__float2bfloat16(rb))<<16);
}
__device__ __forceinline__ float gelu_f(float h){
    return 0.5f*h*(1.f + erff(h*0.70710678118654752f));
}

// =====================================================================
// K1: channel LayerNorm -> pre-split hi/lo planes (+ zero gram accum)
// =====================================================================
__global__ void __launch_bounds__(256) ln_kernel(
    const float* __restrict__ img, const float* __restrict__ evt,
    const float* __restrict__ wi, const float* __restrict__ bi,
    const float* __restrict__ we, const float* __restrict__ be,
    const float* __restrict__ wc, const float* __restrict__ bc,
    const float* __restrict__ wd, const float* __restrict__ bd)
{
    if (blockIdx.x < 256) {
        int base = blockIdx.x * 1024 + threadIdx.x * 4;
        g_gram256[base+0] = 0.f; g_gram256[base+1] = 0.f;
        g_gram256[base+2] = 0.f; g_gram256[base+3] = 0.f;
    }
    int b  = blockIdx.x >> 7;
    int p  = ((blockIdx.x & 127) << 9) + threadIdx.x*2;
    const float* ip = img + (size_t)b*C64*HW + p;
    const float* ep = evt + (size_t)b*C64*HW + p;

    float si0=0,si1=0,se0=0,se1=0,sii0=0,sii1=0,see0=0,see1=0,sie0=0,sie1=0;
    #pragma unroll 8
    for (int c=0;c<C64;c++){
        float2 iv = *(const float2*)&ip[(size_t)c*HW];
        float2 ev = *(const float2*)&ep[(size_t)c*HW];
        si0+=iv.x; si1+=iv.y; se0+=ev.x; se1+=ev.y;
        sii0+=iv.x*iv.x; sii1+=iv.y*iv.y;
        see0+=ev.x*ev.x; see1+=ev.y*ev.y;
        sie0+=iv.x*ev.x; sie1+=iv.y*ev.y;
    }
    const float inv64 = 1.f/64.f;
    float mi0=si0*inv64, mi1=si1*inv64, me0=se0*inv64, me1=se1*inv64;
    float mc0=(si0+se0)*inv64, mc1=(si1+se1)*inv64;
    float md0=(si0-se0)*inv64, md1=(si1-se1)*inv64;
    float ri0=rsqrtf(sii0*inv64-mi0*mi0+EPSF), ri1=rsqrtf(sii1*inv64-mi1*mi1+EPSF);
    float re0=rsqrtf(see0*inv64-me0*me0+EPSF), re1=rsqrtf(see1*inv64-me1*me1+EPSF);
    float rc0=rsqrtf((sii0+2.f*sie0+see0)*inv64-mc0*mc0+EPSF);
    float rc1=rsqrtf((sii1+2.f*sie1+see1)*inv64-mc1*mc1+EPSF);
    float rd0=rsqrtf((sii0-2.f*sie0+see0)*inv64-md0*md0+EPSF);
    float rd1=rsqrtf((sii1-2.f*sie1+see1)*inv64-md1*md1+EPSF);

    size_t ob = (size_t)b*C64*HW + p;
    #pragma unroll 4
    for (int c=0;c<C64;c++){
        float2 iv = *(const float2*)&ip[(size_t)c*HW];
        float2 ev = *(const float2*)&ep[(size_t)c*HW];
        size_t o = ob + (size_t)c*HW;
        uint32_t hh, ll;
        split2((iv.x-mi0)*ri0*wi[c]+bi[c], (iv.y-mi1)*ri1*wi[c]+bi[c], hh, ll);
        *(uint32_t*)&g_hi[o] = hh; *(uint32_t*)&g_lo[o] = ll;
        split2((ev.x-me0)*re0*we[c]+be[c], (ev.y-me1)*re1*we[c]+be[c], hh, ll);
        *(uint32_t*)&g_hi[(size_t)TOT + o] = hh; *(uint32_t*)&g_lo[(size_t)TOT + o] = ll;
        split2((iv.x+ev.x-mc0)*rc0*wc[c]+bc[c], (iv.y+ev.y-mc1)*rc1*wc[c]+bc[c], hh, ll);
        *(uint32_t*)&g_hi[(size_t)2*TOT + o] = hh; *(uint32_t*)&g_lo[(size_t)2*TOT + o] = ll;
        split2((iv.x-ev.x-md0)*rd0*wd[c]+bd[c], (iv.y-ev.y-md1)*rd1*wd[c]+bd[c], hh, ll);
        *(uint32_t*)&g_hi[(size_t)3*TOT + o] = hh; *(uint32_t*)&g_lo[(size_t)3*TOT + o] = ll;
    }
}

// =====================================================================
// K2: stacked Gram, 3 tiles. NEW: diagonal tiles (0 and 2) have A==B,
// so B smem is aliased to A smem and B gmem loads are skipped
// (removes 1/3 of gram DRAM traffic). Per-CTA MMA code unchanged.
// =====================================================================
#define GK_KSPLIT 32
#define GK_KRANGE (HW/GK_KSPLIT)
#define GK_KC     32
#define GK_NCH    (GK_KRANGE/GK_KC)
#define SPITCH    40

__global__ void __launch_bounds__(256) gram_mma_kernel()
{
    __shared__ __align__(16) unsigned short sAhi[128*SPITCH];
    __shared__ __align__(16) unsigned short sAlo[128*SPITCH];
    __shared__ __align__(16) unsigned short sBhi[128*SPITCH];
    __shared__ __align__(16) unsigned short sBlo[128*SPITCH];

    int tid = threadIdx.x;
    int wid = tid >> 5, lane = tid & 31;
    int ks = blockIdx.x, tileid = blockIdx.y, b = blockIdx.z;
    int m0 = (tileid==0) ? 0 : 128;
    int n0 = (tileid==2) ? 128 : 0;
    bool diag = (tileid != 1);
    int warp_m = (wid >> 1) * 32;
    int warp_n = (wid & 1) * 64;

    int lr = tid >> 1;
    int lc = (tid & 1) * 16;
    size_t offA_g = (size_t)((m0+lr)>>6)*TOT + ((size_t)(b*C64)+((m0+lr)&63))*HW + (size_t)ks*GK_KRANGE + lc;
    size_t offB_g = (size_t)((n0+lr)>>6)*TOT + ((size_t)(b*C64)+((n0+lr)&63))*HW + (size_t)ks*GK_KRANGE + lc;
    const unsigned short* sAg_h = g_hi + offA_g;
    const unsigned short* sAg_l = g_lo + offA_g;
    const unsigned short* sBg_h = g_hi + offB_g;
    const unsigned short* sBg_l = g_lo + offB_g;

    uint32_t aHi = smem_u32(sAhi), aLo = smem_u32(sAlo);
    uint32_t bHi = diag ? aHi : smem_u32(sBhi);
    uint32_t bLo = diag ? aLo : smem_u32(sBlo);

    int rowA = warp_m + (lane & 15);
    int colA = (lane >> 4) * 8;
    uint32_t offA = (uint32_t)(rowA*SPITCH + colA) * 2;
    int rowB = warp_n + (lane & 7) + ((lane >> 4) & 1) * 8;
    int colB = ((lane >> 3) & 1) * 8;
    uint32_t offB = (uint32_t)(rowB*SPITCH + colB) * 2;

    float acc[2][8][4];
    #pragma unroll
    for (int i=0;i<2;i++)
        #pragma unroll
        for (int j=0;j<8;j++)
            #pragma unroll
            for (int k=0;k<4;k++) acc[i][j][k] = 0.f;

    unsigned short* dAh = sAhi + lr*SPITCH + lc;
    unsigned short* dAl = sAlo + lr*SPITCH + lc;
    unsigned short* dBh = sBhi + lr*SPITCH + lc;
    unsigned short* dBl = sBlo + lr*SPITCH + lc;

    for (int t = 0; t < GK_NCH; t++) {
        __syncthreads();
        int kc = t * GK_KC;
        *(uint4*)&dAh[0] = *(const uint4*)&sAg_h[kc];
        *(uint4*)&dAh[8] = *(const uint4*)&sAg_h[kc+8];
        *(uint4*)&dAl[0] = *(const uint4*)&sAg_l[kc];
        *(uint4*)&dAl[8] = *(const uint4*)&sAg_l[kc+8];
        if (!diag){
            *(uint4*)&dBh[0] = *(const uint4*)&sBg_h[kc];
            *(uint4*)&dBh[8] = *(const uint4*)&sBg_h[kc+8];
            *(uint4*)&dBl[0] = *(const uint4*)&sBg_l[kc];
            *(uint4*)&dBl[8] = *(const uint4*)&sBg_l[kc+8];
        }
        __syncthreads();
        #pragma unroll
        for (int k16 = 0; k16 < GK_KC; k16 += 16) {
            uint32_t kb = (uint32_t)(k16 * 2);
            uint32_t Ah0[4], Ah1[4], Al0[4], Al1[4];
            ldm_x4(Ah0, aHi + offA + kb);
            ldm_x4(Ah1, aHi + offA + kb + 16*SPITCH*2);
            ldm_x4(Al0, aLo + offA + kb);
            ldm_x4(Al1, aLo + offA + kb + 16*SPITCH*2);
            #pragma unroll
            for (int np = 0; np < 4; np++) {
                uint32_t Bh[4], Bl[4];
                uint32_t ob = offB + kb + (uint32_t)(np*16*SPITCH*2);
                ldm_x4(Bh, bHi + ob);
                ldm_x4(Bl, bLo + ob);
                int n2 = np*2;
                MMA3(acc[0][n2],   Ah0, Al0, Bh[0],Bh[1], Bl[0],Bl[1]);
                MMA3(acc[0][n2+1], Ah0, Al0, Bh[2],Bh[3], Bl[2],Bl[3]);
                MMA3(acc[1][n2],   Ah1, Al1, Bh[0],Bh[1], Bl[0],Bl[1]);
                MMA3(acc[1][n2+1], Ah1, Al1, Bh[2],Bh[3], Bl[2],Bl[3]);
            }
        }
    }

    float* G = g_gram256 + (size_t)b*65536;
    int rbase = m0 + warp_m + (lane >> 2);
    int cbase = n0 + warp_n + (lane & 3)*2;
    #pragma unroll
    for (int i=0;i<2;i++){
        #pragma unroll
        for (int ns=0;ns<8;ns++){
            int rr = rbase + i*16;
            int cc = cbase + ns*8;
            atomicAdd(&G[rr*256 + cc],       acc[i][ns][0]);
            atomicAdd(&G[rr*256 + cc + 1],   acc[i][ns][1]);
            atomicAdd(&G[(rr+8)*256 + cc],   acc[i][ns][2]);
            atomicAdd(&G[(rr+8)*256 + cc+1], acc[i][ns][3]);
        }
    }
}

// =====================================================================
// K3: per-batch, per-branch math -> pre-split M + weights.
// =====================================================================
__device__ __forceinline__ void ld_mat(float* s, const float* __restrict__ g, int tid){
    for (int i=tid; i<4096; i+=256) s[i] = g[i];
}
__device__ __forceinline__ void ld_matg(float* s, const float* __restrict__ g, int tid){
    for (int i=tid; i<4096; i+=256) s[i] = g[(i>>6)*256 + (i&63)];
}
__device__ __forceinline__ void mm64_nn(float* Cm, const float* A, const float* Bm, int tid){
    int ty = tid>>4, tx = tid&15;
    float acc[4][4] = {};
    for (int k=0;k<64;k++){
        float4 bv = *(const float4*)&Bm[k*64 + tx*4];
        float b4[4] = {bv.x,bv.y,bv.z,bv.w};
        #pragma unroll
        for (int ii=0;ii<4;ii++){
            float a = A[(ty*4+ii)*64 + k];
            #pragma unroll
            for (int jj=0;jj<4;jj++) acc[ii][jj] += a*b4[jj];
        }
    }
    #pragma unroll
    for (int ii=0;ii<4;ii++)
        #pragma unroll
        for (int jj=0;jj<4;jj++)
            Cm[(ty*4+ii)*64 + tx*4+jj] = acc[ii][jj];
    __syncthreads();
}
__device__ __forceinline__ void mm64_nt(float* Cm, const float* A, const float* Bm, int tid){
    int ty = tid>>4, tx = tid&15;
    float acc[4][4] = {};
    for (int k=0;k<64;k++){
        float a4[4], b4[4];
        #pragma unroll
        for (int ii=0;ii<4;ii++) a4[ii] = A[(ty*4+ii)*64 + k];
        #pragma unroll
        for (int jj=0;jj<4;jj++) b4[jj] = Bm[(tx*4+jj)*64 + k];
        #pragma unroll
        for (int ii=0;ii<4;ii++)
            #pragma unroll
            for (int jj=0;jj<4;jj++) acc[ii][jj] += a4[ii]*b4[jj];
    }
    #pragma unroll
    for (int ii=0;ii<4;ii++)
        #pragma unroll
        for (int jj=0;jj<4;jj++)
            Cm[(ty*4+ii)*64 + tx*4+jj] = acc[ii][jj];
    __syncthreads();
}
__device__ __forceinline__ void rownorm_inv(float* inv, const float* T, const float* Wm, int tid){
    if (tid < 64){
        float s = 0.f;
        for (int k=0;k<64;k++) s += T[tid*64+k]*Wm[tid*64+k];
        inv[tid] = 1.f / fmaxf(sqrtf(fmaxf(s, 0.f)), 1e-12f);
    }
    __syncthreads();
}
__device__ __forceinline__ void attn_softmax(float* out, const float* raw,
        const float* invq, const float* invk, const float* __restrict__ temp, int tid){
    if (tid < 64){
        int head = tid >> 4, base = head*16;
        float t = temp[head];
        float l[16]; float mx = -1e30f;
        #pragma unroll
        for (int s=0;s<16;s++){
            l[s] = raw[tid*64 + base + s] * invq[tid] * invk[base+s] * t;
            mx = fmaxf(mx, l[s]);
        }
        float sum = 0.f;
        #pragma unroll
        for (int s=0;s<16;s++){ l[s] = expf(l[s]-mx); sum += l[s]; }
        float r = 1.f/sum;
        #pragma unroll
        for (int s=0;s<16;s++) out[tid*16+s] = l[s]*r;
    }
    __syncthreads();
}
__device__ __forceinline__ void bdv(float* Cm, const float* at, const float* Wv, int tid){
    int ty = tid>>4, tx = tid&15;
    float acc[4][4] = {};
    for (int s=0;s<16;s++){
        #pragma unroll
        for (int ii=0;ii<4;ii++){
            int row = ty*4+ii; int head = row >> 4;
            float a = at[row*16 + s];
            float4 wv = *(const float4*)&Wv[(head*16+s)*64 + tx*4];
            acc[ii][0] += a*wv.x; acc[ii][1] += a*wv.y;
            acc[ii][2] += a*wv.z; acc[ii][3] += a*wv.w;
        }
    }
    #pragma unroll
    for (int ii=0;ii<4;ii++)
        #pragma unroll
        for (int jj=0;jj<4;jj++)
            Cm[(ty*4+ii)*64 + tx*4+jj] = acc[ii][jj];
    __syncthreads();
}
__device__ __forceinline__ void store_M_half(const float* sR, int b, int buf, int half, int tid){
    size_t base = ((size_t)b*2+buf)*8704;
    for (int i=tid;i<4096;i+=256){
        int r=i>>6, k=i&63;
        unsigned short h,l; split1(sR[i],h,l);
        g_Mh[base + r*136 + half*64 + k] = h;
        g_Ml[base + r*136 + half*64 + k] = l;
    }
    __syncthreads();
}

__global__ void __launch_bounds__(256) smallmath_kernel(
    const float* __restrict__ Wq_c, const float* __restrict__ Wk_c, const float* __restrict__ Wv_c,
    const float* __restrict__ temp_c,
    const float* __restrict__ Wq_d, const float* __restrict__ Wk_d, const float* __restrict__ Wv_d,
    const float* __restrict__ temp_d,
    const float* __restrict__ proj1, const float* __restrict__ proj2,
    const float* __restrict__ fc1c_w, const float* __restrict__ fc2c_w,
    const float* __restrict__ fc1d_w, const float* __restrict__ fc2d_w)
{
    extern __shared__ float sm[];
    float* sA   = sm;
    float* sB   = sA + 4096;
    float* sG   = sB + 4096;
    float* sT   = sG + 4096;
    float* sR   = sT + 4096;
    float* aA   = sR + 4096;
    float* aB   = aA + 1024;
    float* invq  = aB + 1024;
    float* invk1 = invq + 64;
    float* invk2 = invk1 + 64;

    int b = blockIdx.x;
    int br = blockIdx.y;
    int tid = threadIdx.x;

    if (b == 0){
        const float* W1s = br ? fc1d_w : fc1c_w;
        const float* W2s = br ? fc2d_w : fc2c_w;
        int o1 = br*9216, o2 = br*8704;
        for (int i=tid;i<8192;i+=256){
            int r=i>>6, k=i&63;
            unsigned short h,l;
            split1(W1s[i],h,l); g_W1h[o1+r*72+k]=h; g_W1l[o1+r*72+k]=l;
        }
        for (int i=tid;i<8192;i+=256){
            int r=i>>7, k=i&127;
            unsigned short h,l;
            split1(W2s[i],h,l); g_W2h[o2+r*136+k]=h; g_W2l[o2+r*136+k]=l;
        }
    }

    const float* Wq   = br ? Wq_d   : Wq_c;
    const float* Wk   = br ? Wk_d   : Wk_c;
    const float* Wv   = br ? Wv_d   : Wv_c;
    const float* temp = br ? temp_d : temp_c;
    const float* proj = br ? proj2  : proj1;
    int qr = br ? 3 : 2;

    #define GB(bi,bj) (g_gram256 + (size_t)b*65536 + (bi)*64*256 + (bj)*64)

    ld_mat(sA, Wq, tid); ld_matg(sG, GB(qr,qr), tid); __syncthreads();
    mm64_nn(sT, sA, sG, tid);
    rownorm_inv(invq, sT, sA, tid);
    ld_mat(sB, Wk, tid); ld_matg(sG, GB(0,0), tid); __syncthreads();
    mm64_nn(sT, sB, sG, tid);
    rownorm_inv(invk1, sT, sB, tid);
    ld_matg(sG, GB(1,1), tid); __syncthreads();
    mm64_nn(sT, sB, sG, tid);
    rownorm_inv(invk2, sT, sB, tid);
    ld_matg(sG, GB(qr,0), tid); __syncthreads();
    mm64_nn(sT, sA, sG, tid);
    mm64_nt(sR, sT, sB, tid);
    attn_softmax(aA, sR, invq, invk1, temp, tid);
    ld_matg(sG, GB(qr,1), tid); __syncthreads();
    mm64_nn(sT, sA, sG, tid);
    mm64_nt(sR, sT, sB, tid);
    attn_softmax(aB, sR, invq, invk2, temp, tid);

    if (br == 0){
        if (tid < 64){
            #pragma unroll
            for (int s=0;s<16;s++) aA[tid*16+s] *= aB[tid*16+s];
        }
        __syncthreads();
        ld_mat(sB, Wv, tid); __syncthreads();
        bdv(sT, aA, sB, tid);
        ld_mat(sA, proj, tid); __syncthreads();
        mm64_nn(sR, sA, sT, tid);
        store_M_half(sR, b, 0, 0, tid);
        store_M_half(sR, b, 0, 1, tid);
    } else {
        ld_mat(sB, Wv, tid); ld_mat(sA, proj, tid); __syncthreads();
        bdv(sT, aA, sB, tid);
        mm64_nn(sR, sA, sT, tid);
        store_M_half(sR, b, 1, 0, tid);
        bdv(sT, aB, sB, tid);
        mm64_nn(sR, sA, sT, tid);
        store_M_half(sR, b, 1, 1, tid);
    }
    #undef GB
}

// =====================================================================
// K4: unified apply kernel; grid z selects branch (0=common, 1=diff).
// NEW vs R11: single fused launch; ne tile prefetched into registers
// before GEMM1 pass A so its gmem latency overlaps MMA work.
// =====================================================================
#define AP_SMEM_BYTES 111616

__global__ void __launch_bounds__(256) apply_kernel(
    const float* __restrict__ ln1w, const float* __restrict__ ln1b,
    const float* __restrict__ b1c, const float* __restrict__ b2c,
    const float* __restrict__ ln2w, const float* __restrict__ ln2b,
    const float* __restrict__ b1d, const float* __restrict__ b2d,
    float* __restrict__ outc_, float* __restrict__ outd_)
{
    extern __shared__ char smraw[];
    unsigned short* sAh = (unsigned short*)(smraw);
    unsigned short* sAl = (unsigned short*)(smraw + 18432);
    unsigned short* sXh = (unsigned short*)(smraw + 36864);
    unsigned short* sXl = (unsigned short*)(smraw + 46080);
    unsigned short* sHh = (unsigned short*)(smraw + 55296);
    unsigned short* sHl = (unsigned short*)(smraw + 73728);
    float* sY  = (float*)(smraw + 92160);
    float* sb1 = (float*)(smraw + 109568);
    float* sb2 = sb1 + 128;
    float* slw = sb2 + 64;
    float* slb = slw + 64;
    float* smu = slb + 64;
    float* srs = smu + 64;

    uint32_t aH = smem_u32(sAh), aL = smem_u32(sAl);
    uint32_t xH = smem_u32(sXh), xL = smem_u32(sXl);
    uint32_t hH = smem_u32(sHh), hL = smem_u32(sHl);

    int z = blockIdx.z;
    const float* lnw = z ? ln2w : ln1w;
    const float* lnb = z ? ln2b : ln1b;
    const float* b1g = z ? b1d : b1c;
    const float* b2g = z ? b2d : b2c;
    float* outp = z ? outd_ : outc_;
    int msel = z, widx = z;

    int b = blockIdx.y, p0 = blockIdx.x*64;
    int tid = threadIdx.x, w = tid>>5, lane = tid&31;
    int wc = (w>>1)*16, wpx = (w&1)*32;

    if (tid < 128) sb1[tid] = b1g[tid];
    if (tid < 64){ sb2[tid]=b2g[tid]; slw[tid]=lnw[tid]; slb[tid]=lnb[tid]; }

    {
        const uint4* mh = (const uint4*)&g_Mh[((size_t)b*2+msel)*8704];
        const uint4* ml = (const uint4*)&g_Ml[((size_t)b*2+msel)*8704];
        uint4* dh = (uint4*)sAh; uint4* dl = (uint4*)sAl;
        for (int i=tid;i<1088;i+=256){ dh[i]=mh[i]; dl[i]=ml[i]; }
    }
    for (int i=tid;i<512;i+=256){
        int c=i>>3, q=i&7;
        size_t off = ((size_t)(b*C64+c))*HW + p0 + q*8;
        *(uint4*)&sXh[c*72 + q*8] = *(const uint4*)&g_hi[off];
        *(uint4*)&sXl[c*72 + q*8] = *(const uint4*)&g_lo[off];
    }
    // prefetch ne tile into registers (latency overlapped with GEMM1 pass A)
    uint4 neh0, neh1, nel0, nel1;
    {
        int c0p = tid>>3, q0p = tid&7;
        int i1 = tid+256, c1p = i1>>3, q1p = i1&7;
        size_t o0 = (size_t)TOT + ((size_t)(b*C64+c0p))*HW + p0 + q0p*8;
        size_t o1 = (size_t)TOT + ((size_t)(b*C64+c1p))*HW + p0 + q1p*8;
        neh0 = *(const uint4*)&g_hi[o0];
        nel0 = *(const uint4*)&g_lo[o0];
        neh1 = *(const uint4*)&g_hi[o1];
        nel1 = *(const uint4*)&g_lo[o1];
    }
    __syncthreads();

    float acc[4][4];
    #pragma unroll
    for (int g=0;g<4;g++)
        #pragma unroll
        for (int k=0;k<4;k++) acc[g][k]=0.f;
    uint32_t offA = (uint32_t)(((wc+(lane&15))*136 + ((lane>>4)&1)*8)*2);
    uint32_t offB = (uint32_t)((((lane&7)+((lane>>3)&1)*8)*72 + ((lane>>4)&1)*8)*2);

    #pragma unroll
    for (int k16=0;k16<4;k16++){
        uint32_t Ah[4],Al[4];
        ldm_x4(Ah, aH + offA + k16*32);
        ldm_x4(Al, aL + offA + k16*32);
        #pragma unroll
        for (int hf=0;hf<2;hf++){
            uint32_t Bh[4],Bl[4];
            uint32_t ob = offB + (uint32_t)(k16*16*144 + (wpx+hf*16)*2);
            ldm_t4(Bh, xH + ob); ldm_t4(Bl, xL + ob);
            MMA3(acc[hf*2],   Ah, Al, Bh[0],Bh[1], Bl[0],Bl[1]);
            MMA3(acc[hf*2+1], Ah, Al, Bh[2],Bh[3], Bl[2],Bl[3]);
        }
    }
    __syncthreads();
    // store prefetched ne tile
    {
        int c0p = tid>>3, q0p = tid&7;
        int i1 = tid+256, c1p = i1>>3, q1p = i1&7;
        *(uint4*)&sXh[c0p*72 + q0p*8] = neh0;
        *(uint4*)&sXl[c0p*72 + q0p*8] = nel0;
        *(uint4*)&sXh[c1p*72 + q1p*8] = neh1;
        *(uint4*)&sXl[c1p*72 + q1p*8] = nel1;
    }
    __syncthreads();
    #pragma unroll
    for (int k16=0;k16<4;k16++){
        uint32_t Ah[4],Al[4];
        ldm_x4(Ah, aH + offA + 128 + k16*32);
        ldm_x4(Al, aL + offA + 128 + k16*32);
        #pragma unroll
        for (int hf=0;hf<2;hf++){
            uint32_t Bh[4],Bl[4];
            uint32_t ob = offB + (uint32_t)(k16*16*144 + (wpx+hf*16)*2);
            ldm_t4(Bh, xH + ob); ldm_t4(Bl, xL + ob);
            MMA3(acc[hf*2],   Ah, Al, Bh[0],Bh[1], Bl[0],Bl[1]);
            MMA3(acc[hf*2+1], Ah, Al, Bh[2],Bh[3], Bl[2],Bl[3]);
        }
    }
    {
        int c0 = wc + (lane>>2);
        int pxb = wpx + (lane&3)*2;
        #pragma unroll
        for (int g=0; g<4; g++){
            int px = pxb + g*8;
            *(float2*)&sY[c0*68+px]     = make_float2(acc[g][0], acc[g][1]);
            *(float2*)&sY[(c0+8)*68+px] = make_float2(acc[g][2], acc[g][3]);
        }
    }
    __syncthreads();

    if (tid < 64){
        float s=0.f, ss=0.f;
        for (int c=0;c<64;c++){ float v = sY[c*68+tid]; s += v; ss += v*v; }
        float mu = s*(1.f/64.f);
        float var = ss*(1.f/64.f) - mu*mu;
        smu[tid] = mu; srs[tid] = rsqrtf(var + EPSF);
    }
    __syncthreads();
    for (int i=tid;i<2048;i+=256){
        int c = i>>5, px = (i&31)*2;
        float z0 = (sY[c*68+px  ]-smu[px  ])*srs[px  ]*slw[c] + slb[c];
        float z1 = (sY[c*68+px+1]-smu[px+1])*srs[px+1]*slw[c] + slb[c];
        uint32_t hh, ll; split2(z0, z1, hh, ll);
        *(uint32_t*)&sXh[c*72+px] = hh;
        *(uint32_t*)&sXl[c*72+px] = ll;
    }
    {
        const uint4* wh = (const uint4*)&g_W1h[widx*9216];
        const uint4* wl = (const uint4*)&g_W1l[widx*9216];
        uint4* dh = (uint4*)sAh; uint4* dl = (uint4*)sAl;
        for (int i=tid;i<1152;i+=256){ dh[i]=wh[i]; dl[i]=wl[i]; }
    }
    __syncthreads();

    {
        int wh_ = (w>>1)*32;
        float a2[2][4][4];
        #pragma unroll
        for (int m=0;m<2;m++)
            #pragma unroll
            for (int g=0;g<4;g++)
                #pragma unroll
                for (int k=0;k<4;k++) a2[m][g][k]=0.f;
        uint32_t offA2 = (uint32_t)(((wh_+(lane&15))*72 + ((lane>>4)&1)*8)*2);
        #pragma unroll
        for (int k16=0;k16<4;k16++){
            uint32_t Ah0[4],Al0[4],Ah1[4],Al1[4];
            ldm_x4(Ah0, aH + offA2 + k16*32);
            ldm_x4(Al0, aL + offA2 + k16*32);
            ldm_x4(Ah1, aH + offA2 + k16*32 + 16*144);
            ldm_x4(Al1, aL + offA2 + k16*32 + 16*144);
            #pragma unroll
            for (int hf=0;hf<2;hf++){
                uint32_t Bh[4],Bl[4];
                uint32_t ob = offB + (uint32_t)(k16*16*144 + (wpx+hf*16)*2);
                ldm_t4(Bh, xH + ob); ldm_t4(Bl, xL + ob);
                int g0=hf*2, g1=hf*2+1;
                MMA3(a2[0][g0], Ah0, Al0, Bh[0],Bh[1], Bl[0],Bl[1]);
                MMA3(a2[0][g1], Ah0, Al0, Bh[2],Bh[3], Bl[2],Bl[3]);
                MMA3(a2[1][g0], Ah1, Al1, Bh[0],Bh[1], Bl[0],Bl[1]);
                MMA3(a2[1][g1], Ah1, Al1, Bh[2],Bh[3], Bl[2],Bl[3]);
            }
        }
        int hb = wh_ + (lane>>2);
        int pxb = wpx + (lane&3)*2;
        #pragma unroll
        for (int m=0;m<2;m++){
            int r0 = hb + m*16, r1 = r0 + 8;
            float bb0 = sb1[r0], bb1 = sb1[r1];
            #pragma unroll
            for (int g=0; g<4; g++){
                int px = pxb + g*8;
                float v0 = gelu_f(a2[m][g][0] + bb0);
                float v1 = gelu_f(a2[m][g][1] + bb0);
                float v2 = gelu_f(a2[m][g][2] + bb1);
                float v3 = gelu_f(a2[m][g][3] + bb1);
                uint32_t hh, ll;
                split2(v0, v1, hh, ll);
                *(uint32_t*)&sHh[r0*72+px] = hh; *(uint32_t*)&sHl[r0*72+px] = ll;
                split2(v2, v3, hh, ll);
                *(uint32_t*)&sHh[r1*72+px] = hh; *(uint32_t*)&sHl[r1*72+px] = ll;
            }
        }
    }
    __syncthreads();
    {
        const uint4* wh = (const uint4*)&g_W2h[widx*8704];
        const uint4* wl = (const uint4*)&g_W2l[widx*8704];
        uint4* dh = (uint4*)sAh; uint4* dl = (uint4*)sAl;
        for (int i=tid;i<1088;i+=256){ dh[i]=wh[i]; dl[i]=wl[i]; }
    }
    __syncthreads();

    {
        float a3[4][4];
        #pragma unroll
        for (int g=0;g<4;g++)
            #pragma unroll
            for (int k=0;k<4;k++) a3[g][k]=0.f;
        uint32_t offA3 = (uint32_t)(((wc+(lane&15))*136 + ((lane>>4)&1)*8)*2);
        #pragma unroll
        for (int k16=0;k16<8;k16++){
            uint32_t Ah[4],Al[4];
            ldm_x4(Ah, aH + offA3 + k16*32);
            ldm_x4(Al, aL + offA3 + k16*32);
            #pragma unroll
            for (int hf=0;hf<2;hf++){
                uint32_t Bh[4],Bl[4];
                uint32_t ob = offB + (uint32_t)(k16*16*144 + (wpx+hf*16)*2);
                ldm_t4(Bh, hH + ob); ldm_t4(Bl, hL + ob);
                MMA3(a3[hf*2],   Ah, Al, Bh[0],Bh[1], Bl[0],Bl[1]);
                MMA3(a3[hf*2+1], Ah, Al, Bh[2],Bh[3], Bl[2],Bl[3]);
            }
        }
        int c0 = wc + (lane>>2);
        int pxb = wpx + (lane&3)*2;
        float bc0 = sb2[c0], bc1 = sb2[c0+8];
        #pragma unroll
        for (int g=0; g<4; g++){
            int px = pxb + g*8;
            float2 o;
            o.x = a3[g][0] + bc0 + sY[c0*68+px];
            o.y = a3[g][1] + bc0 + sY[c0*68+px+1];
            *(float2*)&outp[((size_t)(b*C64+c0))*HW + p0 + px] = o;
            o.x = a3[g][2] + bc1 + sY[(c0+8)*68+px];
            o.y = a3[g][3] + bc1 + sY[(c0+8)*68+px+1];
            *(float2*)&outp[((size_t)(b*C64+c0+8))*HW + p0 + px] = o;
        }
    }
}

// =====================================================================
extern "C" void kernel_launch(void* const* d_in, const int* in_sizes, int n_in,
                              void* d_out, int out_size)
{
    (void)in_sizes; (void)n_in; (void)out_size;
    const float* image  = (const float*)d_in[0];
    const float* event_ = (const float*)d_in[1];
    const float* Wq_c = (const float*)d_in[2];
    const float* Wk_c = (const float*)d_in[3];
    const float* Wv_c = (const float*)d_in[4];
    const float* temp_c = (const float*)d_in[5];
    const float* Wq_d = (const float*)d_in[6];
    const float* Wk_d = (const float*)d_in[7];
    const float* Wv_d = (const float*)d_in[8];
    const float* temp_d = (const float*)d_in[9];
    const float* ln_img_w = (const float*)d_in[10];
    const float* ln_img_b = (const float*)d_in[11];
    const float* ln_evt_w = (const float*)d_in[12];
    const float* ln_evt_b = (const float*)d_in[13];
    const float* ln_com_w = (const float*)d_in[14];
    const float* ln_com_b = (const float*)d_in[15];
    const float* ln_dif_w = (const float*)d_in[16];
    const float* ln_dif_b = (const float*)d_in[17];
    const float* ln1_w = (const float*)d_in[18];
    const float* ln1_b = (const float*)d_in[19];
    const float* ln2_w = (const float*)d_in[20];
    const float* ln2_b = (const float*)d_in[21];
    const float* fc1c_w = (const float*)d_in[22];
    const float* fc1c_b = (const float*)d_in[23];
    const float* fc2c_w = (const float*)d_in[24];
    const float* fc2c_b = (const float*)d_in[25];
    const float* fc1d_w = (const float*)d_in[26];
    const float* fc1d_b = (const float*)d_in[27];
    const float* fc2d_w = (const float*)d_in[28];
    const float* fc2d_b = (const float*)d_in[29];
    const float* proj1_w = (const float*)d_in[30];
    const float* proj2_w = (const float*)d_in[31];

    float* outc = (float*)d_out;
    float* outd = outc + (size_t)BATCH*C64*HW;

    const int SM3 = (4096*5 + 1024*2 + 64*3) * sizeof(float);

    cudaFuncSetAttribute(smallmath_kernel, cudaFuncAttributeMaxDynamicSharedMemorySize, SM3);
    cudaFuncSetAttribute(apply_kernel,     cudaFuncAttributeMaxDynamicSharedMemorySize, AP_SMEM_BYTES);

    ln_kernel<<<BATCH*(HW/512), 256>>>(image, event_,
        ln_img_w, ln_img_b, ln_evt_w, ln_evt_b,
        ln_com_w, ln_com_b, ln_dif_w, ln_dif_b);

    dim3 g2(GK_KSPLIT, 3, BATCH);
    gram_mma_kernel<<<g2, 256>>>();

    dim3 g3(BATCH, 2);
    smallmath_kernel<<<g3, 256, SM3>>>(Wq_c, Wk_c, Wv_c, temp_c,
                                       Wq_d, Wk_d, Wv_d, temp_d,
                                       proj1_w, proj2_w,
                                       fc1c_w, fc2c_w, fc1d_w, fc2d_w);

    dim3 g4(HW/64, BATCH, 2);
    apply_kernel<<<g4, 256, AP_SMEM_BYTES>>>(ln1_w, ln1_b, fc1c_b, fc2c_b,
                                             ln2_w, ln2_b, fc1d_b, fc2d_b,
                                             outc, outd);
}

// round 13
// speedup vs baseline: 1.3196x; 1.0111x over previous
#include <cuda_runtime.h>
#include <cuda_bf16.h>
#include <math.h>
#include <stdint.h>

#define BATCH 4
#define C64   64
#define HW    65536
#define HEADS 4
#define HID   128
#define EPSF  1e-5f

#define TOT (BATCH*C64*HW)

// ---------------- scratch (device globals; no allocs) ----------------
__device__ unsigned short g_hi[(size_t)4*TOT];
__device__ unsigned short g_lo[(size_t)4*TOT];
__device__ float g_gram256[BATCH*256*256];
__device__ unsigned short g_Mh[BATCH*2*8704];
__device__ unsigned short g_Ml[BATCH*2*8704];
__device__ unsigned short g_W1h[2*9216];
__device__ unsigned short g_W1l[2*9216];
__device__ unsigned short g_W2h[2*8704];
__device__ unsigned short g_W2l[2*8704];

// ======================= helpers ========================
__device__ __forceinline__ uint32_t smem_u32(const void* p){
    uint32_t a;
    asm("{ .reg .u64 t; cvta.to.shared.u64 t, %1; cvt.u32.u64 %0, t; }" : "=r"(a) : "l"(p));
    return a;
}
__device__ __forceinline__ void ldm_x4(uint32_t* r, uint32_t addr){
    asm volatile("ldmatrix.sync.aligned.m8n8.x4.shared.b16 {%0,%1,%2,%3}, [%4];"
        : "=r"(r[0]), "=r"(r[1]), "=r"(r[2]), "=r"(r[3]) : "r"(addr));
}
__device__ __forceinline__ void ldm_t4(uint32_t* r, uint32_t addr){
    asm volatile("ldmatrix.sync.aligned.m8n8.x4.trans.shared.b16 {%0,%1,%2,%3}, [%4];"
        : "=r"(r[0]), "=r"(r[1]), "=r"(r[2]), "=r"(r[3]) : "r"(addr));
}
__device__ __forceinline__ void mma_bf16(float& d0, float& d1, float& d2, float& d3,
        uint32_t a0, uint32_t a1, uint32_t a2, uint32_t a3,
        uint32_t b0, uint32_t b1){
    asm volatile("mma.sync.aligned.m16n8k16.row.col.f32.bf16.bf16.f32 "
        "{%0,%1,%2,%3}, {%4,%5,%6,%7}, {%8,%9}, {%0,%1,%2,%3};"
        : "+f"(d0), "+f"(d1), "+f"(d2), "+f"(d3)
        : "r"(a0), "r"(a1), "r"(a2), "r"(a3), "r"(b0), "r"(b1));
}
#define MMA3(ACC, AH, AL, BH0, BH1, BL0, BL1) do { \
    mma_bf16((ACC)[0],(ACC)[1],(ACC)[2],(ACC)[3], (AH)[0],(AH)[1],(AH)[2],(AH)[3], (BH0),(BH1)); \
    mma_bf16((ACC)[0],(ACC)[1],(ACC)[2],(ACC)[3], (AH)[0],(AH)[1],(AH)[2],(AH)[3], (BL0),(BL1)); \
    mma_bf16((ACC)[0],(ACC)[1],(ACC)[2],(ACC)[3], (AL)[0],(AL)[1],(AL)[2],(AL)[3], (BH0),(BH1)); \
} while(0)

__device__ __forceinline__ void split1(float a, unsigned short& h, unsigned short& l){
    __nv_bfloat16 hb = __float2bfloat16(a);
    float r = a - __bfloat162float(hb);
    h = __bfloat16_as_ushort(hb);
    l = __bfloat16_as_ushort(__float2bfloat16(r));
}
__device__ __forceinline__ void split2(float a, float b, uint32_t& h, uint32_t& l){
    __nv_bfloat16 ha=__float2bfloat16(a), hb=__float2bfloat16(b);
    float ra = a-__bfloat162float(ha), rb = b-__bfloat162float(hb);
    h = (uint32_t)__bfloat16_as_ushort(ha) | ((uint32_t)__bfloat16_as_ushort(hb)<<16);
    l = (uint32_t)__bfloat16_as_ushort(__float2bfloat16(ra))
      | ((uint32_t)__bfloat16_as_ushort(__float2bfloat16(rb))<<16);
}
__device__ __forceinline__ float gelu_f(float h){
    return 0.5f*h*(1.f + erff(h*0.70710678118654752f));
}

// =====================================================================
// K1: channel LayerNorm -> pre-split hi/lo planes (+ zero gram accum)
// =====================================================================
__global__ void __launch_bounds__(256) ln_kernel(
    const float* __restrict__ img, const float* __restrict__ evt,
    const float* __restrict__ wi, const float* __restrict__ bi,
    const float* __restrict__ we, const float* __restrict__ be,
    const float* __restrict__ wc, const float* __restrict__ bc,
    const float* __restrict__ wd, const float* __restrict__ bd)
{
    if (blockIdx.x < 256) {
        int base = blockIdx.x * 1024 + threadIdx.x * 4;
        g_gram256[base+0] = 0.f; g_gram256[base+1] = 0.f;
        g_gram256[base+2] = 0.f; g_gram256[base+3] = 0.f;
    }
    int b  = blockIdx.x >> 7;
    int p  = ((blockIdx.x & 127) << 9) + threadIdx.x*2;
    const float* ip = img + (size_t)b*C64*HW + p;
    const float* ep = evt + (size_t)b*C64*HW + p;

    float si0=0,si1=0,se0=0,se1=0,sii0=0,sii1=0,see0=0,see1=0,sie0=0,sie1=0;
    #pragma unroll 8
    for (int c=0;c<C64;c++){
        float2 iv = *(const float2*)&ip[(size_t)c*HW];
        float2 ev = *(const float2*)&ep[(size_t)c*HW];
        si0+=iv.x; si1+=iv.y; se0+=ev.x; se1+=ev.y;
        sii0+=iv.x*iv.x; sii1+=iv.y*iv.y;
        see0+=ev.x*ev.x; see1+=ev.y*ev.y;
        sie0+=iv.x*ev.x; sie1+=iv.y*ev.y;
    }
    const float inv64 = 1.f/64.f;
    float mi0=si0*inv64, mi1=si1*inv64, me0=se0*inv64, me1=se1*inv64;
    float mc0=(si0+se0)*inv64, mc1=(si1+se1)*inv64;
    float md0=(si0-se0)*inv64, md1=(si1-se1)*inv64;
    float ri0=rsqrtf(sii0*inv64-mi0*mi0+EPSF), ri1=rsqrtf(sii1*inv64-mi1*mi1+EPSF);
    float re0=rsqrtf(see0*inv64-me0*me0+EPSF), re1=rsqrtf(see1*inv64-me1*me1+EPSF);
    float rc0=rsqrtf((sii0+2.f*sie0+see0)*inv64-mc0*mc0+EPSF);
    float rc1=rsqrtf((sii1+2.f*sie1+see1)*inv64-mc1*mc1+EPSF);
    float rd0=rsqrtf((sii0-2.f*sie0+see0)*inv64-md0*md0+EPSF);
    float rd1=rsqrtf((sii1-2.f*sie1+see1)*inv64-md1*md1+EPSF);

    size_t ob = (size_t)b*C64*HW + p;
    #pragma unroll 4
    for (int c=0;c<C64;c++){
        float2 iv = *(const float2*)&ip[(size_t)c*HW];
        float2 ev = *(const float2*)&ep[(size_t)c*HW];
        size_t o = ob + (size_t)c*HW;
        uint32_t hh, ll;
        split2((iv.x-mi0)*ri0*wi[c]+bi[c], (iv.y-mi1)*ri1*wi[c]+bi[c], hh, ll);
        *(uint32_t*)&g_hi[o] = hh; *(uint32_t*)&g_lo[o] = ll;
        split2((ev.x-me0)*re0*we[c]+be[c], (ev.y-me1)*re1*we[c]+be[c], hh, ll);
        *(uint32_t*)&g_hi[(size_t)TOT + o] = hh; *(uint32_t*)&g_lo[(size_t)TOT + o] = ll;
        split2((iv.x+ev.x-mc0)*rc0*wc[c]+bc[c], (iv.y+ev.y-mc1)*rc1*wc[c]+bc[c], hh, ll);
        *(uint32_t*)&g_hi[(size_t)2*TOT + o] = hh; *(uint32_t*)&g_lo[(size_t)2*TOT + o] = ll;
        split2((iv.x-ev.x-md0)*rd0*wd[c]+bd[c], (iv.y-ev.y-md1)*rd1*wd[c]+bd[c], hh, ll);
        *(uint32_t*)&g_hi[(size_t)3*TOT + o] = hh; *(uint32_t*)&g_lo[(size_t)3*TOT + o] = ll;
    }
}

// =====================================================================
// K2: stacked Gram, 3 tiles, diagonal aliasing (unchanged from R12)
// =====================================================================
#define GK_KSPLIT 32
#define GK_KRANGE (HW/GK_KSPLIT)
#define GK_KC     32
#define GK_NCH    (GK_KRANGE/GK_KC)
#define SPITCH    40

__global__ void __launch_bounds__(256) gram_mma_kernel()
{
    __shared__ __align__(16) unsigned short sAhi[128*SPITCH];
    __shared__ __align__(16) unsigned short sAlo[128*SPITCH];
    __shared__ __align__(16) unsigned short sBhi[128*SPITCH];
    __shared__ __align__(16) unsigned short sBlo[128*SPITCH];

    int tid = threadIdx.x;
    int wid = tid >> 5, lane = tid & 31;
    int ks = blockIdx.x, tileid = blockIdx.y, b = blockIdx.z;
    int m0 = (tileid==0) ? 0 : 128;
    int n0 = (tileid==2) ? 128 : 0;
    bool diag = (tileid != 1);
    int warp_m = (wid >> 1) * 32;
    int warp_n = (wid & 1) * 64;

    int lr = tid >> 1;
    int lc = (tid & 1) * 16;
    size_t offA_g = (size_t)((m0+lr)>>6)*TOT + ((size_t)(b*C64)+((m0+lr)&63))*HW + (size_t)ks*GK_KRANGE + lc;
    size_t offB_g = (size_t)((n0+lr)>>6)*TOT + ((size_t)(b*C64)+((n0+lr)&63))*HW + (size_t)ks*GK_KRANGE + lc;
    const unsigned short* sAg_h = g_hi + offA_g;
    const unsigned short* sAg_l = g_lo + offA_g;
    const unsigned short* sBg_h = g_hi + offB_g;
    const unsigned short* sBg_l = g_lo + offB_g;

    uint32_t aHi = smem_u32(sAhi), aLo = smem_u32(sAlo);
    uint32_t bHi = diag ? aHi : smem_u32(sBhi);
    uint32_t bLo = diag ? aLo : smem_u32(sBlo);

    int rowA = warp_m + (lane & 15);
    int colA = (lane >> 4) * 8;
    uint32_t offA = (uint32_t)(rowA*SPITCH + colA) * 2;
    int rowB = warp_n + (lane & 7) + ((lane >> 4) & 1) * 8;
    int colB = ((lane >> 3) & 1) * 8;
    uint32_t offB = (uint32_t)(rowB*SPITCH + colB) * 2;

    float acc[2][8][4];
    #pragma unroll
    for (int i=0;i<2;i++)
        #pragma unroll
        for (int j=0;j<8;j++)
            #pragma unroll
            for (int k=0;k<4;k++) acc[i][j][k] = 0.f;

    unsigned short* dAh = sAhi + lr*SPITCH + lc;
    unsigned short* dAl = sAlo + lr*SPITCH + lc;
    unsigned short* dBh = sBhi + lr*SPITCH + lc;
    unsigned short* dBl = sBlo + lr*SPITCH + lc;

    for (int t = 0; t < GK_NCH; t++) {
        __syncthreads();
        int kc = t * GK_KC;
        *(uint4*)&dAh[0] = *(const uint4*)&sAg_h[kc];
        *(uint4*)&dAh[8] = *(const uint4*)&sAg_h[kc+8];
        *(uint4*)&dAl[0] = *(const uint4*)&sAg_l[kc];
        *(uint4*)&dAl[8] = *(const uint4*)&sAg_l[kc+8];
        if (!diag){
            *(uint4*)&dBh[0] = *(const uint4*)&sBg_h[kc];
            *(uint4*)&dBh[8] = *(const uint4*)&sBg_h[kc+8];
            *(uint4*)&dBl[0] = *(const uint4*)&sBg_l[kc];
            *(uint4*)&dBl[8] = *(const uint4*)&sBg_l[kc+8];
        }
        __syncthreads();
        #pragma unroll
        for (int k16 = 0; k16 < GK_KC; k16 += 16) {
            uint32_t kb = (uint32_t)(k16 * 2);
            uint32_t Ah0[4], Ah1[4], Al0[4], Al1[4];
            ldm_x4(Ah0, aHi + offA + kb);
            ldm_x4(Ah1, aHi + offA + kb + 16*SPITCH*2);
            ldm_x4(Al0, aLo + offA + kb);
            ldm_x4(Al1, aLo + offA + kb + 16*SPITCH*2);
            #pragma unroll
            for (int np = 0; np < 4; np++) {
                uint32_t Bh[4], Bl[4];
                uint32_t ob = offB + kb + (uint32_t)(np*16*SPITCH*2);
                ldm_x4(Bh, bHi + ob);
                ldm_x4(Bl, bLo + ob);
                int n2 = np*2;
                MMA3(acc[0][n2],   Ah0, Al0, Bh[0],Bh[1], Bl[0],Bl[1]);
                MMA3(acc[0][n2+1], Ah0, Al0, Bh[2],Bh[3], Bl[2],Bl[3]);
                MMA3(acc[1][n2],   Ah1, Al1, Bh[0],Bh[1], Bl[0],Bl[1]);
                MMA3(acc[1][n2+1], Ah1, Al1, Bh[2],Bh[3], Bl[2],Bl[3]);
            }
        }
    }

    float* G = g_gram256 + (size_t)b*65536;
    int rbase = m0 + warp_m + (lane >> 2);
    int cbase = n0 + warp_n + (lane & 3)*2;
    #pragma unroll
    for (int i=0;i<2;i++){
        #pragma unroll
        for (int ns=0;ns<8;ns++){
            int rr = rbase + i*16;
            int cc = cbase + ns*8;
            atomicAdd(&G[rr*256 + cc],       acc[i][ns][0]);
            atomicAdd(&G[rr*256 + cc + 1],   acc[i][ns][1]);
            atomicAdd(&G[(rr+8)*256 + cc],   acc[i][ns][2]);
            atomicAdd(&G[(rr+8)*256 + cc+1], acc[i][ns][3]);
        }
    }
}

// =====================================================================
// K3: per-batch, per-branch math -> pre-split M + weights. (unchanged)
// =====================================================================
__device__ __forceinline__ void ld_mat(float* s, const float* __restrict__ g, int tid){
    for (int i=tid; i<4096; i+=256) s[i] = g[i];
}
__device__ __forceinline__ void ld_matg(float* s, const float* __restrict__ g, int tid){
    for (int i=tid; i<4096; i+=256) s[i] = g[(i>>6)*256 + (i&63)];
}
__device__ __forceinline__ void mm64_nn(float* Cm, const float* A, const float* Bm, int tid){
    int ty = tid>>4, tx = tid&15;
    float acc[4][4] = {};
    for (int k=0;k<64;k++){
        float4 bv = *(const float4*)&Bm[k*64 + tx*4];
        float b4[4] = {bv.x,bv.y,bv.z,bv.w};
        #pragma unroll
        for (int ii=0;ii<4;ii++){
            float a = A[(ty*4+ii)*64 + k];
            #pragma unroll
            for (int jj=0;jj<4;jj++) acc[ii][jj] += a*b4[jj];
        }
    }
    #pragma unroll
    for (int ii=0;ii<4;ii++)
        #pragma unroll
        for (int jj=0;jj<4;jj++)
            Cm[(ty*4+ii)*64 + tx*4+jj] = acc[ii][jj];
    __syncthreads();
}
__device__ __forceinline__ void mm64_nt(float* Cm, const float* A, const float* Bm, int tid){
    int ty = tid>>4, tx = tid&15;
    float acc[4][4] = {};
    for (int k=0;k<64;k++){
        float a4[4], b4[4];
        #pragma unroll
        for (int ii=0;ii<4;ii++) a4[ii] = A[(ty*4+ii)*64 + k];
        #pragma unroll
        for (int jj=0;jj<4;jj++) b4[jj] = Bm[(tx*4+jj)*64 + k];
        #pragma unroll
        for (int ii=0;ii<4;ii++)
            #pragma unroll
            for (int jj=0;jj<4;jj++) acc[ii][jj] += a4[ii]*b4[jj];
    }
    #pragma unroll
    for (int ii=0;ii<4;ii++)
        #pragma unroll
        for (int jj=0;jj<4;jj++)
            Cm[(ty*4+ii)*64 + tx*4+jj] = acc[ii][jj];
    __syncthreads();
}
__device__ __forceinline__ void rownorm_inv(float* inv, const float* T, const float* Wm, int tid){
    if (tid < 64){
        float s = 0.f;
        for (int k=0;k<64;k++) s += T[tid*64+k]*Wm[tid*64+k];
        inv[tid] = 1.f / fmaxf(sqrtf(fmaxf(s, 0.f)), 1e-12f);
    }
    __syncthreads();
}
__device__ __forceinline__ void attn_softmax(float* out, const float* raw,
        const float* invq, const float* invk, const float* __restrict__ temp, int tid){
    if (tid < 64){
        int head = tid >> 4, base = head*16;
        float t = temp[head];
        float l[16]; float mx = -1e30f;
        #pragma unroll
        for (int s=0;s<16;s++){
            l[s] = raw[tid*64 + base + s] * invq[tid] * invk[base+s] * t;
            mx = fmaxf(mx, l[s]);
        }
        float sum = 0.f;
        #pragma unroll
        for (int s=0;s<16;s++){ l[s] = expf(l[s]-mx); sum += l[s]; }
        float r = 1.f/sum;
        #pragma unroll
        for (int s=0;s<16;s++) out[tid*16+s] = l[s]*r;
    }
    __syncthreads();
}
__device__ __forceinline__ void bdv(float* Cm, const float* at, const float* Wv, int tid){
    int ty = tid>>4, tx = tid&15;
    float acc[4][4] = {};
    for (int s=0;s<16;s++){
        #pragma unroll
        for (int ii=0;ii<4;ii++){
            int row = ty*4+ii; int head = row >> 4;
            float a = at[row*16 + s];
            float4 wv = *(const float4*)&Wv[(head*16+s)*64 + tx*4];
            acc[ii][0] += a*wv.x; acc[ii][1] += a*wv.y;
            acc[ii][2] += a*wv.z; acc[ii][3] += a*wv.w;
        }
    }
    #pragma unroll
    for (int ii=0;ii<4;ii++)
        #pragma unroll
        for (int jj=0;jj<4;jj++)
            Cm[(ty*4+ii)*64 + tx*4+jj] = acc[ii][jj];
    __syncthreads();
}
__device__ __forceinline__ void store_M_half(const float* sR, int b, int buf, int half, int tid){
    size_t base = ((size_t)b*2+buf)*8704;
    for (int i=tid;i<4096;i+=256){
        int r=i>>6, k=i&63;
        unsigned short h,l; split1(sR[i],h,l);
        g_Mh[base + r*136 + half*64 + k] = h;
        g_Ml[base + r*136 + half*64 + k] = l;
    }
    __syncthreads();
}

__global__ void __launch_bounds__(256) smallmath_kernel(
    const float* __restrict__ Wq_c, const float* __restrict__ Wk_c, const float* __restrict__ Wv_c,
    const float* __restrict__ temp_c,
    const float* __restrict__ Wq_d, const float* __restrict__ Wk_d, const float* __restrict__ Wv_d,
    const float* __restrict__ temp_d,
    const float* __restrict__ proj1, const float* __restrict__ proj2,
    const float* __restrict__ fc1c_w, const float* __restrict__ fc2c_w,
    const float* __restrict__ fc1d_w, const float* __restrict__ fc2d_w)
{
    extern __shared__ float sm[];
    float* sA   = sm;
    float* sB   = sA + 4096;
    float* sG   = sB + 4096;
    float* sT   = sG + 4096;
    float* sR   = sT + 4096;
    float* aA   = sR + 4096;
    float* aB   = aA + 1024;
    float* invq  = aB + 1024;
    float* invk1 = invq + 64;
    float* invk2 = invk1 + 64;

    int b = blockIdx.x;
    int br = blockIdx.y;
    int tid = threadIdx.x;

    if (b == 0){
        const float* W1s = br ? fc1d_w : fc1c_w;
        const float* W2s = br ? fc2d_w : fc2c_w;
        int o1 = br*9216, o2 = br*8704;
        for (int i=tid;i<8192;i+=256){
            int r=i>>6, k=i&63;
            unsigned short h,l;
            split1(W1s[i],h,l); g_W1h[o1+r*72+k]=h; g_W1l[o1+r*72+k]=l;
        }
        for (int i=tid;i<8192;i+=256){
            int r=i>>7, k=i&127;
            unsigned short h,l;
            split1(W2s[i],h,l); g_W2h[o2+r*136+k]=h; g_W2l[o2+r*136+k]=l;
        }
    }

    const float* Wq   = br ? Wq_d   : Wq_c;
    const float* Wk   = br ? Wk_d   : Wk_c;
    const float* Wv   = br ? Wv_d   : Wv_c;
    const float* temp = br ? temp_d : temp_c;
    const float* proj = br ? proj2  : proj1;
    int qr = br ? 3 : 2;

    #define GB(bi,bj) (g_gram256 + (size_t)b*65536 + (bi)*64*256 + (bj)*64)

    ld_mat(sA, Wq, tid); ld_matg(sG, GB(qr,qr), tid); __syncthreads();
    mm64_nn(sT, sA, sG, tid);
    rownorm_inv(invq, sT, sA, tid);
    ld_mat(sB, Wk, tid); ld_matg(sG, GB(0,0), tid); __syncthreads();
    mm64_nn(sT, sB, sG, tid);
    rownorm_inv(invk1, sT, sB, tid);
    ld_matg(sG, GB(1,1), tid); __syncthreads();
    mm64_nn(sT, sB, sG, tid);
    rownorm_inv(invk2, sT, sB, tid);
    ld_matg(sG, GB(qr,0), tid); __syncthreads();
    mm64_nn(sT, sA, sG, tid);
    mm64_nt(sR, sT, sB, tid);
    attn_softmax(aA, sR, invq, invk1, temp, tid);
    ld_matg(sG, GB(qr,1), tid); __syncthreads();
    mm64_nn(sT, sA, sG, tid);
    mm64_nt(sR, sT, sB, tid);
    attn_softmax(aB, sR, invq, invk2, temp, tid);

    if (br == 0){
        if (tid < 64){
            #pragma unroll
            for (int s=0;s<16;s++) aA[tid*16+s] *= aB[tid*16+s];
        }
        __syncthreads();
        ld_mat(sB, Wv, tid); __syncthreads();
        bdv(sT, aA, sB, tid);
        ld_mat(sA, proj, tid); __syncthreads();
        mm64_nn(sR, sA, sT, tid);
        store_M_half(sR, b, 0, 0, tid);
        store_M_half(sR, b, 0, 1, tid);
    } else {
        ld_mat(sB, Wv, tid); ld_mat(sA, proj, tid); __syncthreads();
        bdv(sT, aA, sB, tid);
        mm64_nn(sR, sA, sT, tid);
        store_M_half(sR, b, 1, 0, tid);
        bdv(sT, aB, sB, tid);
        mm64_nn(sR, sA, sT, tid);
        store_M_half(sR, b, 1, 1, tid);
    }
    #undef GB
}

// =====================================================================
// K4: fused apply kernel. NEW vs R12: Y kept register-resident.
// LN stats via warp butterflies + 4x64 partial buffer; Z computed from
// fragments; residual added from registers; sY deleted (smem 111.6->96KB).
// smem bytes:
//  sAh 0 (18432) sAl 18432 | sXh 36864 (9216) sXl 46080
//  sHh 55296 (18432) sHl 73728
//  psum 92160 (1024: [4][64]) psumsq 93184 (1024)
//  smu 94208 (256) srs 94464 (256) sb1 94720 (512) sb2 95232 (256)
//  slw 95488 (256) slb 95744 (256)  -> total 96000
// =====================================================================
#define AP_SMEM_BYTES 96000

__global__ void __launch_bounds__(256) apply_kernel(
    const float* __restrict__ ln1w, const float* __restrict__ ln1b,
    const float* __restrict__ b1c, const float* __restrict__ b2c,
    const float* __restrict__ ln2w, const float* __restrict__ ln2b,
    const float* __restrict__ b1d, const float* __restrict__ b2d,
    float* __restrict__ outc_, float* __restrict__ outd_)
{
    extern __shared__ char smraw[];
    unsigned short* sAh = (unsigned short*)(smraw);
    unsigned short* sAl = (unsigned short*)(smraw + 18432);
    unsigned short* sXh = (unsigned short*)(smraw + 36864);
    unsigned short* sXl = (unsigned short*)(smraw + 46080);
    unsigned short* sHh = (unsigned short*)(smraw + 55296);
    unsigned short* sHl = (unsigned short*)(smraw + 73728);
    float* psum   = (float*)(smraw + 92160);
    float* psumsq = (float*)(smraw + 93184);
    float* smu = (float*)(smraw + 94208);
    float* srs = (float*)(smraw + 94464);
    float* sb1 = (float*)(smraw + 94720);
    float* sb2 = (float*)(smraw + 95232);
    float* slw = (float*)(smraw + 95488);
    float* slb = (float*)(smraw + 95744);

    uint32_t aH = smem_u32(sAh), aL = smem_u32(sAl);
    uint32_t xH = smem_u32(sXh), xL = smem_u32(sXl);
    uint32_t hH = smem_u32(sHh), hL = smem_u32(sHl);

    int z = blockIdx.z;
    const float* lnw = z ? ln2w : ln1w;
    const float* lnb = z ? ln2b : ln1b;
    const float* b1g = z ? b1d : b1c;
    const float* b2g = z ? b2d : b2c;
    float* outp = z ? outd_ : outc_;
    int msel = z, widx = z;

    int b = blockIdx.y, p0 = blockIdx.x*64;
    int tid = threadIdx.x, w = tid>>5, lane = tid&31;
    int wc = (w>>1)*16, wpx = (w&1)*32;

    if (tid < 128) sb1[tid] = b1g[tid];
    if (tid < 64){ sb2[tid]=b2g[tid]; slw[tid]=lnw[tid]; slb[tid]=lnb[tid]; }

    {
        const uint4* mh = (const uint4*)&g_Mh[((size_t)b*2+msel)*8704];
        const uint4* ml = (const uint4*)&g_Ml[((size_t)b*2+msel)*8704];
        uint4* dh = (uint4*)sAh; uint4* dl = (uint4*)sAl;
        for (int i=tid;i<1088;i+=256){ dh[i]=mh[i]; dl[i]=ml[i]; }
    }
    for (int i=tid;i<512;i+=256){
        int c=i>>3, q=i&7;
        size_t off = ((size_t)(b*C64+c))*HW + p0 + q*8;
        *(uint4*)&sXh[c*72 + q*8] = *(const uint4*)&g_hi[off];
        *(uint4*)&sXl[c*72 + q*8] = *(const uint4*)&g_lo[off];
    }
    // prefetch ne tile into registers
    uint4 neh0, neh1, nel0, nel1;
    {
        int c0p = tid>>3, q0p = tid&7;
        int i1 = tid+256, c1p = i1>>3, q1p = i1&7;
        size_t o0 = (size_t)TOT + ((size_t)(b*C64+c0p))*HW + p0 + q0p*8;
        size_t o1 = (size_t)TOT + ((size_t)(b*C64+c1p))*HW + p0 + q1p*8;
        neh0 = *(const uint4*)&g_hi[o0];
        nel0 = *(const uint4*)&g_lo[o0];
        neh1 = *(const uint4*)&g_hi[o1];
        nel1 = *(const uint4*)&g_lo[o1];
    }
    __syncthreads();

    float accY[4][4];
    #pragma unroll
    for (int g=0;g<4;g++)
        #pragma unroll
        for (int k=0;k<4;k++) accY[g][k]=0.f;
    uint32_t offA = (uint32_t)(((wc+(lane&15))*136 + ((lane>>4)&1)*8)*2);
    uint32_t offB = (uint32_t)((((lane&7)+((lane>>3)&1)*8)*72 + ((lane>>4)&1)*8)*2);

    #pragma unroll
    for (int k16=0;k16<4;k16++){
        uint32_t Ah[4],Al[4];
        ldm_x4(Ah, aH + offA + k16*32);
        ldm_x4(Al, aL + offA + k16*32);
        #pragma unroll
        for (int hf=0;hf<2;hf++){
            uint32_t Bh[4],Bl[4];
            uint32_t ob = offB + (uint32_t)(k16*16*144 + (wpx+hf*16)*2);
            ldm_t4(Bh, xH + ob); ldm_t4(Bl, xL + ob);
            MMA3(accY[hf*2],   Ah, Al, Bh[0],Bh[1], Bl[0],Bl[1]);
            MMA3(accY[hf*2+1], Ah, Al, Bh[2],Bh[3], Bl[2],Bl[3]);
        }
    }
    __syncthreads();
    {
        int c0p = tid>>3, q0p = tid&7;
        int i1 = tid+256, c1p = i1>>3, q1p = i1&7;
        *(uint4*)&sXh[c0p*72 + q0p*8] = neh0;
        *(uint4*)&sXl[c0p*72 + q0p*8] = nel0;
        *(uint4*)&sXh[c1p*72 + q1p*8] = neh1;
        *(uint4*)&sXl[c1p*72 + q1p*8] = nel1;
    }
    __syncthreads();
    #pragma unroll
    for (int k16=0;k16<4;k16++){
        uint32_t Ah[4],Al[4];
        ldm_x4(Ah, aH + offA + 128 + k16*32);
        ldm_x4(Al, aL + offA + 128 + k16*32);
        #pragma unroll
        for (int hf=0;hf<2;hf++){
            uint32_t Bh[4],Bl[4];
            uint32_t ob = offB + (uint32_t)(k16*16*144 + (wpx+hf*16)*2);
            ldm_t4(Bh, xH + ob); ldm_t4(Bl, xL + ob);
            MMA3(accY[hf*2],   Ah, Al, Bh[0],Bh[1], Bl[0],Bl[1]);
            MMA3(accY[hf*2+1], Ah, Al, Bh[2],Bh[3], Bl[2],Bl[3]);
        }
    }

    // ---- LN stats from register fragments ----
    {
        float ps[4][2], pq[4][2];
        #pragma unroll
        for (int g=0;g<4;g++){
            ps[g][0] = accY[g][0] + accY[g][2];
            ps[g][1] = accY[g][1] + accY[g][3];
            pq[g][0] = accY[g][0]*accY[g][0] + accY[g][2]*accY[g][2];
            pq[g][1] = accY[g][1]*accY[g][1] + accY[g][3]*accY[g][3];
        }
        #pragma unroll
        for (int off=4; off<32; off<<=1){
            #pragma unroll
            for (int g=0;g<4;g++){
                ps[g][0] += __shfl_xor_sync(0xffffffffu, ps[g][0], off);
                ps[g][1] += __shfl_xor_sync(0xffffffffu, ps[g][1], off);
                pq[g][0] += __shfl_xor_sync(0xffffffffu, pq[g][0], off);
                pq[g][1] += __shfl_xor_sync(0xffffffffu, pq[g][1], off);
            }
        }
        if (lane < 4){
            #pragma unroll
            for (int g=0;g<4;g++){
                int px = wpx + lane*2 + g*8;
                psum[(w>>1)*64 + px]     = ps[g][0];
                psum[(w>>1)*64 + px+1]   = ps[g][1];
                psumsq[(w>>1)*64 + px]   = pq[g][0];
                psumsq[(w>>1)*64 + px+1] = pq[g][1];
            }
        }
    }
    __syncthreads();
    if (tid < 64){
        float s  = psum[tid] + psum[64+tid] + psum[128+tid] + psum[192+tid];
        float sq = psumsq[tid] + psumsq[64+tid] + psumsq[128+tid] + psumsq[192+tid];
        float mu = s*(1.f/64.f);
        float var = sq*(1.f/64.f) - mu*mu;
        smu[tid] = mu; srs[tid] = rsqrtf(var + EPSF);
    }
    __syncthreads();
    // ---- Z from registers -> sX (hi/lo) ; W1 staging ----
    {
        int c0 = wc + (lane>>2);
        int pxb = wpx + (lane&3)*2;
        float w0 = slw[c0], b0 = slb[c0];
        float w8 = slw[c0+8], b8 = slb[c0+8];
        #pragma unroll
        for (int g=0; g<4; g++){
            int px = pxb + g*8;
            float m0 = smu[px], m1 = smu[px+1];
            float r0 = srs[px], r1 = srs[px+1];
            uint32_t hh, ll;
            split2((accY[g][0]-m0)*r0*w0 + b0, (accY[g][1]-m1)*r1*w0 + b0, hh, ll);
            *(uint32_t*)&sXh[c0*72+px] = hh;
            *(uint32_t*)&sXl[c0*72+px] = ll;
            split2((accY[g][2]-m0)*r0*w8 + b8, (accY[g][3]-m1)*r1*w8 + b8, hh, ll);
            *(uint32_t*)&sXh[(c0+8)*72+px] = hh;
            *(uint32_t*)&sXl[(c0+8)*72+px] = ll;
        }
    }
    {
        const uint4* wh = (const uint4*)&g_W1h[widx*9216];
        const uint4* wl = (const uint4*)&g_W1l[widx*9216];
        uint4* dh = (uint4*)sAh; uint4* dl = (uint4*)sAl;
        for (int i=tid;i<1152;i+=256){ dh[i]=wh[i]; dl[i]=wl[i]; }
    }
    __syncthreads();

    // GEMM2: H = gelu(W1 @ Z + b1)
    {
        int wh_ = (w>>1)*32;
        float a2[2][4][4];
        #pragma unroll
        for (int m=0;m<2;m++)
            #pragma unroll
            for (int g=0;g<4;g++)
                #pragma unroll
                for (int k=0;k<4;k++) a2[m][g][k]=0.f;
        uint32_t offA2 = (uint32_t)(((wh_+(lane&15))*72 + ((lane>>4)&1)*8)*2);
        #pragma unroll
        for (int k16=0;k16<4;k16++){
            uint32_t Ah0[4],Al0[4],Ah1[4],Al1[4];
            ldm_x4(Ah0, aH + offA2 + k16*32);
            ldm_x4(Al0, aL + offA2 + k16*32);
            ldm_x4(Ah1, aH + offA2 + k16*32 + 16*144);
            ldm_x4(Al1, aL + offA2 + k16*32 + 16*144);
            #pragma unroll
            for (int hf=0;hf<2;hf++){
                uint32_t Bh[4],Bl[4];
                uint32_t ob = offB + (uint32_t)(k16*16*144 + (wpx+hf*16)*2);
                ldm_t4(Bh, xH + ob); ldm_t4(Bl, xL + ob);
                int g0=hf*2, g1=hf*2+1;
                MMA3(a2[0][g0], Ah0, Al0, Bh[0],Bh[1], Bl[0],Bl[1]);
                MMA3(a2[0][g1], Ah0, Al0, Bh[2],Bh[3], Bl[2],Bl[3]);
                MMA3(a2[1][g0], Ah1, Al1, Bh[0],Bh[1], Bl[0],Bl[1]);
                MMA3(a2[1][g1], Ah1, Al1, Bh[2],Bh[3], Bl[2],Bl[3]);
            }
        }
        int hb = wh_ + (lane>>2);
        int pxb = wpx + (lane&3)*2;
        #pragma unroll
        for (int m=0;m<2;m++){
            int r0 = hb + m*16, r1 = r0 + 8;
            float bb0 = sb1[r0], bb1 = sb1[r1];
            #pragma unroll
            for (int g=0; g<4; g++){
                int px = pxb + g*8;
                float v0 = gelu_f(a2[m][g][0] + bb0);
                float v1 = gelu_f(a2[m][g][1] + bb0);
                float v2 = gelu_f(a2[m][g][2] + bb1);
                float v3 = gelu_f(a2[m][g][3] + bb1);
                uint32_t hh, ll;
                split2(v0, v1, hh, ll);
                *(uint32_t*)&sHh[r0*72+px] = hh; *(uint32_t*)&sHl[r0*72+px] = ll;
                split2(v2, v3, hh, ll);
                *(uint32_t*)&sHh[r1*72+px] = hh; *(uint32_t*)&sHl[r1*72+px] = ll;
            }
        }
    }
    __syncthreads();
    {
        const uint4* wh = (const uint4*)&g_W2h[widx*8704];
        const uint4* wl = (const uint4*)&g_W2l[widx*8704];
        uint4* dh = (uint4*)sAh; uint4* dl = (uint4*)sAl;
        for (int i=tid;i<1088;i+=256){ dh[i]=wh[i]; dl[i]=wl[i]; }
    }
    __syncthreads();

    // GEMM3 + bias + residual(from regs) + store
    {
        float a3[4][4];
        #pragma unroll
        for (int g=0;g<4;g++)
            #pragma unroll
            for (int k=0;k<4;k++) a3[g][k]=0.f;
        uint32_t offA3 = (uint32_t)(((wc+(lane&15))*136 + ((lane>>4)&1)*8)*2);
        #pragma unroll
        for (int k16=0;k16<8;k16++){
            uint32_t Ah[4],Al[4];
            ldm_x4(Ah, aH + offA3 + k16*32);
            ldm_x4(Al, aL + offA3 + k16*32);
            #pragma unroll
            for (int hf=0;hf<2;hf++){
                uint32_t Bh[4],Bl[4];
                uint32_t ob = offB + (uint32_t)(k16*16*144 + (wpx+hf*16)*2);
                ldm_t4(Bh, hH + ob); ldm_t4(Bl, hL + ob);
                MMA3(a3[hf*2],   Ah, Al, Bh[0],Bh[1], Bl[0],Bl[1]);
                MMA3(a3[hf*2+1], Ah, Al, Bh[2],Bh[3], Bl[2],Bl[3]);
            }
        }
        int c0 = wc + (lane>>2);
        int pxb = wpx + (lane&3)*2;
        float bc0 = sb2[c0], bc1 = sb2[c0+8];
        #pragma unroll
        for (int g=0; g<4; g++){
            int px = pxb + g*8;
            float2 o;
            o.x = a3[g][0] + bc0 + accY[g][0];
            o.y = a3[g][1] + bc0 + accY[g][1];
            *(float2*)&outp[((size_t)(b*C64+c0))*HW + p0 + px] = o;
            o.x = a3[g][2] + bc1 + accY[g][2];
            o.y = a3[g][3] + bc1 + accY[g][3];
            *(float2*)&outp[((size_t)(b*C64+c0+8))*HW + p0 + px] = o;
        }
    }
}

// =====================================================================
extern "C" void kernel_launch(void* const* d_in, const int* in_sizes, int n_in,
                              void* d_out, int out_size)
{
    (void)in_sizes; (void)n_in; (void)out_size;
    const float* image  = (const float*)d_in[0];
    const float* event_ = (const float*)d_in[1];
    const float* Wq_c = (const float*)d_in[2];
    const float* Wk_c = (const float*)d_in[3];
    const float* Wv_c = (const float*)d_in[4];
    const float* temp_c = (const float*)d_in[5];
    const float* Wq_d = (const float*)d_in[6];
    const float* Wk_d = (const float*)d_in[7];
    const float* Wv_d = (const float*)d_in[8];
    const float* temp_d = (const float*)d_in[9];
    const float* ln_img_w = (const float*)d_in[10];
    const float* ln_img_b = (const float*)d_in[11];
    const float* ln_evt_w = (const float*)d_in[12];
    const float* ln_evt_b = (const float*)d_in[13];
    const float* ln_com_w = (const float*)d_in[14];
    const float* ln_com_b = (const float*)d_in[15];
    const float* ln_dif_w = (const float*)d_in[16];
    const float* ln_dif_b = (const float*)d_in[17];
    const float* ln1_w = (const float*)d_in[18];
    const float* ln1_b = (const float*)d_in[19];
    const float* ln2_w = (const float*)d_in[20];
    const float* ln2_b = (const float*)d_in[21];
    const float* fc1c_w = (const float*)d_in[22];
    const float* fc1c_b = (const float*)d_in[23];
    const float* fc2c_w = (const float*)d_in[24];
    const float* fc2c_b = (const float*)d_in[25];
    const float* fc1d_w = (const float*)d_in[26];
    const float* fc1d_b = (const float*)d_in[27];
    const float* fc2d_w = (const float*)d_in[28];
    const float* fc2d_b = (const float*)d_in[29];
    const float* proj1_w = (const float*)d_in[30];
    const float* proj2_w = (const float*)d_in[31];

    float* outc = (float*)d_out;
    float* outd = outc + (size_t)BATCH*C64*HW;

    const int SM3 = (4096*5 + 1024*2 + 64*3) * sizeof(float);

    cudaFuncSetAttribute(smallmath_kernel, cudaFuncAttributeMaxDynamicSharedMemorySize, SM3);
    cudaFuncSetAttribute(apply_kernel,     cudaFuncAttributeMaxDynamicSharedMemorySize, AP_SMEM_BYTES);

    ln_kernel<<<BATCH*(HW/512), 256>>>(image, event_,
        ln_img_w, ln_img_b, ln_evt_w, ln_evt_b,
        ln_com_w, ln_com_b, ln_dif_w, ln_dif_b);

    dim3 g2(GK_KSPLIT, 3, BATCH);
    gram_mma_kernel<<<g2, 256>>>();

    dim3 g3(BATCH, 2);
    smallmath_kernel<<<g3, 256, SM3>>>(Wq_c, Wk_c, Wv_c, temp_c,
                                       Wq_d, Wk_d, Wv_d, temp_d,
                                       proj1_w, proj2_w,
                                       fc1c_w, fc2c_w, fc1d_w, fc2d_w);

    dim3 g4(HW/64, BATCH, 2);
    apply_kernel<<<g4, 256, AP_SMEM_BYTES>>>(ln1_w, ln1_b, fc1c_b, fc2c_b,
                                             ln2_w, ln2_b, fc1d_b, fc2d_b,
                                             outc, outd);
}

// round 14
// speedup vs baseline: 1.6164x; 1.2249x over previous
#include <cuda_runtime.h>
#include <cuda_bf16.h>
#include <math.h>
#include <stdint.h>

#define BATCH 4
#define C64   64
#define HW    65536
#define HEADS 4
#define HID   128
#define EPSF  1e-5f

#define TOT (BATCH*C64*HW)

// ---------------- scratch (device globals; no allocs) ----------------
__device__ unsigned short g_hi[(size_t)4*TOT];
__device__ unsigned short g_lo[(size_t)4*TOT];   // planes 2,3 unused now
__device__ float g_gram256[BATCH*256*256];
__device__ unsigned short g_Mh[BATCH*2*8704];
__device__ unsigned short g_Ml[BATCH*2*8704];
__device__ unsigned short g_W1h[2*9216];
__device__ unsigned short g_W1l[2*9216];
__device__ unsigned short g_W2h[2*8704];
__device__ unsigned short g_W2l[2*8704];

// ======================= helpers ========================
__device__ __forceinline__ uint32_t smem_u32(const void* p){
    uint32_t a;
    asm("{ .reg .u64 t; cvta.to.shared.u64 t, %1; cvt.u32.u64 %0, t; }" : "=r"(a) : "l"(p));
    return a;
}
__device__ __forceinline__ void ldm_x4(uint32_t* r, uint32_t addr){
    asm volatile("ldmatrix.sync.aligned.m8n8.x4.shared.b16 {%0,%1,%2,%3}, [%4];"
        : "=r"(r[0]), "=r"(r[1]), "=r"(r[2]), "=r"(r[3]) : "r"(addr));
}
__device__ __forceinline__ void ldm_t4(uint32_t* r, uint32_t addr){
    asm volatile("ldmatrix.sync.aligned.m8n8.x4.trans.shared.b16 {%0,%1,%2,%3}, [%4];"
        : "=r"(r[0]), "=r"(r[1]), "=r"(r[2]), "=r"(r[3]) : "r"(addr));
}
__device__ __forceinline__ void mma_bf16(float& d0, float& d1, float& d2, float& d3,
        uint32_t a0, uint32_t a1, uint32_t a2, uint32_t a3,
        uint32_t b0, uint32_t b1){
    asm volatile("mma.sync.aligned.m16n8k16.row.col.f32.bf16.bf16.f32 "
        "{%0,%1,%2,%3}, {%4,%5,%6,%7}, {%8,%9}, {%0,%1,%2,%3};"
        : "+f"(d0), "+f"(d1), "+f"(d2), "+f"(d3)
        : "r"(a0), "r"(a1), "r"(a2), "r"(a3), "r"(b0), "r"(b1));
}
#define MMA3(ACC, AH, AL, BH0, BH1, BL0, BL1) do { \
    mma_bf16((ACC)[0],(ACC)[1],(ACC)[2],(ACC)[3], (AH)[0],(AH)[1],(AH)[2],(AH)[3], (BH0),(BH1)); \
    mma_bf16((ACC)[0],(ACC)[1],(ACC)[2],(ACC)[3], (AH)[0],(AH)[1],(AH)[2],(AH)[3], (BL0),(BL1)); \
    mma_bf16((ACC)[0],(ACC)[1],(ACC)[2],(ACC)[3], (AL)[0],(AL)[1],(AL)[2],(AL)[3], (BH0),(BH1)); \
} while(0)
#define MMA1(ACC, AH, BH0, BH1) \
    mma_bf16((ACC)[0],(ACC)[1],(ACC)[2],(ACC)[3], (AH)[0],(AH)[1],(AH)[2],(AH)[3], (BH0),(BH1))

__device__ __forceinline__ void split1(float a, unsigned short& h, unsigned short& l){
    __nv_bfloat16 hb = __float2bfloat16(a);
    float r = a - __bfloat162float(hb);
    h = __bfloat16_as_ushort(hb);
    l = __bfloat16_as_ushort(__float2bfloat16(r));
}
__device__ __forceinline__ void split2(float a, float b, uint32_t& h, uint32_t& l){
    __nv_bfloat16 ha=__float2bfloat16(a), hb=__float2bfloat16(b);
    float ra = a-__bfloat162float(ha), rb = b-__bfloat162float(hb);
    h = (uint32_t)__bfloat16_as_ushort(ha) | ((uint32_t)__bfloat16_as_ushort(hb)<<16);
    l = (uint32_t)__bfloat16_as_ushort(__float2bfloat16(ra))
      | ((uint32_t)__bfloat16_as_ushort(__float2bfloat16(rb))<<16);
}
__device__ __forceinline__ uint32_t pack_bf2(float a, float b){
    return (uint32_t)__bfloat16_as_ushort(__float2bfloat16(a))
         | ((uint32_t)__bfloat16_as_ushort(__float2bfloat16(b))<<16);
}
__device__ __forceinline__ float gelu_f(float h){
    return 0.5f*h*(1.f + erff(h*0.70710678118654752f));
}

// =====================================================================
// K1: channel LayerNorm -> hi planes (all 4) + lo planes (ni/ne only)
// =====================================================================
__global__ void __launch_bounds__(256) ln_kernel(
    const float* __restrict__ img, const float* __restrict__ evt,
    const float* __restrict__ wi, const float* __restrict__ bi,
    const float* __restrict__ we, const float* __restrict__ be,
    const float* __restrict__ wc, const float* __restrict__ bc,
    const float* __restrict__ wd, const float* __restrict__ bd)
{
    if (blockIdx.x < 256) {
        int base = blockIdx.x * 1024 + threadIdx.x * 4;
        g_gram256[base+0] = 0.f; g_gram256[base+1] = 0.f;
        g_gram256[base+2] = 0.f; g_gram256[base+3] = 0.f;
    }
    int b  = blockIdx.x >> 7;
    int p  = ((blockIdx.x & 127) << 9) + threadIdx.x*2;
    const float* ip = img + (size_t)b*C64*HW + p;
    const float* ep = evt + (size_t)b*C64*HW + p;

    float si0=0,si1=0,se0=0,se1=0,sii0=0,sii1=0,see0=0,see1=0,sie0=0,sie1=0;
    #pragma unroll 8
    for (int c=0;c<C64;c++){
        float2 iv = *(const float2*)&ip[(size_t)c*HW];
        float2 ev = *(const float2*)&ep[(size_t)c*HW];
        si0+=iv.x; si1+=iv.y; se0+=ev.x; se1+=ev.y;
        sii0+=iv.x*iv.x; sii1+=iv.y*iv.y;
        see0+=ev.x*ev.x; see1+=ev.y*ev.y;
        sie0+=iv.x*ev.x; sie1+=iv.y*ev.y;
    }
    const float inv64 = 1.f/64.f;
    float mi0=si0*inv64, mi1=si1*inv64, me0=se0*inv64, me1=se1*inv64;
    float mc0=(si0+se0)*inv64, mc1=(si1+se1)*inv64;
    float md0=(si0-se0)*inv64, md1=(si1-se1)*inv64;
    float ri0=rsqrtf(sii0*inv64-mi0*mi0+EPSF), ri1=rsqrtf(sii1*inv64-mi1*mi1+EPSF);
    float re0=rsqrtf(see0*inv64-me0*me0+EPSF), re1=rsqrtf(see1*inv64-me1*me1+EPSF);
    float rc0=rsqrtf((sii0+2.f*sie0+see0)*inv64-mc0*mc0+EPSF);
    float rc1=rsqrtf((sii1+2.f*sie1+see1)*inv64-mc1*mc1+EPSF);
    float rd0=rsqrtf((sii0-2.f*sie0+see0)*inv64-md0*md0+EPSF);
    float rd1=rsqrtf((sii1-2.f*sie1+see1)*inv64-md1*md1+EPSF);

    size_t ob = (size_t)b*C64*HW + p;
    #pragma unroll 4
    for (int c=0;c<C64;c++){
        float2 iv = *(const float2*)&ip[(size_t)c*HW];
        float2 ev = *(const float2*)&ep[(size_t)c*HW];
        size_t o = ob + (size_t)c*HW;
        uint32_t hh, ll;
        split2((iv.x-mi0)*ri0*wi[c]+bi[c], (iv.y-mi1)*ri1*wi[c]+bi[c], hh, ll);
        *(uint32_t*)&g_hi[o] = hh; *(uint32_t*)&g_lo[o] = ll;
        split2((ev.x-me0)*re0*we[c]+be[c], (ev.y-me1)*re1*we[c]+be[c], hh, ll);
        *(uint32_t*)&g_hi[(size_t)TOT + o] = hh; *(uint32_t*)&g_lo[(size_t)TOT + o] = ll;
        // nc / nd: hi only (gram is bf16-only now)
        *(uint32_t*)&g_hi[(size_t)2*TOT + o] =
            pack_bf2((iv.x+ev.x-mc0)*rc0*wc[c]+bc[c], (iv.y+ev.y-mc1)*rc1*wc[c]+bc[c]);
        *(uint32_t*)&g_hi[(size_t)3*TOT + o] =
            pack_bf2((iv.x-ev.x-md0)*rd0*wd[c]+bd[c], (iv.y-ev.y-md1)*rd1*wd[c]+bd[c]);
    }
}

// =====================================================================
// K2: stacked Gram, 3 tiles, diagonal aliasing, PURE bf16 (1 MMA pass,
// hi planes only). Gram's 65536-term sums average out bf16 rounding.
// =====================================================================
#define GK_KSPLIT 32
#define GK_KRANGE (HW/GK_KSPLIT)
#define GK_KC     32
#define GK_NCH    (GK_KRANGE/GK_KC)
#define SPITCH    40

__global__ void __launch_bounds__(256) gram_mma_kernel()
{
    __shared__ __align__(16) unsigned short sAhi[128*SPITCH];
    __shared__ __align__(16) unsigned short sBhi[128*SPITCH];

    int tid = threadIdx.x;
    int wid = tid >> 5, lane = tid & 31;
    int ks = blockIdx.x, tileid = blockIdx.y, b = blockIdx.z;
    int m0 = (tileid==0) ? 0 : 128;
    int n0 = (tileid==2) ? 128 : 0;
    bool diag = (tileid != 1);
    int warp_m = (wid >> 1) * 32;
    int warp_n = (wid & 1) * 64;

    int lr = tid >> 1;
    int lc = (tid & 1) * 16;
    size_t offA_g = (size_t)((m0+lr)>>6)*TOT + ((size_t)(b*C64)+((m0+lr)&63))*HW + (size_t)ks*GK_KRANGE + lc;
    size_t offB_g = (size_t)((n0+lr)>>6)*TOT + ((size_t)(b*C64)+((n0+lr)&63))*HW + (size_t)ks*GK_KRANGE + lc;
    const unsigned short* sAg_h = g_hi + offA_g;
    const unsigned short* sBg_h = g_hi + offB_g;

    uint32_t aHi = smem_u32(sAhi);
    uint32_t bHi = diag ? aHi : smem_u32(sBhi);

    int rowA = warp_m + (lane & 15);
    int colA = (lane >> 4) * 8;
    uint32_t offA = (uint32_t)(rowA*SPITCH + colA) * 2;
    int rowB = warp_n + (lane & 7) + ((lane >> 4) & 1) * 8;
    int colB = ((lane >> 3) & 1) * 8;
    uint32_t offB = (uint32_t)(rowB*SPITCH + colB) * 2;

    float acc[2][8][4];
    #pragma unroll
    for (int i=0;i<2;i++)
        #pragma unroll
        for (int j=0;j<8;j++)
            #pragma unroll
            for (int k=0;k<4;k++) acc[i][j][k] = 0.f;

    unsigned short* dAh = sAhi + lr*SPITCH + lc;
    unsigned short* dBh = sBhi + lr*SPITCH + lc;

    for (int t = 0; t < GK_NCH; t++) {
        __syncthreads();
        int kc = t * GK_KC;
        *(uint4*)&dAh[0] = *(const uint4*)&sAg_h[kc];
        *(uint4*)&dAh[8] = *(const uint4*)&sAg_h[kc+8];
        if (!diag){
            *(uint4*)&dBh[0] = *(const uint4*)&sBg_h[kc];
            *(uint4*)&dBh[8] = *(const uint4*)&sBg_h[kc+8];
        }
        __syncthreads();
        #pragma unroll
        for (int k16 = 0; k16 < GK_KC; k16 += 16) {
            uint32_t kb = (uint32_t)(k16 * 2);
            uint32_t Ah0[4], Ah1[4];
            ldm_x4(Ah0, aHi + offA + kb);
            ldm_x4(Ah1, aHi + offA + kb + 16*SPITCH*2);
            #pragma unroll
            for (int np = 0; np < 4; np++) {
                uint32_t Bh[4];
                uint32_t ob = offB + kb + (uint32_t)(np*16*SPITCH*2);
                ldm_x4(Bh, bHi + ob);
                int n2 = np*2;
                MMA1(acc[0][n2],   Ah0, Bh[0],Bh[1]);
                MMA1(acc[0][n2+1], Ah0, Bh[2],Bh[3]);
                MMA1(acc[1][n2],   Ah1, Bh[0],Bh[1]);
                MMA1(acc[1][n2+1], Ah1, Bh[2],Bh[3]);
            }
        }
    }

    float* G = g_gram256 + (size_t)b*65536;
    int rbase = m0 + warp_m + (lane >> 2);
    int cbase = n0 + warp_n + (lane & 3)*2;
    #pragma unroll
    for (int i=0;i<2;i++){
        #pragma unroll
        for (int ns=0;ns<8;ns++){
            int rr = rbase + i*16;
            int cc = cbase + ns*8;
            atomicAdd(&G[rr*256 + cc],       acc[i][ns][0]);
            atomicAdd(&G[rr*256 + cc + 1],   acc[i][ns][1]);
            atomicAdd(&G[(rr+8)*256 + cc],   acc[i][ns][2]);
            atomicAdd(&G[(rr+8)*256 + cc+1], acc[i][ns][3]);
        }
    }
}

// =====================================================================
// K3: per-batch, per-branch math -> pre-split M + weights. (unchanged)
// =====================================================================
__device__ __forceinline__ void ld_mat(float* s, const float* __restrict__ g, int tid){
    for (int i=tid; i<4096; i+=256) s[i] = g[i];
}
__device__ __forceinline__ void ld_matg(float* s, const float* __restrict__ g, int tid){
    for (int i=tid; i<4096; i+=256) s[i] = g[(i>>6)*256 + (i&63)];
}
__device__ __forceinline__ void mm64_nn(float* Cm, const float* A, const float* Bm, int tid){
    int ty = tid>>4, tx = tid&15;
    float acc[4][4] = {};
    for (int k=0;k<64;k++){
        float4 bv = *(const float4*)&Bm[k*64 + tx*4];
        float b4[4] = {bv.x,bv.y,bv.z,bv.w};
        #pragma unroll
        for (int ii=0;ii<4;ii++){
            float a = A[(ty*4+ii)*64 + k];
            #pragma unroll
            for (int jj=0;jj<4;jj++) acc[ii][jj] += a*b4[jj];
        }
    }
    #pragma unroll
    for (int ii=0;ii<4;ii++)
        #pragma unroll
        for (int jj=0;jj<4;jj++)
            Cm[(ty*4+ii)*64 + tx*4+jj] = acc[ii][jj];
    __syncthreads();
}
__device__ __forceinline__ void mm64_nt(float* Cm, const float* A, const float* Bm, int tid){
    int ty = tid>>4, tx = tid&15;
    float acc[4][4] = {};
    for (int k=0;k<64;k++){
        float a4[4], b4[4];
        #pragma unroll
        for (int ii=0;ii<4;ii++) a4[ii] = A[(ty*4+ii)*64 + k];
        #pragma unroll
        for (int jj=0;jj<4;jj++) b4[jj] = Bm[(tx*4+jj)*64 + k];
        #pragma unroll
        for (int ii=0;ii<4;ii++)
            #pragma unroll
            for (int jj=0;jj<4;jj++) acc[ii][jj] += a4[ii]*b4[jj];
    }
    #pragma unroll
    for (int ii=0;ii<4;ii++)
        #pragma unroll
        for (int jj=0;jj<4;jj++)
            Cm[(ty*4+ii)*64 + tx*4+jj] = acc[ii][jj];
    __syncthreads();
}
__device__ __forceinline__ void rownorm_inv(float* inv, const float* T, const float* Wm, int tid){
    if (tid < 64){
        float s = 0.f;
        for (int k=0;k<64;k++) s += T[tid*64+k]*Wm[tid*64+k];
        inv[tid] = 1.f / fmaxf(sqrtf(fmaxf(s, 0.f)), 1e-12f);
    }
    __syncthreads();
}
__device__ __forceinline__ void attn_softmax(float* out, const float* raw,
        const float* invq, const float* invk, const float* __restrict__ temp, int tid){
    if (tid < 64){
        int head = tid >> 4, base = head*16;
        float t = temp[head];
        float l[16]; float mx = -1e30f;
        #pragma unroll
        for (int s=0;s<16;s++){
            l[s] = raw[tid*64 + base + s] * invq[tid] * invk[base+s] * t;
            mx = fmaxf(mx, l[s]);
        }
        float sum = 0.f;
        #pragma unroll
        for (int s=0;s<16;s++){ l[s] = expf(l[s]-mx); sum += l[s]; }
        float r = 1.f/sum;
        #pragma unroll
        for (int s=0;s<16;s++) out[tid*16+s] = l[s]*r;
    }
    __syncthreads();
}
__device__ __forceinline__ void bdv(float* Cm, const float* at, const float* Wv, int tid){
    int ty = tid>>4, tx = tid&15;
    float acc[4][4] = {};
    for (int s=0;s<16;s++){
        #pragma unroll
        for (int ii=0;ii<4;ii++){
            int row = ty*4+ii; int head = row >> 4;
            float a = at[row*16 + s];
            float4 wv = *(const float4*)&Wv[(head*16+s)*64 + tx*4];
            acc[ii][0] += a*wv.x; acc[ii][1] += a*wv.y;
            acc[ii][2] += a*wv.z; acc[ii][3] += a*wv.w;
        }
    }
    #pragma unroll
    for (int ii=0;ii<4;ii++)
        #pragma unroll
        for (int jj=0;jj<4;jj++)
            Cm[(ty*4+ii)*64 + tx*4+jj] = acc[ii][jj];
    __syncthreads();
}
__device__ __forceinline__ void store_M_half(const float* sR, int b, int buf, int half, int tid){
    size_t base = ((size_t)b*2+buf)*8704;
    for (int i=tid;i<4096;i+=256){
        int r=i>>6, k=i&63;
        unsigned short h,l; split1(sR[i],h,l);
        g_Mh[base + r*136 + half*64 + k] = h;
        g_Ml[base + r*136 + half*64 + k] = l;
    }
    __syncthreads();
}

__global__ void __launch_bounds__(256) smallmath_kernel(
    const float* __restrict__ Wq_c, const float* __restrict__ Wk_c, const float* __restrict__ Wv_c,
    const float* __restrict__ temp_c,
    const float* __restrict__ Wq_d, const float* __restrict__ Wk_d, const float* __restrict__ Wv_d,
    const float* __restrict__ temp_d,
    const float* __restrict__ proj1, const float* __restrict__ proj2,
    const float* __restrict__ fc1c_w, const float* __restrict__ fc2c_w,
    const float* __restrict__ fc1d_w, const float* __restrict__ fc2d_w)
{
    extern __shared__ float sm[];
    float* sA   = sm;
    float* sB   = sA + 4096;
    float* sG   = sB + 4096;
    float* sT   = sG + 4096;
    float* sR   = sT + 4096;
    float* aA   = sR + 4096;
    float* aB   = aA + 1024;
    float* invq  = aB + 1024;
    float* invk1 = invq + 64;
    float* invk2 = invk1 + 64;

    int b = blockIdx.x;
    int br = blockIdx.y;
    int tid = threadIdx.x;

    if (b == 0){
        const float* W1s = br ? fc1d_w : fc1c_w;
        const float* W2s = br ? fc2d_w : fc2c_w;
        int o1 = br*9216, o2 = br*8704;
        for (int i=tid;i<8192;i+=256){
            int r=i>>6, k=i&63;
            unsigned short h,l;
            split1(W1s[i],h,l); g_W1h[o1+r*72+k]=h; g_W1l[o1+r*72+k]=l;
        }
        for (int i=tid;i<8192;i+=256){
            int r=i>>7, k=i&127;
            unsigned short h,l;
            split1(W2s[i],h,l); g_W2h[o2+r*136+k]=h; g_W2l[o2+r*136+k]=l;
        }
    }

    const float* Wq   = br ? Wq_d   : Wq_c;
    const float* Wk   = br ? Wk_d   : Wk_c;
    const float* Wv   = br ? Wv_d   : Wv_c;
    const float* temp = br ? temp_d : temp_c;
    const float* proj = br ? proj2  : proj1;
    int qr = br ? 3 : 2;

    #define GB(bi,bj) (g_gram256 + (size_t)b*65536 + (bi)*64*256 + (bj)*64)

    ld_mat(sA, Wq, tid); ld_matg(sG, GB(qr,qr), tid); __syncthreads();
    mm64_nn(sT, sA, sG, tid);
    rownorm_inv(invq, sT, sA, tid);
    ld_mat(sB, Wk, tid); ld_matg(sG, GB(0,0), tid); __syncthreads();
    mm64_nn(sT, sB, sG, tid);
    rownorm_inv(invk1, sT, sB, tid);
    ld_matg(sG, GB(1,1), tid); __syncthreads();
    mm64_nn(sT, sB, sG, tid);
    rownorm_inv(invk2, sT, sB, tid);
    ld_matg(sG, GB(qr,0), tid); __syncthreads();
    mm64_nn(sT, sA, sG, tid);
    mm64_nt(sR, sT, sB, tid);
    attn_softmax(aA, sR, invq, invk1, temp, tid);
    ld_matg(sG, GB(qr,1), tid); __syncthreads();
    mm64_nn(sT, sA, sG, tid);
    mm64_nt(sR, sT, sB, tid);
    attn_softmax(aB, sR, invq, invk2, temp, tid);

    if (br == 0){
        if (tid < 64){
            #pragma unroll
            for (int s=0;s<16;s++) aA[tid*16+s] *= aB[tid*16+s];
        }
        __syncthreads();
        ld_mat(sB, Wv, tid); __syncthreads();
        bdv(sT, aA, sB, tid);
        ld_mat(sA, proj, tid); __syncthreads();
        mm64_nn(sR, sA, sT, tid);
        store_M_half(sR, b, 0, 0, tid);
        store_M_half(sR, b, 0, 1, tid);
    } else {
        ld_mat(sB, Wv, tid); ld_mat(sA, proj, tid); __syncthreads();
        bdv(sT, aA, sB, tid);
        mm64_nn(sR, sA, sT, tid);
        store_M_half(sR, b, 1, 0, tid);
        bdv(sT, aB, sB, tid);
        mm64_nn(sR, sA, sT, tid);
        store_M_half(sR, b, 1, 1, tid);
    }
    #undef GB
}

// =====================================================================
// K4: fused apply kernel (unchanged from R13 — register-resident Y)
// =====================================================================
#define AP_SMEM_BYTES 96000

__global__ void __launch_bounds__(256) apply_kernel(
    const float* __restrict__ ln1w, const float* __restrict__ ln1b,
    const float* __restrict__ b1c, const float* __restrict__ b2c,
    const float* __restrict__ ln2w, const float* __restrict__ ln2b,
    const float* __restrict__ b1d, const float* __restrict__ b2d,
    float* __restrict__ outc_, float* __restrict__ outd_)
{
    extern __shared__ char smraw[];
    unsigned short* sAh = (unsigned short*)(smraw);
    unsigned short* sAl = (unsigned short*)(smraw + 18432);
    unsigned short* sXh = (unsigned short*)(smraw + 36864);
    unsigned short* sXl = (unsigned short*)(smraw + 46080);
    unsigned short* sHh = (unsigned short*)(smraw + 55296);
    unsigned short* sHl = (unsigned short*)(smraw + 73728);
    float* psum   = (float*)(smraw + 92160);
    float* psumsq = (float*)(smraw + 93184);
    float* smu = (float*)(smraw + 94208);
    float* srs = (float*)(smraw + 94464);
    float* sb1 = (float*)(smraw + 94720);
    float* sb2 = (float*)(smraw + 95232);
    float* slw = (float*)(smraw + 95488);
    float* slb = (float*)(smraw + 95744);

    uint32_t aH = smem_u32(sAh), aL = smem_u32(sAl);
    uint32_t xH = smem_u32(sXh), xL = smem_u32(sXl);
    uint32_t hH = smem_u32(sHh), hL = smem_u32(sHl);

    int z = blockIdx.z;
    const float* lnw = z ? ln2w : ln1w;
    const float* lnb = z ? ln2b : ln1b;
    const float* b1g = z ? b1d : b1c;
    const float* b2g = z ? b2d : b2c;
    float* outp = z ? outd_ : outc_;
    int msel = z, widx = z;

    int b = blockIdx.y, p0 = blockIdx.x*64;
    int tid = threadIdx.x, w = tid>>5, lane = tid&31;
    int wc = (w>>1)*16, wpx = (w&1)*32;

    if (tid < 128) sb1[tid] = b1g[tid];
    if (tid < 64){ sb2[tid]=b2g[tid]; slw[tid]=lnw[tid]; slb[tid]=lnb[tid]; }

    {
        const uint4* mh = (const uint4*)&g_Mh[((size_t)b*2+msel)*8704];
        const uint4* ml = (const uint4*)&g_Ml[((size_t)b*2+msel)*8704];
        uint4* dh = (uint4*)sAh; uint4* dl = (uint4*)sAl;
        for (int i=tid;i<1088;i+=256){ dh[i]=mh[i]; dl[i]=ml[i]; }
    }
    for (int i=tid;i<512;i+=256){
        int c=i>>3, q=i&7;
        size_t off = ((size_t)(b*C64+c))*HW + p0 + q*8;
        *(uint4*)&sXh[c*72 + q*8] = *(const uint4*)&g_hi[off];
        *(uint4*)&sXl[c*72 + q*8] = *(const uint4*)&g_lo[off];
    }
    uint4 neh0, neh1, nel0, nel1;
    {
        int c0p = tid>>3, q0p = tid&7;
        int i1 = tid+256, c1p = i1>>3, q1p = i1&7;
        size_t o0 = (size_t)TOT + ((size_t)(b*C64+c0p))*HW + p0 + q0p*8;
        size_t o1 = (size_t)TOT + ((size_t)(b*C64+c1p))*HW + p0 + q1p*8;
        neh0 = *(const uint4*)&g_hi[o0];
        nel0 = *(const uint4*)&g_lo[o0];
        neh1 = *(const uint4*)&g_hi[o1];
        nel1 = *(const uint4*)&g_lo[o1];
    }
    __syncthreads();

    float accY[4][4];
    #pragma unroll
    for (int g=0;g<4;g++)
        #pragma unroll
        for (int k=0;k<4;k++) accY[g][k]=0.f;
    uint32_t offA = (uint32_t)(((wc+(lane&15))*136 + ((lane>>4)&1)*8)*2);
    uint32_t offB = (uint32_t)((((lane&7)+((lane>>3)&1)*8)*72 + ((lane>>4)&1)*8)*2);

    #pragma unroll
    for (int k16=0;k16<4;k16++){
        uint32_t Ah[4],Al[4];
        ldm_x4(Ah, aH + offA + k16*32);
        ldm_x4(Al, aL + offA + k16*32);
        #pragma unroll
        for (int hf=0;hf<2;hf++){
            uint32_t Bh[4],Bl[4];
            uint32_t ob = offB + (uint32_t)(k16*16*144 + (wpx+hf*16)*2);
            ldm_t4(Bh, xH + ob); ldm_t4(Bl, xL + ob);
            MMA3(accY[hf*2],   Ah, Al, Bh[0],Bh[1], Bl[0],Bl[1]);
            MMA3(accY[hf*2+1], Ah, Al, Bh[2],Bh[3], Bl[2],Bl[3]);
        }
    }
    __syncthreads();
    {
        int c0p = tid>>3, q0p = tid&7;
        int i1 = tid+256, c1p = i1>>3, q1p = i1&7;
        *(uint4*)&sXh[c0p*72 + q0p*8] = neh0;
        *(uint4*)&sXl[c0p*72 + q0p*8] = nel0;
        *(uint4*)&sXh[c1p*72 + q1p*8] = neh1;
        *(uint4*)&sXl[c1p*72 + q1p*8] = nel1;
    }
    __syncthreads();
    #pragma unroll
    for (int k16=0;k16<4;k16++){
        uint32_t Ah[4],Al[4];
        ldm_x4(Ah, aH + offA + 128 + k16*32);
        ldm_x4(Al, aL + offA + 128 + k16*32);
        #pragma unroll
        for (int hf=0;hf<2;hf++){
            uint32_t Bh[4],Bl[4];
            uint32_t ob = offB + (uint32_t)(k16*16*144 + (wpx+hf*16)*2);
            ldm_t4(Bh, xH + ob); ldm_t4(Bl, xL + ob);
            MMA3(accY[hf*2],   Ah, Al, Bh[0],Bh[1], Bl[0],Bl[1]);
            MMA3(accY[hf*2+1], Ah, Al, Bh[2],Bh[3], Bl[2],Bl[3]);
        }
    }

    {
        float ps[4][2], pq[4][2];
        #pragma unroll
        for (int g=0;g<4;g++){
            ps[g][0] = accY[g][0] + accY[g][2];
            ps[g][1] = accY[g][1] + accY[g][3];
            pq[g][0] = accY[g][0]*accY[g][0] + accY[g][2]*accY[g][2];
            pq[g][1] = accY[g][1]*accY[g][1] + accY[g][3]*accY[g][3];
        }
        #pragma unroll
        for (int off=4; off<32; off<<=1){
            #pragma unroll
            for (int g=0;g<4;g++){
                ps[g][0] += __shfl_xor_sync(0xffffffffu, ps[g][0], off);
                ps[g][1] += __shfl_xor_sync(0xffffffffu, ps[g][1], off);
                pq[g][0] += __shfl_xor_sync(0xffffffffu, pq[g][0], off);
                pq[g][1] += __shfl_xor_sync(0xffffffffu, pq[g][1], off);
            }
        }
        if (lane < 4){
            #pragma unroll
            for (int g=0;g<4;g++){
                int px = wpx + lane*2 + g*8;
                psum[(w>>1)*64 + px]     = ps[g][0];
                psum[(w>>1)*64 + px+1]   = ps[g][1];
                psumsq[(w>>1)*64 + px]   = pq[g][0];
                psumsq[(w>>1)*64 + px+1] = pq[g][1];
            }
        }
    }
    __syncthreads();
    if (tid < 64){
        float s  = psum[tid] + psum[64+tid] + psum[128+tid] + psum[192+tid];
        float sq = psumsq[tid] + psumsq[64+tid] + psumsq[128+tid] + psumsq[192+tid];
        float mu = s*(1.f/64.f);
        float var = sq*(1.f/64.f) - mu*mu;
        smu[tid] = mu; srs[tid] = rsqrtf(var + EPSF);
    }
    __syncthreads();
    {
        int c0 = wc + (lane>>2);
        int pxb = wpx + (lane&3)*2;
        float w0 = slw[c0], b0 = slb[c0];
        float w8 = slw[c0+8], b8 = slb[c0+8];
        #pragma unroll
        for (int g=0; g<4; g++){
            int px = pxb + g*8;
            float m0 = smu[px], m1 = smu[px+1];
            float r0 = srs[px], r1 = srs[px+1];
            uint32_t hh, ll;
            split2((accY[g][0]-m0)*r0*w0 + b0, (accY[g][1]-m1)*r1*w0 + b0, hh, ll);
            *(uint32_t*)&sXh[c0*72+px] = hh;
            *(uint32_t*)&sXl[c0*72+px] = ll;
            split2((accY[g][2]-m0)*r0*w8 + b8, (accY[g][3]-m1)*r1*w8 + b8, hh, ll);
            *(uint32_t*)&sXh[(c0+8)*72+px] = hh;
            *(uint32_t*)&sXl[(c0+8)*72+px] = ll;
        }
    }
    {
        const uint4* wh = (const uint4*)&g_W1h[widx*9216];
        const uint4* wl = (const uint4*)&g_W1l[widx*9216];
        uint4* dh = (uint4*)sAh; uint4* dl = (uint4*)sAl;
        for (int i=tid;i<1152;i+=256){ dh[i]=wh[i]; dl[i]=wl[i]; }
    }
    __syncthreads();

    {
        int wh_ = (w>>1)*32;
        float a2[2][4][4];
        #pragma unroll
        for (int m=0;m<2;m++)
            #pragma unroll
            for (int g=0;g<4;g++)
                #pragma unroll
                for (int k=0;k<4;k++) a2[m][g][k]=0.f;
        uint32_t offA2 = (uint32_t)(((wh_+(lane&15))*72 + ((lane>>4)&1)*8)*2);
        #pragma unroll
        for (int k16=0;k16<4;k16++){
            uint32_t Ah0[4],Al0[4],Ah1[4],Al1[4];
            ldm_x4(Ah0, aH + offA2 + k16*32);
            ldm_x4(Al0, aL + offA2 + k16*32);
            ldm_x4(Ah1, aH + offA2 + k16*32 + 16*144);
            ldm_x4(Al1, aL + offA2 + k16*32 + 16*144);
            #pragma unroll
            for (int hf=0;hf<2;hf++){
                uint32_t Bh[4],Bl[4];
                uint32_t ob = offB + (uint32_t)(k16*16*144 + (wpx+hf*16)*2);
                ldm_t4(Bh, xH + ob); ldm_t4(Bl, xL + ob);
                int g0=hf*2, g1=hf*2+1;
                MMA3(a2[0][g0], Ah0, Al0, Bh[0],Bh[1], Bl[0],Bl[1]);
                MMA3(a2[0][g1], Ah0, Al0, Bh[2],Bh[3], Bl[2],Bl[3]);
                MMA3(a2[1][g0], Ah1, Al1, Bh[0],Bh[1], Bl[0],Bl[1]);
                MMA3(a2[1][g1], Ah1, Al1, Bh[2],Bh[3], Bl[2],Bl[3]);
            }
        }
        int hb = wh_ + (lane>>2);
        int pxb = wpx + (lane&3)*2;
        #pragma unroll
        for (int m=0;m<2;m++){
            int r0 = hb + m*16, r1 = r0 + 8;
            float bb0 = sb1[r0], bb1 = sb1[r1];
            #pragma unroll
            for (int g=0; g<4; g++){
                int px = pxb + g*8;
                float v0 = gelu_f(a2[m][g][0] + bb0);
                float v1 = gelu_f(a2[m][g][1] + bb0);
                float v2 = gelu_f(a2[m][g][2] + bb1);
                float v3 = gelu_f(a2[m][g][3] + bb1);
                uint32_t hh, ll;
                split2(v0, v1, hh, ll);
                *(uint32_t*)&sHh[r0*72+px] = hh; *(uint32_t*)&sHl[r0*72+px] = ll;
                split2(v2, v3, hh, ll);
                *(uint32_t*)&sHh[r1*72+px] = hh; *(uint32_t*)&sHl[r1*72+px] = ll;
            }
        }
    }
    __syncthreads();
    {
        const uint4* wh = (const uint4*)&g_W2h[widx*8704];
        const uint4* wl = (const uint4*)&g_W2l[widx*8704];
        uint4* dh = (uint4*)sAh; uint4* dl = (uint4*)sAl;
        for (int i=tid;i<1088;i+=256){ dh[i]=wh[i]; dl[i]=wl[i]; }
    }
    __syncthreads();

    {
        float a3[4][4];
        #pragma unroll
        for (int g=0;g<4;g++)
            #pragma unroll
            for (int k=0;k<4;k++) a3[g][k]=0.f;
        uint32_t offA3 = (uint32_t)(((wc+(lane&15))*136 + ((lane>>4)&1)*8)*2);
        #pragma unroll
        for (int k16=0;k16<8;k16++){
            uint32_t Ah[4],Al[4];
            ldm_x4(Ah, aH + offA3 + k16*32);
            ldm_x4(Al, aL + offA3 + k16*32);
            #pragma unroll
            for (int hf=0;hf<2;hf++){
                uint32_t Bh[4],Bl[4];
                uint32_t ob = offB + (uint32_t)(k16*16*144 + (wpx+hf*16)*2);
                ldm_t4(Bh, hH + ob); ldm_t4(Bl, hL + ob);
                MMA3(a3[hf*2],   Ah, Al, Bh[0],Bh[1], Bl[0],Bl[1]);
                MMA3(a3[hf*2+1], Ah, Al, Bh[2],Bh[3], Bl[2],Bl[3]);
            }
        }
        int c0 = wc + (lane>>2);
        int pxb = wpx + (lane&3)*2;
        float bc0 = sb2[c0], bc1 = sb2[c0+8];
        #pragma unroll
        for (int g=0; g<4; g++){
            int px = pxb + g*8;
            float2 o;
            o.x = a3[g][0] + bc0 + accY[g][0];
            o.y = a3[g][1] + bc0 + accY[g][1];
            *(float2*)&outp[((size_t)(b*C64+c0))*HW + p0 + px] = o;
            o.x = a3[g][2] + bc1 + accY[g][2];
            o.y = a3[g][3] + bc1 + accY[g][3];
            *(float2*)&outp[((size_t)(b*C64+c0+8))*HW + p0 + px] = o;
        }
    }
}

// =====================================================================
extern "C" void kernel_launch(void* const* d_in, const int* in_sizes, int n_in,
                              void* d_out, int out_size)
{
    (void)in_sizes; (void)n_in; (void)out_size;
    const float* image  = (const float*)d_in[0];
    const float* event_ = (const float*)d_in[1];
    const float* Wq_c = (const float*)d_in[2];
    const float* Wk_c = (const float*)d_in[3];
    const float* Wv_c = (const float*)d_in[4];
    const float* temp_c = (const float*)d_in[5];
    const float* Wq_d = (const float*)d_in[6];
    const float* Wk_d = (const float*)d_in[7];
    const float* Wv_d = (const float*)d_in[8];
    const float* temp_d = (const float*)d_in[9];
    const float* ln_img_w = (const float*)d_in[10];
    const float* ln_img_b = (const float*)d_in[11];
    const float* ln_evt_w = (const float*)d_in[12];
    const float* ln_evt_b = (const float*)d_in[13];
    const float* ln_com_w = (const float*)d_in[14];
    const float* ln_com_b = (const float*)d_in[15];
    const float* ln_dif_w = (const float*)d_in[16];
    const float* ln_dif_b = (const float*)d_in[17];
    const float* ln1_w = (const float*)d_in[18];
    const float* ln1_b = (const float*)d_in[19];
    const float* ln2_w = (const float*)d_in[20];
    const float* ln2_b = (const float*)d_in[21];
    const float* fc1c_w = (const float*)d_in[22];
    const float* fc1c_b = (const float*)d_in[23];
    const float* fc2c_w = (const float*)d_in[24];
    const float* fc2c_b = (const float*)d_in[25];
    const float* fc1d_w = (const float*)d_in[26];
    const float* fc1d_b = (const float*)d_in[27];
    const float* fc2d_w = (const float*)d_in[28];
    const float* fc2d_b = (const float*)d_in[29];
    const float* proj1_w = (const float*)d_in[30];
    const float* proj2_w = (const float*)d_in[31];

    float* outc = (float*)d_out;
    float* outd = outc + (size_t)BATCH*C64*HW;

    const int SM3 = (4096*5 + 1024*2 + 64*3) * sizeof(float);

    cudaFuncSetAttribute(smallmath_kernel, cudaFuncAttributeMaxDynamicSharedMemorySize, SM3);
    cudaFuncSetAttribute(apply_kernel,     cudaFuncAttributeMaxDynamicSharedMemorySize, AP_SMEM_BYTES);

    ln_kernel<<<BATCH*(HW/512), 256>>>(image, event_,
        ln_img_w, ln_img_b, ln_evt_w, ln_evt_b,
        ln_com_w, ln_com_b, ln_dif_w, ln_dif_b);

    dim3 g2(GK_KSPLIT, 3, BATCH);
    gram_mma_kernel<<<g2, 256>>>();

    dim3 g3(BATCH, 2);
    smallmath_kernel<<<g3, 256, SM3>>>(Wq_c, Wk_c, Wv_c, temp_c,
                                       Wq_d, Wk_d, Wv_d, temp_d,
                                       proj1_w, proj2_w,
                                       fc1c_w, fc2c_w, fc1d_w, fc2d_w);

    dim3 g4(HW/64, BATCH, 2);
    apply_kernel<<<g4, 256, AP_SMEM_BYTES>>>(ln1_w, ln1_b, fc1c_b, fc2c_b,
                                             ln2_w, ln2_b, fc1d_b, fc2d_b,
                                             outc, outd);
}

// round 15
// speedup vs baseline: 1.6720x; 1.0344x over previous
#include <cuda_runtime.h>
#include <cuda_bf16.h>
#include <math.h>
#include <stdint.h>

#define BATCH 4
#define C64   64
#define HW    65536
#define HEADS 4
#define HID   128
#define EPSF  1e-5f

#define TOT (BATCH*C64*HW)

// ---------------- scratch (device globals; no allocs) ----------------
__device__ unsigned short g_hi[(size_t)4*TOT];
__device__ unsigned short g_lo[(size_t)2*TOT];   // ni/ne only
__device__ float g_gram256[BATCH*256*256];
__device__ unsigned short g_Mh[BATCH*2*8704];
__device__ unsigned short g_Ml[BATCH*2*8704];
__device__ unsigned short g_W1h[2*9216];
__device__ unsigned short g_W1l[2*9216];
__device__ unsigned short g_W2h[2*8704];
__device__ unsigned short g_W2l[2*8704];

// ======================= helpers ========================
__device__ __forceinline__ uint32_t smem_u32(const void* p){
    uint32_t a;
    asm("{ .reg .u64 t; cvta.to.shared.u64 t, %1; cvt.u32.u64 %0, t; }" : "=r"(a) : "l"(p));
    return a;
}
__device__ __forceinline__ void ldm_x4(uint32_t* r, uint32_t addr){
    asm volatile("ldmatrix.sync.aligned.m8n8.x4.shared.b16 {%0,%1,%2,%3}, [%4];"
        : "=r"(r[0]), "=r"(r[1]), "=r"(r[2]), "=r"(r[3]) : "r"(addr));
}
__device__ __forceinline__ void ldm_t4(uint32_t* r, uint32_t addr){
    asm volatile("ldmatrix.sync.aligned.m8n8.x4.trans.shared.b16 {%0,%1,%2,%3}, [%4];"
        : "=r"(r[0]), "=r"(r[1]), "=r"(r[2]), "=r"(r[3]) : "r"(addr));
}
__device__ __forceinline__ void mma_bf16(float& d0, float& d1, float& d2, float& d3,
        uint32_t a0, uint32_t a1, uint32_t a2, uint32_t a3,
        uint32_t b0, uint32_t b1){
    asm volatile("mma.sync.aligned.m16n8k16.row.col.f32.bf16.bf16.f32 "
        "{%0,%1,%2,%3}, {%4,%5,%6,%7}, {%8,%9}, {%0,%1,%2,%3};"
        : "+f"(d0), "+f"(d1), "+f"(d2), "+f"(d3)
        : "r"(a0), "r"(a1), "r"(a2), "r"(a3), "r"(b0), "r"(b1));
}
#define MMA3(ACC, AH, AL, BH0, BH1, BL0, BL1) do { \
    mma_bf16((ACC)[0],(ACC)[1],(ACC)[2],(ACC)[3], (AH)[0],(AH)[1],(AH)[2],(AH)[3], (BH0),(BH1)); \
    mma_bf16((ACC)[0],(ACC)[1],(ACC)[2],(ACC)[3], (AH)[0],(AH)[1],(AH)[2],(AH)[3], (BL0),(BL1)); \
    mma_bf16((ACC)[0],(ACC)[1],(ACC)[2],(ACC)[3], (AL)[0],(AL)[1],(AL)[2],(AL)[3], (BH0),(BH1)); \
} while(0)
#define MMA1(ACC, AH, BH0, BH1) \
    mma_bf16((ACC)[0],(ACC)[1],(ACC)[2],(ACC)[3], (AH)[0],(AH)[1],(AH)[2],(AH)[3], (BH0),(BH1))

__device__ __forceinline__ void split1(float a, unsigned short& h, unsigned short& l){
    __nv_bfloat16 hb = __float2bfloat16(a);
    float r = a - __bfloat162float(hb);
    h = __bfloat16_as_ushort(hb);
    l = __bfloat16_as_ushort(__float2bfloat16(r));
}
__device__ __forceinline__ void split2(float a, float b, uint32_t& h, uint32_t& l){
    __nv_bfloat16 ha=__float2bfloat16(a), hb=__float2bfloat16(b);
    float ra = a-__bfloat162float(ha), rb = b-__bfloat162float(hb);
    h = (uint32_t)__bfloat16_as_ushort(ha) | ((uint32_t)__bfloat16_as_ushort(hb)<<16);
    l = (uint32_t)__bfloat16_as_ushort(__float2bfloat16(ra))
      | ((uint32_t)__bfloat16_as_ushort(__float2bfloat16(rb))<<16);
}
__device__ __forceinline__ uint32_t pack_bf2(float a, float b){
    return (uint32_t)__bfloat16_as_ushort(__float2bfloat16(a))
         | ((uint32_t)__bfloat16_as_ushort(__float2bfloat16(b))<<16);
}
__device__ __forceinline__ float gelu_f(float h){
    return 0.5f*h*(1.f + erff(h*0.70710678118654752f));
}

// =====================================================================
// K1: tiled LayerNorm, single gmem read.
// grid (HW/64, BATCH), block 256. Tile = 64ch x 64px staged in smem.
// =====================================================================
__global__ void __launch_bounds__(256) ln_kernel(
    const float* __restrict__ img, const float* __restrict__ evt,
    const float* __restrict__ wi, const float* __restrict__ bi,
    const float* __restrict__ we, const float* __restrict__ be,
    const float* __restrict__ wc, const float* __restrict__ bc,
    const float* __restrict__ wd, const float* __restrict__ bd)
{
    __shared__ float sI[64*68];
    __shared__ float sE[64*68];
    __shared__ float sp[4][5][64];
    __shared__ float st[8][64];   // mi ri me re mc rc md rd

    int b = blockIdx.y, p0 = blockIdx.x*64;
    int t = threadIdx.x;

    if (b == 0 && blockIdx.x < 256) {
        int base = blockIdx.x * 1024 + t * 4;
        g_gram256[base+0]=0.f; g_gram256[base+1]=0.f;
        g_gram256[base+2]=0.f; g_gram256[base+3]=0.f;
    }

    int c = t>>2, pq = (t&3)*16;
    {
        const float* ip = img + ((size_t)(b*C64+c))*HW + p0 + pq;
        const float* ep = evt + ((size_t)(b*C64+c))*HW + p0 + pq;
        #pragma unroll
        for (int j=0;j<4;j++){
            *(float4*)&sI[c*68+pq+j*4] = *(const float4*)&ip[j*4];
            *(float4*)&sE[c*68+pq+j*4] = *(const float4*)&ep[j*4];
        }
    }
    __syncthreads();
    // quarter-split partial stats: thread (q, px)
    {
        int px = t & 63, q = t >> 6;
        float si=0,se=0,sii=0,see=0,sie=0;
        #pragma unroll
        for (int cc=q*16; cc<q*16+16; cc++){
            float iv = sI[cc*68+px], ev = sE[cc*68+px];
            si+=iv; se+=ev; sii+=iv*iv; see+=ev*ev; sie+=iv*ev;
        }
        sp[q][0][px]=si; sp[q][1][px]=se; sp[q][2][px]=sii;
        sp[q][3][px]=see; sp[q][4][px]=sie;
    }
    __syncthreads();
    if (t < 64){
        float si  = sp[0][0][t]+sp[1][0][t]+sp[2][0][t]+sp[3][0][t];
        float se  = sp[0][1][t]+sp[1][1][t]+sp[2][1][t]+sp[3][1][t];
        float sii = sp[0][2][t]+sp[1][2][t]+sp[2][2][t]+sp[3][2][t];
        float see = sp[0][3][t]+sp[1][3][t]+sp[2][3][t]+sp[3][3][t];
        float sie = sp[0][4][t]+sp[1][4][t]+sp[2][4][t]+sp[3][4][t];
        const float inv64 = 1.f/64.f;
        float mi = si*inv64, me = se*inv64;
        float mc = (si+se)*inv64, md = (si-se)*inv64;
        st[0][t] = mi;
        st[1][t] = rsqrtf(sii*inv64 - mi*mi + EPSF);
        st[2][t] = me;
        st[3][t] = rsqrtf(see*inv64 - me*me + EPSF);
        st[4][t] = mc;
        st[5][t] = rsqrtf((sii+2.f*sie+see)*inv64 - mc*mc + EPSF);
        st[6][t] = md;
        st[7][t] = rsqrtf((sii-2.f*sie+see)*inv64 - md*md + EPSF);
    }
    __syncthreads();
    // outputs for this thread's 16 pixels of channel c
    {
        float Wi=wi[c], Bi=bi[c], We=we[c], Be=be[c];
        float Wc=wc[c], Bc=bc[c], Wd=wd[c], Bd=bd[c];
        uint32_t nih[8], nil_[8], neh[8], nel_[8], nch[8], ndh[8];
        #pragma unroll
        for (int j=0;j<8;j++){
            int px = pq + j*2;
            float i0 = sI[c*68+px], i1 = sI[c*68+px+1];
            float e0 = sE[c*68+px], e1 = sE[c*68+px+1];
            float mi0=st[0][px], mi1=st[0][px+1];
            float ri0=st[1][px], ri1=st[1][px+1];
            float me0=st[2][px], me1=st[2][px+1];
            float re0=st[3][px], re1=st[3][px+1];
            float mc0=st[4][px], mc1=st[4][px+1];
            float rc0=st[5][px], rc1=st[5][px+1];
            float md0=st[6][px], md1=st[6][px+1];
            float rd0=st[7][px], rd1=st[7][px+1];
            split2((i0-mi0)*ri0*Wi+Bi, (i1-mi1)*ri1*Wi+Bi, nih[j], nil_[j]);
            split2((e0-me0)*re0*We+Be, (e1-me1)*re1*We+Be, neh[j], nel_[j]);
            nch[j] = pack_bf2((i0+e0-mc0)*rc0*Wc+Bc, (i1+e1-mc1)*rc1*Wc+Bc);
            ndh[j] = pack_bf2((i0-e0-md0)*rd0*Wd+Bd, (i1-e1-md1)*rd1*Wd+Bd);
        }
        size_t o = ((size_t)(b*C64+c))*HW + p0 + pq;
        *(uint4*)&g_hi[o]   = *(uint4*)&nih[0];
        *(uint4*)&g_hi[o+8] = *(uint4*)&nih[4];
        *(uint4*)&g_lo[o]   = *(uint4*)&nil_[0];
        *(uint4*)&g_lo[o+8] = *(uint4*)&nil_[4];
        *(uint4*)&g_hi[(size_t)TOT+o]   = *(uint4*)&neh[0];
        *(uint4*)&g_hi[(size_t)TOT+o+8] = *(uint4*)&neh[4];
        *(uint4*)&g_lo[(size_t)TOT+o]   = *(uint4*)&nel_[0];
        *(uint4*)&g_lo[(size_t)TOT+o+8] = *(uint4*)&nel_[4];
        *(uint4*)&g_hi[(size_t)2*TOT+o]   = *(uint4*)&nch[0];
        *(uint4*)&g_hi[(size_t)2*TOT+o+8] = *(uint4*)&nch[4];
        *(uint4*)&g_hi[(size_t)3*TOT+o]   = *(uint4*)&ndh[0];
        *(uint4*)&g_hi[(size_t)3*TOT+o+8] = *(uint4*)&ndh[4];
    }
}

// =====================================================================
// K2: stacked Gram, 3 tiles, diagonal aliasing, pure bf16 (unchanged)
// =====================================================================
#define GK_KSPLIT 32
#define GK_KRANGE (HW/GK_KSPLIT)
#define GK_KC     32
#define GK_NCH    (GK_KRANGE/GK_KC)
#define SPITCH    40

__global__ void __launch_bounds__(256) gram_mma_kernel()
{
    __shared__ __align__(16) unsigned short sAhi[128*SPITCH];
    __shared__ __align__(16) unsigned short sBhi[128*SPITCH];

    int tid = threadIdx.x;
    int wid = tid >> 5, lane = tid & 31;
    int ks = blockIdx.x, tileid = blockIdx.y, b = blockIdx.z;
    int m0 = (tileid==0) ? 0 : 128;
    int n0 = (tileid==2) ? 128 : 0;
    bool diag = (tileid != 1);
    int warp_m = (wid >> 1) * 32;
    int warp_n = (wid & 1) * 64;

    int lr = tid >> 1;
    int lc = (tid & 1) * 16;
    size_t offA_g = (size_t)((m0+lr)>>6)*TOT + ((size_t)(b*C64)+((m0+lr)&63))*HW + (size_t)ks*GK_KRANGE + lc;
    size_t offB_g = (size_t)((n0+lr)>>6)*TOT + ((size_t)(b*C64)+((n0+lr)&63))*HW + (size_t)ks*GK_KRANGE + lc;
    const unsigned short* sAg_h = g_hi + offA_g;
    const unsigned short* sBg_h = g_hi + offB_g;

    uint32_t aHi = smem_u32(sAhi);
    uint32_t bHi = diag ? aHi : smem_u32(sBhi);

    int rowA = warp_m + (lane & 15);
    int colA = (lane >> 4) * 8;
    uint32_t offA = (uint32_t)(rowA*SPITCH + colA) * 2;
    int rowB = warp_n + (lane & 7) + ((lane >> 4) & 1) * 8;
    int colB = ((lane >> 3) & 1) * 8;
    uint32_t offB = (uint32_t)(rowB*SPITCH + colB) * 2;

    float acc[2][8][4];
    #pragma unroll
    for (int i=0;i<2;i++)
        #pragma unroll
        for (int j=0;j<8;j++)
            #pragma unroll
            for (int k=0;k<4;k++) acc[i][j][k] = 0.f;

    unsigned short* dAh = sAhi + lr*SPITCH + lc;
    unsigned short* dBh = sBhi + lr*SPITCH + lc;

    for (int t = 0; t < GK_NCH; t++) {
        __syncthreads();
        int kc = t * GK_KC;
        *(uint4*)&dAh[0] = *(const uint4*)&sAg_h[kc];
        *(uint4*)&dAh[8] = *(const uint4*)&sAg_h[kc+8];
        if (!diag){
            *(uint4*)&dBh[0] = *(const uint4*)&sBg_h[kc];
            *(uint4*)&dBh[8] = *(const uint4*)&sBg_h[kc+8];
        }
        __syncthreads();
        #pragma unroll
        for (int k16 = 0; k16 < GK_KC; k16 += 16) {
            uint32_t kb = (uint32_t)(k16 * 2);
            uint32_t Ah0[4], Ah1[4];
            ldm_x4(Ah0, aHi + offA + kb);
            ldm_x4(Ah1, aHi + offA + kb + 16*SPITCH*2);
            #pragma unroll
            for (int np = 0; np < 4; np++) {
                uint32_t Bh[4];
                uint32_t ob = offB + kb + (uint32_t)(np*16*SPITCH*2);
                ldm_x4(Bh, bHi + ob);
                int n2 = np*2;
                MMA1(acc[0][n2],   Ah0, Bh[0],Bh[1]);
                MMA1(acc[0][n2+1], Ah0, Bh[2],Bh[3]);
                MMA1(acc[1][n2],   Ah1, Bh[0],Bh[1]);
                MMA1(acc[1][n2+1], Ah1, Bh[2],Bh[3]);
            }
        }
    }

    float* G = g_gram256 + (size_t)b*65536;
    int rbase = m0 + warp_m + (lane >> 2);
    int cbase = n0 + warp_n + (lane & 3)*2;
    #pragma unroll
    for (int i=0;i<2;i++){
        #pragma unroll
        for (int ns=0;ns<8;ns++){
            int rr = rbase + i*16;
            int cc = cbase + ns*8;
            atomicAdd(&G[rr*256 + cc],       acc[i][ns][0]);
            atomicAdd(&G[rr*256 + cc + 1],   acc[i][ns][1]);
            atomicAdd(&G[(rr+8)*256 + cc],   acc[i][ns][2]);
            atomicAdd(&G[(rr+8)*256 + cc+1], acc[i][ns][3]);
        }
    }
}

// =====================================================================
// K3: per-batch, per-branch math -> pre-split M + weights. (unchanged)
// =====================================================================
__device__ __forceinline__ void ld_mat(float* s, const float* __restrict__ g, int tid){
    for (int i=tid; i<4096; i+=256) s[i] = g[i];
}
__device__ __forceinline__ void ld_matg(float* s, const float* __restrict__ g, int tid){
    for (int i=tid; i<4096; i+=256) s[i] = g[(i>>6)*256 + (i&63)];
}
__device__ __forceinline__ void mm64_nn(float* Cm, const float* A, const float* Bm, int tid){
    int ty = tid>>4, tx = tid&15;
    float acc[4][4] = {};
    for (int k=0;k<64;k++){
        float4 bv = *(const float4*)&Bm[k*64 + tx*4];
        float b4[4] = {bv.x,bv.y,bv.z,bv.w};
        #pragma unroll
        for (int ii=0;ii<4;ii++){
            float a = A[(ty*4+ii)*64 + k];
            #pragma unroll
            for (int jj=0;jj<4;jj++) acc[ii][jj] += a*b4[jj];
        }
    }
    #pragma unroll
    for (int ii=0;ii<4;ii++)
        #pragma unroll
        for (int jj=0;jj<4;jj++)
            Cm[(ty*4+ii)*64 + tx*4+jj] = acc[ii][jj];
    __syncthreads();
}
__device__ __forceinline__ void mm64_nt(float* Cm, const float* A, const float* Bm, int tid){
    int ty = tid>>4, tx = tid&15;
    float acc[4][4] = {};
    for (int k=0;k<64;k++){
        float a4[4], b4[4];
        #pragma unroll
        for (int ii=0;ii<4;ii++) a4[ii] = A[(ty*4+ii)*64 + k];
        #pragma unroll
        for (int jj=0;jj<4;jj++) b4[jj] = Bm[(tx*4+jj)*64 + k];
        #pragma unroll
        for (int ii=0;ii<4;ii++)
            #pragma unroll
            for (int jj=0;jj<4;jj++) acc[ii][jj] += a4[ii]*b4[jj];
    }
    #pragma unroll
    for (int ii=0;ii<4;ii++)
        #pragma unroll
        for (int jj=0;jj<4;jj++)
            Cm[(ty*4+ii)*64 + tx*4+jj] = acc[ii][jj];
    __syncthreads();
}
__device__ __forceinline__ void rownorm_inv(float* inv, const float* T, const float* Wm, int tid){
    if (tid < 64){
        float s = 0.f;
        for (int k=0;k<64;k++) s += T[tid*64+k]*Wm[tid*64+k];
        inv[tid] = 1.f / fmaxf(sqrtf(fmaxf(s, 0.f)), 1e-12f);
    }
    __syncthreads();
}
__device__ __forceinline__ void attn_softmax(float* out, const float* raw,
        const float* invq, const float* invk, const float* __restrict__ temp, int tid){
    if (tid < 64){
        int head = tid >> 4, base = head*16;
        float t = temp[head];
        float l[16]; float mx = -1e30f;
        #pragma unroll
        for (int s=0;s<16;s++){
            l[s] = raw[tid*64 + base + s] * invq[tid] * invk[base+s] * t;
            mx = fmaxf(mx, l[s]);
        }
        float sum = 0.f;
        #pragma unroll
        for (int s=0;s<16;s++){ l[s] = expf(l[s]-mx); sum += l[s]; }
        float r = 1.f/sum;
        #pragma unroll
        for (int s=0;s<16;s++) out[tid*16+s] = l[s]*r;
    }
    __syncthreads();
}
__device__ __forceinline__ void bdv(float* Cm, const float* at, const float* Wv, int tid){
    int ty = tid>>4, tx = tid&15;
    float acc[4][4] = {};
    for (int s=0;s<16;s++){
        #pragma unroll
        for (int ii=0;ii<4;ii++){
            int row = ty*4+ii; int head = row >> 4;
            float a = at[row*16 + s];
            float4 wv = *(const float4*)&Wv[(head*16+s)*64 + tx*4];
            acc[ii][0] += a*wv.x; acc[ii][1] += a*wv.y;
            acc[ii][2] += a*wv.z; acc[ii][3] += a*wv.w;
        }
    }
    #pragma unroll
    for (int ii=0;ii<4;ii++)
        #pragma unroll
        for (int jj=0;jj<4;jj++)
            Cm[(ty*4+ii)*64 + tx*4+jj] = acc[ii][jj];
    __syncthreads();
}
__device__ __forceinline__ void store_M_half(const float* sR, int b, int buf, int half, int tid){
    size_t base = ((size_t)b*2+buf)*8704;
    for (int i=tid;i<4096;i+=256){
        int r=i>>6, k=i&63;
        unsigned short h,l; split1(sR[i],h,l);
        g_Mh[base + r*136 + half*64 + k] = h;
        g_Ml[base + r*136 + half*64 + k] = l;
    }
    __syncthreads();
}

__global__ void __launch_bounds__(256) smallmath_kernel(
    const float* __restrict__ Wq_c, const float* __restrict__ Wk_c, const float* __restrict__ Wv_c,
    const float* __restrict__ temp_c,
    const float* __restrict__ Wq_d, const float* __restrict__ Wk_d, const float* __restrict__ Wv_d,
    const float* __restrict__ temp_d,
    const float* __restrict__ proj1, const float* __restrict__ proj2,
    const float* __restrict__ fc1c_w, const float* __restrict__ fc2c_w,
    const float* __restrict__ fc1d_w, const float* __restrict__ fc2d_w)
{
    extern __shared__ float sm[];
    float* sA   = sm;
    float* sB   = sA + 4096;
    float* sG   = sB + 4096;
    float* sT   = sG + 4096;
    float* sR   = sT + 4096;
    float* aA   = sR + 4096;
    float* aB   = aA + 1024;
    float* invq  = aB + 1024;
    float* invk1 = invq + 64;
    float* invk2 = invk1 + 64;

    int b = blockIdx.x;
    int br = blockIdx.y;
    int tid = threadIdx.x;

    if (b == 0){
        const float* W1s = br ? fc1d_w : fc1c_w;
        const float* W2s = br ? fc2d_w : fc2c_w;
        int o1 = br*9216, o2 = br*8704;
        for (int i=tid;i<8192;i+=256){
            int r=i>>6, k=i&63;
            unsigned short h,l;
            split1(W1s[i],h,l); g_W1h[o1+r*72+k]=h; g_W1l[o1+r*72+k]=l;
        }
        for (int i=tid;i<8192;i+=256){
            int r=i>>7, k=i&127;
            unsigned short h,l;
            split1(W2s[i],h,l); g_W2h[o2+r*136+k]=h; g_W2l[o2+r*136+k]=l;
        }
    }

    const float* Wq   = br ? Wq_d   : Wq_c;
    const float* Wk   = br ? Wk_d   : Wk_c;
    const float* Wv   = br ? Wv_d   : Wv_c;
    const float* temp = br ? temp_d : temp_c;
    const float* proj = br ? proj2  : proj1;
    int qr = br ? 3 : 2;

    #define GB(bi,bj) (g_gram256 + (size_t)b*65536 + (bi)*64*256 + (bj)*64)

    ld_mat(sA, Wq, tid); ld_matg(sG, GB(qr,qr), tid); __syncthreads();
    mm64_nn(sT, sA, sG, tid);
    rownorm_inv(invq, sT, sA, tid);
    ld_mat(sB, Wk, tid); ld_matg(sG, GB(0,0), tid); __syncthreads();
    mm64_nn(sT, sB, sG, tid);
    rownorm_inv(invk1, sT, sB, tid);
    ld_matg(sG, GB(1,1), tid); __syncthreads();
    mm64_nn(sT, sB, sG, tid);
    rownorm_inv(invk2, sT, sB, tid);
    ld_matg(sG, GB(qr,0), tid); __syncthreads();
    mm64_nn(sT, sA, sG, tid);
    mm64_nt(sR, sT, sB, tid);
    attn_softmax(aA, sR, invq, invk1, temp, tid);
    ld_matg(sG, GB(qr,1), tid); __syncthreads();
    mm64_nn(sT, sA, sG, tid);
    mm64_nt(sR, sT, sB, tid);
    attn_softmax(aB, sR, invq, invk2, temp, tid);

    if (br == 0){
        if (tid < 64){
            #pragma unroll
            for (int s=0;s<16;s++) aA[tid*16+s] *= aB[tid*16+s];
        }
        __syncthreads();
        ld_mat(sB, Wv, tid); __syncthreads();
        bdv(sT, aA, sB, tid);
        ld_mat(sA, proj, tid); __syncthreads();
        mm64_nn(sR, sA, sT, tid);
        store_M_half(sR, b, 0, 0, tid);
        store_M_half(sR, b, 0, 1, tid);
    } else {
        ld_mat(sB, Wv, tid); ld_mat(sA, proj, tid); __syncthreads();
        bdv(sT, aA, sB, tid);
        mm64_nn(sR, sA, sT, tid);
        store_M_half(sR, b, 1, 0, tid);
        bdv(sT, aB, sB, tid);
        mm64_nn(sR, sA, sT, tid);
        store_M_half(sR, b, 1, 1, tid);
    }
    #undef GB
}

// =====================================================================
// K4: fused apply kernel (unchanged from R14 — register-resident Y)
// =====================================================================
#define AP_SMEM_BYTES 96000

__global__ void __launch_bounds__(256) apply_kernel(
    const float* __restrict__ ln1w, const float* __restrict__ ln1b,
    const float* __restrict__ b1c, const float* __restrict__ b2c,
    const float* __restrict__ ln2w, const float* __restrict__ ln2b,
    const float* __restrict__ b1d, const float* __restrict__ b2d,
    float* __restrict__ outc_, float* __restrict__ outd_)
{
    extern __shared__ char smraw[];
    unsigned short* sAh = (unsigned short*)(smraw);
    unsigned short* sAl = (unsigned short*)(smraw + 18432);
    unsigned short* sXh = (unsigned short*)(smraw + 36864);
    unsigned short* sXl = (unsigned short*)(smraw + 46080);
    unsigned short* sHh = (unsigned short*)(smraw + 55296);
    unsigned short* sHl = (unsigned short*)(smraw + 73728);
    float* psum   = (float*)(smraw + 92160);
    float* psumsq = (float*)(smraw + 93184);
    float* smu = (float*)(smraw + 94208);
    float* srs = (float*)(smraw + 94464);
    float* sb1 = (float*)(smraw + 94720);
    float* sb2 = (float*)(smraw + 95232);
    float* slw = (float*)(smraw + 95488);
    float* slb = (float*)(smraw + 95744);

    uint32_t aH = smem_u32(sAh), aL = smem_u32(sAl);
    uint32_t xH = smem_u32(sXh), xL = smem_u32(sXl);
    uint32_t hH = smem_u32(sHh), hL = smem_u32(sHl);

    int z = blockIdx.z;
    const float* lnw = z ? ln2w : ln1w;
    const float* lnb = z ? ln2b : ln1b;
    const float* b1g = z ? b1d : b1c;
    const float* b2g = z ? b2d : b2c;
    float* outp = z ? outd_ : outc_;
    int msel = z, widx = z;

    int b = blockIdx.y, p0 = blockIdx.x*64;
    int tid = threadIdx.x, w = tid>>5, lane = tid&31;
    int wc = (w>>1)*16, wpx = (w&1)*32;

    if (tid < 128) sb1[tid] = b1g[tid];
    if (tid < 64){ sb2[tid]=b2g[tid]; slw[tid]=lnw[tid]; slb[tid]=lnb[tid]; }

    {
        const uint4* mh = (const uint4*)&g_Mh[((size_t)b*2+msel)*8704];
        const uint4* ml = (const uint4*)&g_Ml[((size_t)b*2+msel)*8704];
        uint4* dh = (uint4*)sAh; uint4* dl = (uint4*)sAl;
        for (int i=tid;i<1088;i+=256){ dh[i]=mh[i]; dl[i]=ml[i]; }
    }
    for (int i=tid;i<512;i+=256){
        int c=i>>3, q=i&7;
        size_t off = ((size_t)(b*C64+c))*HW + p0 + q*8;
        *(uint4*)&sXh[c*72 + q*8] = *(const uint4*)&g_hi[off];
        *(uint4*)&sXl[c*72 + q*8] = *(const uint4*)&g_lo[off];
    }
    uint4 neh0, neh1, nel0, nel1;
    {
        int c0p = tid>>3, q0p = tid&7;
        int i1 = tid+256, c1p = i1>>3, q1p = i1&7;
        size_t o0 = (size_t)TOT + ((size_t)(b*C64+c0p))*HW + p0 + q0p*8;
        size_t o1 = (size_t)TOT + ((size_t)(b*C64+c1p))*HW + p0 + q1p*8;
        neh0 = *(const uint4*)&g_hi[o0];
        nel0 = *(const uint4*)&g_lo[o0];
        neh1 = *(const uint4*)&g_hi[o1];
        nel1 = *(const uint4*)&g_lo[o1];
    }
    __syncthreads();

    float accY[4][4];
    #pragma unroll
    for (int g=0;g<4;g++)
        #pragma unroll
        for (int k=0;k<4;k++) accY[g][k]=0.f;
    uint32_t offA = (uint32_t)(((wc+(lane&15))*136 + ((lane>>4)&1)*8)*2);
    uint32_t offB = (uint32_t)((((lane&7)+((lane>>3)&1)*8)*72 + ((lane>>4)&1)*8)*2);

    #pragma unroll
    for (int k16=0;k16<4;k16++){
        uint32_t Ah[4],Al[4];
        ldm_x4(Ah, aH + offA + k16*32);
        ldm_x4(Al, aL + offA + k16*32);
        #pragma unroll
        for (int hf=0;hf<2;hf++){
            uint32_t Bh[4],Bl[4];
            uint32_t ob = offB + (uint32_t)(k16*16*144 + (wpx+hf*16)*2);
            ldm_t4(Bh, xH + ob); ldm_t4(Bl, xL + ob);
            MMA3(accY[hf*2],   Ah, Al, Bh[0],Bh[1], Bl[0],Bl[1]);
            MMA3(accY[hf*2+1], Ah, Al, Bh[2],Bh[3], Bl[2],Bl[3]);
        }
    }
    __syncthreads();
    {
        int c0p = tid>>3, q0p = tid&7;
        int i1 = tid+256, c1p = i1>>3, q1p = i1&7;
        *(uint4*)&sXh[c0p*72 + q0p*8] = neh0;
        *(uint4*)&sXl[c0p*72 + q0p*8] = nel0;
        *(uint4*)&sXh[c1p*72 + q1p*8] = neh1;
        *(uint4*)&sXl[c1p*72 + q1p*8] = nel1;
    }
    __syncthreads();
    #pragma unroll
    for (int k16=0;k16<4;k16++){
        uint32_t Ah[4],Al[4];
        ldm_x4(Ah, aH + offA + 128 + k16*32);
        ldm_x4(Al, aL + offA + 128 + k16*32);
        #pragma unroll
        for (int hf=0;hf<2;hf++){
            uint32_t Bh[4],Bl[4];
            uint32_t ob = offB + (uint32_t)(k16*16*144 + (wpx+hf*16)*2);
            ldm_t4(Bh, xH + ob); ldm_t4(Bl, xL + ob);
            MMA3(accY[hf*2],   Ah, Al, Bh[0],Bh[1], Bl[0],Bl[1]);
            MMA3(accY[hf*2+1], Ah, Al, Bh[2],Bh[3], Bl[2],Bl[3]);
        }
    }

    {
        float ps[4][2], pq[4][2];
        #pragma unroll
        for (int g=0;g<4;g++){
            ps[g][0] = accY[g][0] + accY[g][2];
            ps[g][1] = accY[g][1] + accY[g][3];
            pq[g][0] = accY[g][0]*accY[g][0] + accY[g][2]*accY[g][2];
            pq[g][1] = accY[g][1]*accY[g][1] + accY[g][3]*accY[g][3];
        }
        #pragma unroll
        for (int off=4; off<32; off<<=1){
            #pragma unroll
            for (int g=0;g<4;g++){
                ps[g][0] += __shfl_xor_sync(0xffffffffu, ps[g][0], off);
                ps[g][1] += __shfl_xor_sync(0xffffffffu, ps[g][1], off);
                pq[g][0] += __shfl_xor_sync(0xffffffffu, pq[g][0], off);
                pq[g][1] += __shfl_xor_sync(0xffffffffu, pq[g][1], off);
            }
        }
        if (lane < 4){
            #pragma unroll
            for (int g=0;g<4;g++){
                int px = wpx + lane*2 + g*8;
                psum[(w>>1)*64 + px]     = ps[g][0];
                psum[(w>>1)*64 + px+1]   = ps[g][1];
                psumsq[(w>>1)*64 + px]   = pq[g][0];
                psumsq[(w>>1)*64 + px+1] = pq[g][1];
            }
        }
    }
    __syncthreads();
    if (tid < 64){
        float s  = psum[tid] + psum[64+tid] + psum[128+tid] + psum[192+tid];
        float sq = psumsq[tid] + psumsq[64+tid] + psumsq[128+tid] + psumsq[192+tid];
        float mu = s*(1.f/64.f);
        float var = sq*(1.f/64.f) - mu*mu;
        smu[tid] = mu; srs[tid] = rsqrtf(var + EPSF);
    }
    __syncthreads();
    {
        int c0 = wc + (lane>>2);
        int pxb = wpx + (lane&3)*2;
        float w0 = slw[c0], b0 = slb[c0];
        float w8 = slw[c0+8], b8 = slb[c0+8];
        #pragma unroll
        for (int g=0; g<4; g++){
            int px = pxb + g*8;
            float m0 = smu[px], m1 = smu[px+1];
            float r0 = srs[px], r1 = srs[px+1];
            uint32_t hh, ll;
            split2((accY[g][0]-m0)*r0*w0 + b0, (accY[g][1]-m1)*r1*w0 + b0, hh, ll);
            *(uint32_t*)&sXh[c0*72+px] = hh;
            *(uint32_t*)&sXl[c0*72+px] = ll;
            split2((accY[g][2]-m0)*r0*w8 + b8, (accY[g][3]-m1)*r1*w8 + b8, hh, ll);
            *(uint32_t*)&sXh[(c0+8)*72+px] = hh;
            *(uint32_t*)&sXl[(c0+8)*72+px] = ll;
        }
    }
    {
        const uint4* wh = (const uint4*)&g_W1h[widx*9216];
        const uint4* wl = (const uint4*)&g_W1l[widx*9216];
        uint4* dh = (uint4*)sAh; uint4* dl = (uint4*)sAl;
        for (int i=tid;i<1152;i+=256){ dh[i]=wh[i]; dl[i]=wl[i]; }
    }
    __syncthreads();

    {
        int wh_ = (w>>1)*32;
        float a2[2][4][4];
        #pragma unroll
        for (int m=0;m<2;m++)
            #pragma unroll
            for (int g=0;g<4;g++)
                #pragma unroll
                for (int k=0;k<4;k++) a2[m][g][k]=0.f;
        uint32_t offA2 = (uint32_t)(((wh_+(lane&15))*72 + ((lane>>4)&1)*8)*2);
        #pragma unroll
        for (int k16=0;k16<4;k16++){
            uint32_t Ah0[4],Al0[4],Ah1[4],Al1[4];
            ldm_x4(Ah0, aH + offA2 + k16*32);
            ldm_x4(Al0, aL + offA2 + k16*32);
            ldm_x4(Ah1, aH + offA2 + k16*32 + 16*144);
            ldm_x4(Al1, aL + offA2 + k16*32 + 16*144);
            #pragma unroll
            for (int hf=0;hf<2;hf++){
                uint32_t Bh[4],Bl[4];
                uint32_t ob = offB + (uint32_t)(k16*16*144 + (wpx+hf*16)*2);
                ldm_t4(Bh, xH + ob); ldm_t4(Bl, xL + ob);
                int g0=hf*2, g1=hf*2+1;
                MMA3(a2[0][g0], Ah0, Al0, Bh[0],Bh[1], Bl[0],Bl[1]);
                MMA3(a2[0][g1], Ah0, Al0, Bh[2],Bh[3], Bl[2],Bl[3]);
                MMA3(a2[1][g0], Ah1, Al1, Bh[0],Bh[1], Bl[0],Bl[1]);
                MMA3(a2[1][g1], Ah1, Al1, Bh[2],Bh[3], Bl[2],Bl[3]);
            }
        }
        int hb = wh_ + (lane>>2);
        int pxb = wpx + (lane&3)*2;
        #pragma unroll
        for (int m=0;m<2;m++){
            int r0 = hb + m*16, r1 = r0 + 8;
            float bb0 = sb1[r0], bb1 = sb1[r1];
            #pragma unroll
            for (int g=0; g<4; g++){
                int px = pxb + g*8;
                float v0 = gelu_f(a2[m][g][0] + bb0);
                float v1 = gelu_f(a2[m][g][1] + bb0);
                float v2 = gelu_f(a2[m][g][2] + bb1);
                float v3 = gelu_f(a2[m][g][3] + bb1);
                uint32_t hh, ll;
                split2(v0, v1, hh, ll);
                *(uint32_t*)&sHh[r0*72+px] = hh; *(uint32_t*)&sHl[r0*72+px] = ll;
                split2(v2, v3, hh, ll);
                *(uint32_t*)&sHh[r1*72+px] = hh; *(uint32_t*)&sHl[r1*72+px] = ll;
            }
        }
    }
    __syncthreads();
    {
        const uint4* wh = (const uint4*)&g_W2h[widx*8704];
        const uint4* wl = (const uint4*)&g_W2l[widx*8704];
        uint4* dh = (uint4*)sAh; uint4* dl = (uint4*)sAl;
        for (int i=tid;i<1088;i+=256){ dh[i]=wh[i]; dl[i]=wl[i]; }
    }
    __syncthreads();

    {
        float a3[4][4];
        #pragma unroll
        for (int g=0;g<4;g++)
            #pragma unroll
            for (int k=0;k<4;k++) a3[g][k]=0.f;
        uint32_t offA3 = (uint32_t)(((wc+(lane&15))*136 + ((lane>>4)&1)*8)*2);
        #pragma unroll
        for (int k16=0;k16<8;k16++){
            uint32_t Ah[4],Al[4];
            ldm_x4(Ah, aH + offA3 + k16*32);
            ldm_x4(Al, aL + offA3 + k16*32);
            #pragma unroll
            for (int hf=0;hf<2;hf++){
                uint32_t Bh[4],Bl[4];
                uint32_t ob = offB + (uint32_t)(k16*16*144 + (wpx+hf*16)*2);
                ldm_t4(Bh, hH + ob); ldm_t4(Bl, hL + ob);
                MMA3(a3[hf*2],   Ah, Al, Bh[0],Bh[1], Bl[0],Bl[1]);
                MMA3(a3[hf*2+1], Ah, Al, Bh[2],Bh[3], Bl[2],Bl[3]);
            }
        }
        int c0 = wc + (lane>>2);
        int pxb = wpx + (lane&3)*2;
        float bc0 = sb2[c0], bc1 = sb2[c0+8];
        #pragma unroll
        for (int g=0; g<4; g++){
            int px = pxb + g*8;
            float2 o;
            o.x = a3[g][0] + bc0 + accY[g][0];
            o.y = a3[g][1] + bc0 + accY[g][1];
            *(float2*)&outp[((size_t)(b*C64+c0))*HW + p0 + px] = o;
            o.x = a3[g][2] + bc1 + accY[g][2];
            o.y = a3[g][3] + bc1 + accY[g][3];
            *(float2*)&outp[((size_t)(b*C64+c0+8))*HW + p0 + px] = o;
        }
    }
}

// =====================================================================
extern "C" void kernel_launch(void* const* d_in, const int* in_sizes, int n_in,
                              void* d_out, int out_size)
{
    (void)in_sizes; (void)n_in; (void)out_size;
    const float* image  = (const float*)d_in[0];
    const float* event_ = (const float*)d_in[1];
    const float* Wq_c = (const float*)d_in[2];
    const float* Wk_c = (const float*)d_in[3];
    const float* Wv_c = (const float*)d_in[4];
    const float* temp_c = (const float*)d_in[5];
    const float* Wq_d = (const float*)d_in[6];
    const float* Wk_d = (const float*)d_in[7];
    const float* Wv_d = (const float*)d_in[8];
    const float* temp_d = (const float*)d_in[9];
    const float* ln_img_w = (const float*)d_in[10];
    const float* ln_img_b = (const float*)d_in[11];
    const float* ln_evt_w = (const float*)d_in[12];
    const float* ln_evt_b = (const float*)d_in[13];
    const float* ln_com_w = (const float*)d_in[14];
    const float* ln_com_b = (const float*)d_in[15];
    const float* ln_dif_w = (const float*)d_in[16];
    const float* ln_dif_b = (const float*)d_in[17];
    const float* ln1_w = (const float*)d_in[18];
    const float* ln1_b = (const float*)d_in[19];
    const float* ln2_w = (const float*)d_in[20];
    const float* ln2_b = (const float*)d_in[21];
    const float* fc1c_w = (const float*)d_in[22];
    const float* fc1c_b = (const float*)d_in[23];
    const float* fc2c_w = (const float*)d_in[24];
    const float* fc2c_b = (const float*)d_in[25];
    const float* fc1d_w = (const float*)d_in[26];
    const float* fc1d_b = (const float*)d_in[27];
    const float* fc2d_w = (const float*)d_in[28];
    const float* fc2d_b = (const float*)d_in[29];
    const float* proj1_w = (const float*)d_in[30];
    const float* proj2_w = (const float*)d_in[31];

    float* outc = (float*)d_out;
    float* outd = outc + (size_t)BATCH*C64*HW;

    const int SM3 = (4096*5 + 1024*2 + 64*3) * sizeof(float);

    cudaFuncSetAttribute(smallmath_kernel, cudaFuncAttributeMaxDynamicSharedMemorySize, SM3);
    cudaFuncSetAttribute(apply_kernel,     cudaFuncAttributeMaxDynamicSharedMemorySize, AP_SMEM_BYTES);

    dim3 g1(HW/64, BATCH);
    ln_kernel<<<g1, 256>>>(image, event_,
        ln_img_w, ln_img_b, ln_evt_w, ln_evt_b,
        ln_com_w, ln_com_b, ln_dif_w, ln_dif_b);

    dim3 g2(GK_KSPLIT, 3, BATCH);
    gram_mma_kernel<<<g2, 256>>>();

    dim3 g3(BATCH, 2);
    smallmath_kernel<<<g3, 256, SM3>>>(Wq_c, Wk_c, Wv_c, temp_c,
                                       Wq_d, Wk_d, Wv_d, temp_d,
                                       proj1_w, proj2_w,
                                       fc1c_w, fc2c_w, fc1d_w, fc2d_w);

    dim3 g4(HW/64, BATCH, 2);
    apply_kernel<<<g4, 256, AP_SMEM_BYTES>>>(ln1_w, ln1_b, fc1c_b, fc2c_b,
                                             ln2_w, ln2_b, fc1d_b, fc2d_b,
                                             outc, outd);
}

// round 17
// speedup vs baseline: 1.8411x; 1.1012x over previous
#include <cuda_runtime.h>
#include <cuda_bf16.h>
#include <math.h>
#include <stdint.h>

#define BATCH 4
#define C64   64
#define HW    65536
#define HEADS 4
#define HID   128
#define EPSF  1e-5f

#define TOT (BATCH*C64*HW)

// ---------------- scratch (device globals; no allocs) ----------------
__device__ unsigned short g_hi[(size_t)4*TOT];
__device__ unsigned short g_lo[(size_t)2*TOT];   // ni/ne only
__device__ float g_gram256[BATCH*256*256];
__device__ unsigned short g_Mh[BATCH*2*8704];
__device__ unsigned short g_Ml[BATCH*2*8704];
__device__ unsigned short g_W1h[2*9216];
__device__ unsigned short g_W1l[2*9216];
__device__ unsigned short g_W2h[2*8704];
__device__ unsigned short g_W2l[2*8704];

// ======================= helpers ========================
__device__ __forceinline__ uint32_t smem_u32(const void* p){
    uint32_t a;
    asm("{ .reg .u64 t; cvta.to.shared.u64 t, %1; cvt.u32.u64 %0, t; }" : "=r"(a) : "l"(p));
    return a;
}
__device__ __forceinline__ void ldm_x4(uint32_t* r, uint32_t addr){
    asm volatile("ldmatrix.sync.aligned.m8n8.x4.shared.b16 {%0,%1,%2,%3}, [%4];"
        : "=r"(r[0]), "=r"(r[1]), "=r"(r[2]), "=r"(r[3]) : "r"(addr));
}
__device__ __forceinline__ void ldm_t4(uint32_t* r, uint32_t addr){
    asm volatile("ldmatrix.sync.aligned.m8n8.x4.trans.shared.b16 {%0,%1,%2,%3}, [%4];"
        : "=r"(r[0]), "=r"(r[1]), "=r"(r[2]), "=r"(r[3]) : "r"(addr));
}
__device__ __forceinline__ void mma_bf16(float& d0, float& d1, float& d2, float& d3,
        uint32_t a0, uint32_t a1, uint32_t a2, uint32_t a3,
        uint32_t b0, uint32_t b1){
    asm volatile("mma.sync.aligned.m16n8k16.row.col.f32.bf16.bf16.f32 "
        "{%0,%1,%2,%3}, {%4,%5,%6,%7}, {%8,%9}, {%0,%1,%2,%3};"
        : "+f"(d0), "+f"(d1), "+f"(d2), "+f"(d3)
        : "r"(a0), "r"(a1), "r"(a2), "r"(a3), "r"(b0), "r"(b1));
}
#define MMA3(ACC, AH, AL, BH0, BH1, BL0, BL1) do { \
    mma_bf16((ACC)[0],(ACC)[1],(ACC)[2],(ACC)[3], (AH)[0],(AH)[1],(AH)[2],(AH)[3], (BH0),(BH1)); \
    mma_bf16((ACC)[0],(ACC)[1],(ACC)[2],(ACC)[3], (AH)[0],(AH)[1],(AH)[2],(AH)[3], (BL0),(BL1)); \
    mma_bf16((ACC)[0],(ACC)[1],(ACC)[2],(ACC)[3], (AL)[0],(AL)[1],(AL)[2],(AL)[3], (BH0),(BH1)); \
} while(0)
#define MMA1(ACC, AH, BH0, BH1) \
    mma_bf16((ACC)[0],(ACC)[1],(ACC)[2],(ACC)[3], (AH)[0],(AH)[1],(AH)[2],(AH)[3], (BH0),(BH1))

__device__ __forceinline__ void cpa16(uint32_t saddr, const void* g){
    asm volatile("cp.async.cg.shared.global [%0], [%1], 16;" :: "r"(saddr), "l"(g));
}
#define CPA_COMMIT() asm volatile("cp.async.commit_group;" ::: "memory")
#define CPA_WAIT0()  asm volatile("cp.async.wait_group 0;" ::: "memory")

__device__ __forceinline__ void split1(float a, unsigned short& h, unsigned short& l){
    __nv_bfloat16 hb = __float2bfloat16(a);
    float r = a - __bfloat162float(hb);
    h = __bfloat16_as_ushort(hb);
    l = __bfloat16_as_ushort(__float2bfloat16(r));
}
__device__ __forceinline__ void split2(float a, float b, uint32_t& h, uint32_t& l){
    __nv_bfloat16 ha=__float2bfloat16(a), hb=__float2bfloat16(b);
    float ra = a-__bfloat162float(ha), rb = b-__bfloat162float(hb);
    h = (uint32_t)__bfloat16_as_ushort(ha) | ((uint32_t)__bfloat16_as_ushort(hb)<<16);
    l = (uint32_t)__bfloat16_as_ushort(__float2bfloat16(ra))
      | ((uint32_t)__bfloat16_as_ushort(__float2bfloat16(rb))<<16);
}
__device__ __forceinline__ uint32_t pack_bf2(float a, float b){
    return (uint32_t)__bfloat16_as_ushort(__float2bfloat16(a))
         | ((uint32_t)__bfloat16_as_ushort(__float2bfloat16(b))<<16);
}
__device__ __forceinline__ float gelu_f(float h){
    return 0.5f*h*(1.f + erff(h*0.70710678118654752f));
}

// =====================================================================
// K1: tiled LayerNorm, single gmem read. (unchanged from R15)
// =====================================================================
__global__ void __launch_bounds__(256) ln_kernel(
    const float* __restrict__ img, const float* __restrict__ evt,
    const float* __restrict__ wi, const float* __restrict__ bi,
    const float* __restrict__ we, const float* __restrict__ be,
    const float* __restrict__ wc, const float* __restrict__ bc,
    const float* __restrict__ wd, const float* __restrict__ bd)
{
    __shared__ float sI[64*68];
    __shared__ float sE[64*68];
    __shared__ float sp[4][5][64];
    __shared__ float st[8][64];

    int b = blockIdx.y, p0 = blockIdx.x*64;
    int t = threadIdx.x;

    if (b == 0 && blockIdx.x < 256) {
        int base = blockIdx.x * 1024 + t * 4;
        g_gram256[base+0]=0.f; g_gram256[base+1]=0.f;
        g_gram256[base+2]=0.f; g_gram256[base+3]=0.f;
    }

    int c = t>>2, pq = (t&3)*16;
    {
        const float* ip = img + ((size_t)(b*C64+c))*HW + p0 + pq;
        const float* ep = evt + ((size_t)(b*C64+c))*HW + p0 + pq;
        #pragma unroll
        for (int j=0;j<4;j++){
            *(float4*)&sI[c*68+pq+j*4] = *(const float4*)&ip[j*4];
            *(float4*)&sE[c*68+pq+j*4] = *(const float4*)&ep[j*4];
        }
    }
    __syncthreads();
    {
        int px = t & 63, q = t >> 6;
        float si=0,se=0,sii=0,see=0,sie=0;
        #pragma unroll
        for (int cc=q*16; cc<q*16+16; cc++){
            float iv = sI[cc*68+px], ev = sE[cc*68+px];
            si+=iv; se+=ev; sii+=iv*iv; see+=ev*ev; sie+=iv*ev;
        }
        sp[q][0][px]=si; sp[q][1][px]=se; sp[q][2][px]=sii;
        sp[q][3][px]=see; sp[q][4][px]=sie;
    }
    __syncthreads();
    if (t < 64){
        float si  = sp[0][0][t]+sp[1][0][t]+sp[2][0][t]+sp[3][0][t];
        float se  = sp[0][1][t]+sp[1][1][t]+sp[2][1][t]+sp[3][1][t];
        float sii = sp[0][2][t]+sp[1][2][t]+sp[2][2][t]+sp[3][2][t];
        float see = sp[0][3][t]+sp[1][3][t]+sp[2][3][t]+sp[3][3][t];
        float sie = sp[0][4][t]+sp[1][4][t]+sp[2][4][t]+sp[3][4][t];
        const float inv64 = 1.f/64.f;
        float mi = si*inv64, me = se*inv64;
        float mc = (si+se)*inv64, md = (si-se)*inv64;
        st[0][t] = mi;
        st[1][t] = rsqrtf(sii*inv64 - mi*mi + EPSF);
        st[2][t] = me;
        st[3][t] = rsqrtf(see*inv64 - me*me + EPSF);
        st[4][t] = mc;
        st[5][t] = rsqrtf((sii+2.f*sie+see)*inv64 - mc*mc + EPSF);
        st[6][t] = md;
        st[7][t] = rsqrtf((sii-2.f*sie+see)*inv64 - md*md + EPSF);
    }
    __syncthreads();
    {
        float Wi=wi[c], Bi=bi[c], We=we[c], Be=be[c];
        float Wc=wc[c], Bc=bc[c], Wd=wd[c], Bd=bd[c];
        uint32_t nih[8], nil_[8], neh[8], nel_[8], nch[8], ndh[8];
        #pragma unroll
        for (int j=0;j<8;j++){
            int px = pq + j*2;
            float i0 = sI[c*68+px], i1 = sI[c*68+px+1];
            float e0 = sE[c*68+px], e1 = sE[c*68+px+1];
            float mi0=st[0][px], mi1=st[0][px+1];
            float ri0=st[1][px], ri1=st[1][px+1];
            float me0=st[2][px], me1=st[2][px+1];
            float re0=st[3][px], re1=st[3][px+1];
            float mc0=st[4][px], mc1=st[4][px+1];
            float rc0=st[5][px], rc1=st[5][px+1];
            float md0=st[6][px], md1=st[6][px+1];
            float rd0=st[7][px], rd1=st[7][px+1];
            split2((i0-mi0)*ri0*Wi+Bi, (i1-mi1)*ri1*Wi+Bi, nih[j], nil_[j]);
            split2((e0-me0)*re0*We+Be, (e1-me1)*re1*We+Be, neh[j], nel_[j]);
            nch[j] = pack_bf2((i0+e0-mc0)*rc0*Wc+Bc, (i1+e1-mc1)*rc1*Wc+Bc);
            ndh[j] = pack_bf2((i0-e0-md0)*rd0*Wd+Bd, (i1-e1-md1)*rd1*Wd+Bd);
        }
        size_t o = ((size_t)(b*C64+c))*HW + p0 + pq;
        *(uint4*)&g_hi[o]   = *(uint4*)&nih[0];
        *(uint4*)&g_hi[o+8] = *(uint4*)&nih[4];
        *(uint4*)&g_lo[o]   = *(uint4*)&nil_[0];
        *(uint4*)&g_lo[o+8] = *(uint4*)&nil_[4];
        *(uint4*)&g_hi[(size_t)TOT+o]   = *(uint4*)&neh[0];
        *(uint4*)&g_hi[(size_t)TOT+o+8] = *(uint4*)&neh[4];
        *(uint4*)&g_lo[(size_t)TOT+o]   = *(uint4*)&nel_[0];
        *(uint4*)&g_lo[(size_t)TOT+o+8] = *(uint4*)&nel_[4];
        *(uint4*)&g_hi[(size_t)2*TOT+o]   = *(uint4*)&nch[0];
        *(uint4*)&g_hi[(size_t)2*TOT+o+8] = *(uint4*)&nch[4];
        *(uint4*)&g_hi[(size_t)3*TOT+o]   = *(uint4*)&ndh[0];
        *(uint4*)&g_hi[(size_t)3*TOT+o+8] = *(uint4*)&ndh[4];
    }
}

// =====================================================================
// K2: stacked Gram, 3 tiles, diagonal aliasing, pure bf16 (unchanged)
// =====================================================================
#define GK_KSPLIT 32
#define GK_KRANGE (HW/GK_KSPLIT)
#define GK_KC     32
#define GK_NCH    (GK_KRANGE/GK_KC)
#define SPITCH    40

__global__ void __launch_bounds__(256) gram_mma_kernel()
{
    __shared__ __align__(16) unsigned short sAhi[128*SPITCH];
    __shared__ __align__(16) unsigned short sBhi[128*SPITCH];

    int tid = threadIdx.x;
    int wid = tid >> 5, lane = tid & 31;
    int ks = blockIdx.x, tileid = blockIdx.y, b = blockIdx.z;
    int m0 = (tileid==0) ? 0 : 128;
    int n0 = (tileid==2) ? 128 : 0;
    bool diag = (tileid != 1);
    int warp_m = (wid >> 1) * 32;
    int warp_n = (wid & 1) * 64;

    int lr = tid >> 1;
    int lc = (tid & 1) * 16;
    size_t offA_g = (size_t)((m0+lr)>>6)*TOT + ((size_t)(b*C64)+((m0+lr)&63))*HW + (size_t)ks*GK_KRANGE + lc;
    size_t offB_g = (size_t)((n0+lr)>>6)*TOT + ((size_t)(b*C64)+((n0+lr)&63))*HW + (size_t)ks*GK_KRANGE + lc;
    const unsigned short* sAg_h = g_hi + offA_g;
    const unsigned short* sBg_h = g_hi + offB_g;

    uint32_t aHi = smem_u32(sAhi);
    uint32_t bHi = diag ? aHi : smem_u32(sBhi);

    int rowA = warp_m + (lane & 15);
    int colA = (lane >> 4) * 8;
    uint32_t offA = (uint32_t)(rowA*SPITCH + colA) * 2;
    int rowB = warp_n + (lane & 7) + ((lane >> 4) & 1) * 8;
    int colB = ((lane >> 3) & 1) * 8;
    uint32_t offB = (uint32_t)(rowB*SPITCH + colB) * 2;

    float acc[2][8][4];
    #pragma unroll
    for (int i=0;i<2;i++)
        #pragma unroll
        for (int j=0;j<8;j++)
            #pragma unroll
            for (int k=0;k<4;k++) acc[i][j][k] = 0.f;

    unsigned short* dAh = sAhi + lr*SPITCH + lc;
    unsigned short* dBh = sBhi + lr*SPITCH + lc;

    for (int t = 0; t < GK_NCH; t++) {
        __syncthreads();
        int kc = t * GK_KC;
        *(uint4*)&dAh[0] = *(const uint4*)&sAg_h[kc];
        *(uint4*)&dAh[8] = *(const uint4*)&sAg_h[kc+8];
        if (!diag){
            *(uint4*)&dBh[0] = *(const uint4*)&sBg_h[kc];
            *(uint4*)&dBh[8] = *(const uint4*)&sBg_h[kc+8];
        }
        __syncthreads();
        #pragma unroll
        for (int k16 = 0; k16 < GK_KC; k16 += 16) {
            uint32_t kb = (uint32_t)(k16 * 2);
            uint32_t Ah0[4], Ah1[4];
            ldm_x4(Ah0, aHi + offA + kb);
            ldm_x4(Ah1, aHi + offA + kb + 16*SPITCH*2);
            #pragma unroll
            for (int np = 0; np < 4; np++) {
                uint32_t Bh[4];
                uint32_t ob = offB + kb + (uint32_t)(np*16*SPITCH*2);
                ldm_x4(Bh, bHi + ob);
                int n2 = np*2;
                MMA1(acc[0][n2],   Ah0, Bh[0],Bh[1]);
                MMA1(acc[0][n2+1], Ah0, Bh[2],Bh[3]);
                MMA1(acc[1][n2],   Ah1, Bh[0],Bh[1]);
                MMA1(acc[1][n2+1], Ah1, Bh[2],Bh[3]);
            }
        }
    }

    float* G = g_gram256 + (size_t)b*65536;
    int rbase = m0 + warp_m + (lane >> 2);
    int cbase = n0 + warp_n + (lane & 3)*2;
    #pragma unroll
    for (int i=0;i<2;i++){
        #pragma unroll
        for (int ns=0;ns<8;ns++){
            int rr = rbase + i*16;
            int cc = cbase + ns*8;
            atomicAdd(&G[rr*256 + cc],       acc[i][ns][0]);
            atomicAdd(&G[rr*256 + cc + 1],   acc[i][ns][1]);
            atomicAdd(&G[(rr+8)*256 + cc],   acc[i][ns][2]);
            atomicAdd(&G[(rr+8)*256 + cc+1], acc[i][ns][3]);
        }
    }
}

// =====================================================================
// K3: per-batch, per-branch math -> pre-split M + weights. (unchanged)
// =====================================================================
__device__ __forceinline__ void ld_mat(float* s, const float* __restrict__ g, int tid){
    for (int i=tid; i<4096; i+=256) s[i] = g[i];
}
__device__ __forceinline__ void ld_matg(float* s, const float* __restrict__ g, int tid){
    for (int i=tid; i<4096; i+=256) s[i] = g[(i>>6)*256 + (i&63)];
}
__device__ __forceinline__ void mm64_nn(float* Cm, const float* A, const float* Bm, int tid){
    int ty = tid>>4, tx = tid&15;
    float acc[4][4] = {};
    for (int k=0;k<64;k++){
        float4 bv = *(const float4*)&Bm[k*64 + tx*4];
        float b4[4] = {bv.x,bv.y,bv.z,bv.w};
        #pragma unroll
        for (int ii=0;ii<4;ii++){
            float a = A[(ty*4+ii)*64 + k];
            #pragma unroll
            for (int jj=0;jj<4;jj++) acc[ii][jj] += a*b4[jj];
        }
    }
    #pragma unroll
    for (int ii=0;ii<4;ii++)
        #pragma unroll
        for (int jj=0;jj<4;jj++)
            Cm[(ty*4+ii)*64 + tx*4+jj] = acc[ii][jj];
    __syncthreads();
}
__device__ __forceinline__ void mm64_nt(float* Cm, const float* A, const float* Bm, int tid){
    int ty = tid>>4, tx = tid&15;
    float acc[4][4] = {};
    for (int k=0;k<64;k++){
        float a4[4], b4[4];
        #pragma unroll
        for (int ii=0;ii<4;ii++) a4[ii] = A[(ty*4+ii)*64 + k];
        #pragma unroll
        for (int jj=0;jj<4;jj++) b4[jj] = Bm[(tx*4+jj)*64 + k];
        #pragma unroll
        for (int ii=0;ii<4;ii++)
            #pragma unroll
            for (int jj=0;jj<4;jj++) acc[ii][jj] += a4[ii]*b4[jj];
    }
    #pragma unroll
    for (int ii=0;ii<4;ii++)
        #pragma unroll
        for (int jj=0;jj<4;jj++)
            Cm[(ty*4+ii)*64 + tx*4+jj] = acc[ii][jj];
    __syncthreads();
}
__device__ __forceinline__ void rownorm_inv(float* inv, const float* T, const float* Wm, int tid){
    if (tid < 64){
        float s = 0.f;
        for (int k=0;k<64;k++) s += T[tid*64+k]*Wm[tid*64+k];
        inv[tid] = 1.f / fmaxf(sqrtf(fmaxf(s, 0.f)), 1e-12f);
    }
    __syncthreads();
}
__device__ __forceinline__ void attn_softmax(float* out, const float* raw,
        const float* invq, const float* invk, const float* __restrict__ temp, int tid){
    if (tid < 64){
        int head = tid >> 4, base = head*16;
        float t = temp[head];
        float l[16]; float mx = -1e30f;
        #pragma unroll
        for (int s=0;s<16;s++){
            l[s] = raw[tid*64 + base + s] * invq[tid] * invk[base+s] * t;
            mx = fmaxf(mx, l[s]);
        }
        float sum = 0.f;
        #pragma unroll
        for (int s=0;s<16;s++){ l[s] = expf(l[s]-mx); sum += l[s]; }
        float r = 1.f/sum;
        #pragma unroll
        for (int s=0;s<16;s++) out[tid*16+s] = l[s]*r;
    }
    __syncthreads();
}
__device__ __forceinline__ void bdv(float* Cm, const float* at, const float* Wv, int tid){
    int ty = tid>>4, tx = tid&15;
    float acc[4][4] = {};
    for (int s=0;s<16;s++){
        #pragma unroll
        for (int ii=0;ii<4;ii++){
            int row = ty*4+ii; int head = row >> 4;
            float a = at[row*16 + s];
            float4 wv = *(const float4*)&Wv[(head*16+s)*64 + tx*4];
            acc[ii][0] += a*wv.x; acc[ii][1] += a*wv.y;
            acc[ii][2] += a*wv.z; acc[ii][3] += a*wv.w;
        }
    }
    #pragma unroll
    for (int ii=0;ii<4;ii++)
        #pragma unroll
        for (int jj=0;jj<4;jj++)
            Cm[(ty*4+ii)*64 + tx*4+jj] = acc[ii][jj];
    __syncthreads();
}
__device__ __forceinline__ void store_M_half(const float* sR, int b, int buf, int half, int tid){
    size_t base = ((size_t)b*2+buf)*8704;
    for (int i=tid;i<4096;i+=256){
        int r=i>>6, k=i&63;
        unsigned short h,l; split1(sR[i],h,l);
        g_Mh[base + r*136 + half*64 + k] = h;
        g_Ml[base + r*136 + half*64 + k] = l;
    }
    __syncthreads();
}

__global__ void __launch_bounds__(256) smallmath_kernel(
    const float* __restrict__ Wq_c, const float* __restrict__ Wk_c, const float* __restrict__ Wv_c,
    const float* __restrict__ temp_c,
    const float* __restrict__ Wq_d, const float* __restrict__ Wk_d, const float* __restrict__ Wv_d,
    const float* __restrict__ temp_d,
    const float* __restrict__ proj1, const float* __restrict__ proj2,
    const float* __restrict__ fc1c_w, const float* __restrict__ fc2c_w,
    const float* __restrict__ fc1d_w, const float* __restrict__ fc2d_w)
{
    extern __shared__ float sm[];
    float* sA   = sm;
    float* sB   = sA + 4096;
    float* sG   = sB + 4096;
    float* sT   = sG + 4096;
    float* sR   = sT + 4096;
    float* aA   = sR + 4096;
    float* aB   = aA + 1024;
    float* invq  = aB + 1024;
    float* invk1 = invq + 64;
    float* invk2 = invk1 + 64;

    int b = blockIdx.x;
    int br = blockIdx.y;
    int tid = threadIdx.x;

    if (b == 0){
        const float* W1s = br ? fc1d_w : fc1c_w;
        const float* W2s = br ? fc2d_w : fc2c_w;
        int o1 = br*9216, o2 = br*8704;
        for (int i=tid;i<8192;i+=256){
            int r=i>>6, k=i&63;
            unsigned short h,l;
            split1(W1s[i],h,l); g_W1h[o1+r*72+k]=h; g_W1l[o1+r*72+k]=l;
        }
        for (int i=tid;i<8192;i+=256){
            int r=i>>7, k=i&127;
            unsigned short h,l;
            split1(W2s[i],h,l); g_W2h[o2+r*136+k]=h; g_W2l[o2+r*136+k]=l;
        }
    }

    const float* Wq   = br ? Wq_d   : Wq_c;
    const float* Wk   = br ? Wk_d   : Wk_c;
    const float* Wv   = br ? Wv_d   : Wv_c;
    const float* temp = br ? temp_d : temp_c;
    const float* proj = br ? proj2  : proj1;
    int qr = br ? 3 : 2;

    #define GB(bi,bj) (g_gram256 + (size_t)b*65536 + (bi)*64*256 + (bj)*64)

    ld_mat(sA, Wq, tid); ld_matg(sG, GB(qr,qr), tid); __syncthreads();
    mm64_nn(sT, sA, sG, tid);
    rownorm_inv(invq, sT, sA, tid);
    ld_mat(sB, Wk, tid); ld_matg(sG, GB(0,0), tid); __syncthreads();
    mm64_nn(sT, sB, sG, tid);
    rownorm_inv(invk1, sT, sB, tid);
    ld_matg(sG, GB(1,1), tid); __syncthreads();
    mm64_nn(sT, sB, sG, tid);
    rownorm_inv(invk2, sT, sB, tid);
    ld_matg(sG, GB(qr,0), tid); __syncthreads();
    mm64_nn(sT, sA, sG, tid);
    mm64_nt(sR, sT, sB, tid);
    attn_softmax(aA, sR, invq, invk1, temp, tid);
    ld_matg(sG, GB(qr,1), tid); __syncthreads();
    mm64_nn(sT, sA, sG, tid);
    mm64_nt(sR, sT, sB, tid);
    attn_softmax(aB, sR, invq, invk2, temp, tid);

    if (br == 0){
        if (tid < 64){
            #pragma unroll
            for (int s=0;s<16;s++) aA[tid*16+s] *= aB[tid*16+s];
        }
        __syncthreads();
        ld_mat(sB, Wv, tid); __syncthreads();
        bdv(sT, aA, sB, tid);
        ld_mat(sA, proj, tid); __syncthreads();
        mm64_nn(sR, sA, sT, tid);
        store_M_half(sR, b, 0, 0, tid);
        store_M_half(sR, b, 0, 1, tid);
    } else {
        ld_mat(sB, Wv, tid); ld_mat(sA, proj, tid); __syncthreads();
        bdv(sT, aA, sB, tid);
        mm64_nn(sR, sA, sT, tid);
        store_M_half(sR, b, 1, 0, tid);
        bdv(sT, aB, sB, tid);
        mm64_nn(sR, sA, sT, tid);
        store_M_half(sR, b, 1, 1, tid);
    }
    #undef GB
}

// =====================================================================
// K4: fused apply kernel. NEW vs R15:
//  - all gmem->smem staging via cp.async (no register round-trip)
//  - sX widened to 128 rows: [ni;ne]; GEMM1 is a single K=128 pass
//    against A=[M1|M2] (pitch 136, already contiguous in k)
// smem bytes (114432 total, 2 CTA/SM):
//  sAh 0 (18432) sAl 18432 | sXh 36864 (18432) sXl 55296 (18432)
//  sHh 73728 (18432) sHl 92160 (18432)
//  psum 110592 (1024) psumsq 111616 (1024) smu 112640 (256) srs 112896 (256)
//  sb1 113152 (512) sb2 113664 (256) slw 113920 (256) slb 114176 (256)
// =====================================================================
#define AP_SMEM_BYTES 114432

__global__ void __launch_bounds__(256) apply_kernel(
    const float* __restrict__ ln1w, const float* __restrict__ ln1b,
    const float* __restrict__ b1c, const float* __restrict__ b2c,
    const float* __restrict__ ln2w, const float* __restrict__ ln2b,
    const float* __restrict__ b1d, const float* __restrict__ b2d,
    float* __restrict__ outc_, float* __restrict__ outd_)
{
    extern __shared__ char smraw[];
    unsigned short* sAh = (unsigned short*)(smraw);
    unsigned short* sAl = (unsigned short*)(smraw + 18432);
    unsigned short* sXh = (unsigned short*)(smraw + 36864);
    unsigned short* sXl = (unsigned short*)(smraw + 55296);
    unsigned short* sHh = (unsigned short*)(smraw + 73728);
    unsigned short* sHl = (unsigned short*)(smraw + 92160);
    float* psum   = (float*)(smraw + 110592);
    float* psumsq = (float*)(smraw + 111616);
    float* smu = (float*)(smraw + 112640);
    float* srs = (float*)(smraw + 112896);
    float* sb1 = (float*)(smraw + 113152);
    float* sb2 = (float*)(smraw + 113664);
    float* slw = (float*)(smraw + 113920);
    float* slb = (float*)(smraw + 114176);

    uint32_t aH = smem_u32(sAh), aL = smem_u32(sAl);
    uint32_t xH = smem_u32(sXh), xL = smem_u32(sXl);
    uint32_t hH = smem_u32(sHh), hL = smem_u32(sHl);

    int z = blockIdx.z;
    const float* lnw = z ? ln2w : ln1w;
    const float* lnb = z ? ln2b : ln1b;
    const float* b1g = z ? b1d : b1c;
    const float* b2g = z ? b2d : b2c;
    float* outp = z ? outd_ : outc_;
    int msel = z, widx = z;

    int b = blockIdx.y, p0 = blockIdx.x*64;
    int tid = threadIdx.x, w = tid>>5, lane = tid&31;
    int wc = (w>>1)*16, wpx = (w&1)*32;

    if (tid < 128) sb1[tid] = b1g[tid];
    if (tid < 64){ sb2[tid]=b2g[tid]; slw[tid]=lnw[tid]; slb[tid]=lnb[tid]; }

    // ---- stage M + [ni;ne] via cp.async ----
    {
        const uint4* mh = (const uint4*)&g_Mh[((size_t)b*2+msel)*8704];
        const uint4* ml = (const uint4*)&g_Ml[((size_t)b*2+msel)*8704];
        for (int i=tid;i<1088;i+=256){
            cpa16(aH + i*16, mh+i);
            cpa16(aL + i*16, ml+i);
        }
        for (int i=tid;i<512;i+=256){
            int c=i>>3, q=i&7;
            size_t off = ((size_t)(b*C64+c))*HW + p0 + q*8;
            uint32_t so = (uint32_t)(c*72 + q*8)*2;
            cpa16(xH + so, &g_hi[off]);
            cpa16(xL + so, &g_lo[off]);
            uint32_t so2 = (uint32_t)((64+c)*72 + q*8)*2;
            cpa16(xH + so2, &g_hi[(size_t)TOT + off]);
            cpa16(xL + so2, &g_lo[(size_t)TOT + off]);
        }
        CPA_COMMIT();
    }
    CPA_WAIT0();
    __syncthreads();

    // ---- GEMM1: Y = [M1|M2] @ [ni;ne], single K=128 pass ----
    float accY[4][4];
    #pragma unroll
    for (int g=0;g<4;g++)
        #pragma unroll
        for (int k=0;k<4;k++) accY[g][k]=0.f;
    uint32_t offA = (uint32_t)(((wc+(lane&15))*136 + ((lane>>4)&1)*8)*2);
    uint32_t offB = (uint32_t)((((lane&7)+((lane>>3)&1)*8)*72 + ((lane>>4)&1)*8)*2);

    #pragma unroll
    for (int k16=0;k16<8;k16++){
        uint32_t Ah[4],Al[4];
        ldm_x4(Ah, aH + offA + k16*32);
        ldm_x4(Al, aL + offA + k16*32);
        #pragma unroll
        for (int hf=0;hf<2;hf++){
            uint32_t Bh[4],Bl[4];
            uint32_t ob = offB + (uint32_t)(k16*16*144 + (wpx+hf*16)*2);
            ldm_t4(Bh, xH + ob); ldm_t4(Bl, xL + ob);
            MMA3(accY[hf*2],   Ah, Al, Bh[0],Bh[1], Bl[0],Bl[1]);
            MMA3(accY[hf*2+1], Ah, Al, Bh[2],Bh[3], Bl[2],Bl[3]);
        }
    }

    // ---- LN stats from register fragments ----
    {
        float ps[4][2], pq[4][2];
        #pragma unroll
        for (int g=0;g<4;g++){
            ps[g][0] = accY[g][0] + accY[g][2];
            ps[g][1] = accY[g][1] + accY[g][3];
            pq[g][0] = accY[g][0]*accY[g][0] + accY[g][2]*accY[g][2];
            pq[g][1] = accY[g][1]*accY[g][1] + accY[g][3]*accY[g][3];
        }
        #pragma unroll
        for (int off=4; off<32; off<<=1){
            #pragma unroll
            for (int g=0;g<4;g++){
                ps[g][0] += __shfl_xor_sync(0xffffffffu, ps[g][0], off);
                ps[g][1] += __shfl_xor_sync(0xffffffffu, ps[g][1], off);
                pq[g][0] += __shfl_xor_sync(0xffffffffu, pq[g][0], off);
                pq[g][1] += __shfl_xor_sync(0xffffffffu, pq[g][1], off);
            }
        }
        if (lane < 4){
            #pragma unroll
            for (int g=0;g<4;g++){
                int px = wpx + lane*2 + g*8;
                psum[(w>>1)*64 + px]     = ps[g][0];
                psum[(w>>1)*64 + px+1]   = ps[g][1];
                psumsq[(w>>1)*64 + px]   = pq[g][0];
                psumsq[(w>>1)*64 + px+1] = pq[g][1];
            }
        }
    }
    __syncthreads();
    if (tid < 64){
        float s  = psum[tid] + psum[64+tid] + psum[128+tid] + psum[192+tid];
        float sq = psumsq[tid] + psumsq[64+tid] + psumsq[128+tid] + psumsq[192+tid];
        float mu = s*(1.f/64.f);
        float var = sq*(1.f/64.f) - mu*mu;
        smu[tid] = mu; srs[tid] = rsqrtf(var + EPSF);
    }
    __syncthreads();
    // ---- Z from registers -> sX rows 0..63 ; W1 staging via cp.async ----
    {
        const uint4* wh = (const uint4*)&g_W1h[widx*9216];
        const uint4* wl = (const uint4*)&g_W1l[widx*9216];
        for (int i=tid;i<1152;i+=256){
            cpa16(aH + i*16, wh+i);
            cpa16(aL + i*16, wl+i);
        }
        CPA_COMMIT();
    }
    {
        int c0 = wc + (lane>>2);
        int pxb = wpx + (lane&3)*2;
        float w0 = slw[c0], b0 = slb[c0];
        float w8 = slw[c0+8], b8 = slb[c0+8];
        #pragma unroll
        for (int g=0; g<4; g++){
            int px = pxb + g*8;
            float m0 = smu[px], m1 = smu[px+1];
            float r0 = srs[px], r1 = srs[px+1];
            uint32_t hh, ll;
            split2((accY[g][0]-m0)*r0*w0 + b0, (accY[g][1]-m1)*r1*w0 + b0, hh, ll);
            *(uint32_t*)&sXh[c0*72+px] = hh;
            *(uint32_t*)&sXl[c0*72+px] = ll;
            split2((accY[g][2]-m0)*r0*w8 + b8, (accY[g][3]-m1)*r1*w8 + b8, hh, ll);
            *(uint32_t*)&sXh[(c0+8)*72+px] = hh;
            *(uint32_t*)&sXl[(c0+8)*72+px] = ll;
        }
    }
    CPA_WAIT0();
    __syncthreads();

    // ---- GEMM2: H = gelu(W1 @ Z + b1) ----
    {
        int wh_ = (w>>1)*32;
        float a2[2][4][4];
        #pragma unroll
        for (int m=0;m<2;m++)
            #pragma unroll
            for (int g=0;g<4;g++)
                #pragma unroll
                for (int k=0;k<4;k++) a2[m][g][k]=0.f;
        uint32_t offA2 = (uint32_t)(((wh_+(lane&15))*72 + ((lane>>4)&1)*8)*2);
        #pragma unroll
        for (int k16=0;k16<4;k16++){
            uint32_t Ah0[4],Al0[4],Ah1[4],Al1[4];
            ldm_x4(Ah0, aH + offA2 + k16*32);
            ldm_x4(Al0, aL + offA2 + k16*32);
            ldm_x4(Ah1, aH + offA2 + k16*32 + 16*144);
            ldm_x4(Al1, aL + offA2 + k16*32 + 16*144);
            #pragma unroll
            for (int hf=0;hf<2;hf++){
                uint32_t Bh[4],Bl[4];
                uint32_t ob = offB + (uint32_t)(k16*16*144 + (wpx+hf*16)*2);
                ldm_t4(Bh, xH + ob); ldm_t4(Bl, xL + ob);
                int g0=hf*2, g1=hf*2+1;
                MMA3(a2[0][g0], Ah0, Al0, Bh[0],Bh[1], Bl[0],Bl[1]);
                MMA3(a2[0][g1], Ah0, Al0, Bh[2],Bh[3], Bl[2],Bl[3]);
                MMA3(a2[1][g0], Ah1, Al1, Bh[0],Bh[1], Bl[0],Bl[1]);
                MMA3(a2[1][g1], Ah1, Al1, Bh[2],Bh[3], Bl[2],Bl[3]);
            }
        }
        int hb = wh_ + (lane>>2);
        int pxb = wpx + (lane&3)*2;
        #pragma unroll
        for (int m=0;m<2;m++){
            int r0 = hb + m*16, r1 = r0 + 8;
            float bb0 = sb1[r0], bb1 = sb1[r1];
            #pragma unroll
            for (int g=0; g<4; g++){
                int px = pxb + g*8;
                float v0 = gelu_f(a2[m][g][0] + bb0);
                float v1 = gelu_f(a2[m][g][1] + bb0);
                float v2 = gelu_f(a2[m][g][2] + bb1);
                float v3 = gelu_f(a2[m][g][3] + bb1);
                uint32_t hh, ll;
                split2(v0, v1, hh, ll);
                *(uint32_t*)&sHh[r0*72+px] = hh; *(uint32_t*)&sHl[r0*72+px] = ll;
                split2(v2, v3, hh, ll);
                *(uint32_t*)&sHh[r1*72+px] = hh; *(uint32_t*)&sHl[r1*72+px] = ll;
            }
        }
    }
    __syncthreads();
    // ---- W2 staging via cp.async ----
    {
        const uint4* wh = (const uint4*)&g_W2h[widx*8704];
        const uint4* wl = (const uint4*)&g_W2l[widx*8704];
        for (int i=tid;i<1088;i+=256){
            cpa16(aH + i*16, wh+i);
            cpa16(aL + i*16, wl+i);
        }
        CPA_COMMIT();
    }
    CPA_WAIT0();
    __syncthreads();

    // ---- GEMM3 + bias + residual(from regs) + store ----
    {
        float a3[4][4];
        #pragma unroll
        for (int g=0;g<4;g++)
            #pragma unroll
            for (int k=0;k<4;k++) a3[g][k]=0.f;
        uint32_t offA3 = (uint32_t)(((wc+(lane&15))*136 + ((lane>>4)&1)*8)*2);
        #pragma unroll
        for (int k16=0;k16<8;k16++){
            uint32_t Ah[4],Al[4];
            ldm_x4(Ah, aH + offA3 + k16*32);
            ldm_x4(Al, aL + offA3 + k16*32);
            #pragma unroll
            for (int hf=0;hf<2;hf++){
                uint32_t Bh[4],Bl[4];
                uint32_t ob = offB + (uint32_t)(k16*16*144 + (wpx+hf*16)*2);
                ldm_t4(Bh, hH + ob); ldm_t4(Bl, hL + ob);
                MMA3(a3[hf*2],   Ah, Al, Bh[0],Bh[1], Bl[0],Bl[1]);
                MMA3(a3[hf*2+1], Ah, Al, Bh[2],Bh[3], Bl[2],Bl[3]);
            }
        }
        int c0 = wc + (lane>>2);
        int pxb = wpx + (lane&3)*2;
        float bc0 = sb2[c0], bc1 = sb2[c0+8];
        #pragma unroll
        for (int g=0; g<4; g++){
            int px = pxb + g*8;
            float2 o;
            o.x = a3[g][0] + bc0 + accY[g][0];
            o.y = a3[g][1] + bc0 + accY[g][1];
            *(float2*)&outp[((size_t)(b*C64+c0))*HW + p0 + px] = o;
            o.x = a3[g][2] + bc1 + accY[g][2];
            o.y = a3[g][3] + bc1 + accY[g][3];
            *(float2*)&outp[((size_t)(b*C64+c0+8))*HW + p0 + px] = o;
        }
    }
}

// =====================================================================
extern "C" void kernel_launch(void* const* d_in, const int* in_sizes, int n_in,
                              void* d_out, int out_size)
{
    (void)in_sizes; (void)n_in; (void)out_size;
    const float* image  = (const float*)d_in[0];
    const float* event_ = (const float*)d_in[1];
    const float* Wq_c = (const float*)d_in[2];
    const float* Wk_c = (const float*)d_in[3];
    const float* Wv_c = (const float*)d_in[4];
    const float* temp_c = (const float*)d_in[5];
    const float* Wq_d = (const float*)d_in[6];
    const float* Wk_d = (const float*)d_in[7];
    const float* Wv_d = (const float*)d_in[8];
    const float* temp_d = (const float*)d_in[9];
    const float* ln_img_w = (const float*)d_in[10];
    const float* ln_img_b = (const float*)d_in[11];
    const float* ln_evt_w = (const float*)d_in[12];
    const float* ln_evt_b = (const float*)d_in[13];
    const float* ln_com_w = (const float*)d_in[14];
    const float* ln_com_b = (const float*)d_in[15];
    const float* ln_dif_w = (const float*)d_in[16];
    const float* ln_dif_b = (const float*)d_in[17];
    const float* ln1_w = (const float*)d_in[18];
    const float* ln1_b = (const float*)d_in[19];
    const float* ln2_w = (const float*)d_in[20];
    const float* ln2_b = (const float*)d_in[21];
    const float* fc1c_w = (const float*)d_in[22];
    const float* fc1c_b = (const float*)d_in[23];
    const float* fc2c_w = (const float*)d_in[24];
    const float* fc2c_b = (const float*)d_in[25];
    const float* fc1d_w = (const float*)d_in[26];
    const float* fc1d_b = (const float*)d_in[27];
    const float* fc2d_w = (const float*)d_in[28];
    const float* fc2d_b = (const float*)d_in[29];
    const float* proj1_w = (const float*)d_in[30];
    const float* proj2_w = (const float*)d_in[31];

    float* outc = (float*)d_out;
    float* outd = outc + (size_t)BATCH*C64*HW;

    const int SM3 = (4096*5 + 1024*2 + 64*3) * sizeof(float);

    cudaFuncSetAttribute(smallmath_kernel, cudaFuncAttributeMaxDynamicSharedMemorySize, SM3);
    cudaFuncSetAttribute(apply_kernel,     cudaFuncAttributeMaxDynamicSharedMemorySize, AP_SMEM_BYTES);

    dim3 g1(HW/64, BATCH);
    ln_kernel<<<g1, 256>>>(image, event_,
        ln_img_w, ln_img_b, ln_evt_w, ln_evt_b,
        ln_com_w, ln_com_b, ln_dif_w, ln_dif_b);

    dim3 g2(GK_KSPLIT, 3, BATCH);
    gram_mma_kernel<<<g2, 256>>>();

    dim3 g3(BATCH, 2);
    smallmath_kernel<<<g3, 256, SM3>>>(Wq_c, Wk_c, Wv_c, temp_c,
                                       Wq_d, Wk_d, Wv_d, temp_d,
                                       proj1_w, proj2_w,
                                       fc1c_w, fc2c_w, fc1d_w, fc2d_w);

    dim3 g4(HW/64, BATCH, 2);
    apply_kernel<<<g4, 256, AP_SMEM_BYTES>>>(ln1_w, ln1_b, fc1c_b, fc2c_b,
                                             ln2_w, ln2_b, fc1d_b, fc2d_b,
                                             outc, outd);
}